// round 4
// baseline (speedup 1.0000x reference)
#include <cuda_runtime.h>
#include <cuda_bf16.h>
#include <math.h>
#include <stdint.h>

#define S   2048
#define D   1024
#define H   16
#define HD  64
#define MM  4096
#define LAY 4
#define QKVW 3072   // fused qkv row width

// ---------------- scratch (device globals) ----------------
__device__ float g_x[S * D];
__device__ float g_qkv[S * QKVW];
__device__ __nv_bfloat16 g_a3[S * 3 * D];        // split activations [row, 3*1024]
__device__ __nv_bfloat16 g_y3[S * 3 * MM];       // split mlp hidden [row, 3*4096]
__device__ __nv_bfloat16 g_wT[12 * 1024 * 1024]; // transposed split weights [N, 3K]

// ================= PTX helpers =================
__device__ __forceinline__ uint32_t smem_u32(const void* p) {
    uint32_t a;
    asm("{ .reg .u64 t; cvta.to.shared.u64 t, %1; cvt.u32.u64 %0, t; }" : "=r"(a) : "l"(p));
    return a;
}
__device__ __forceinline__ void cp16(uint32_t saddr, const void* g) {
    asm volatile("cp.async.cg.shared.global [%0], [%1], 16;" :: "r"(saddr), "l"(g));
}
#define CP_COMMIT() asm volatile("cp.async.commit_group;" ::: "memory")
#define CP_WAIT2()  asm volatile("cp.async.wait_group 2;" ::: "memory")

__device__ __forceinline__ void ldsm4(uint32_t* r, uint32_t a) {
    asm volatile("ldmatrix.sync.aligned.m8n8.x4.shared.b16 {%0,%1,%2,%3}, [%4];"
                 : "=r"(r[0]), "=r"(r[1]), "=r"(r[2]), "=r"(r[3]) : "r"(a));
}
__device__ __forceinline__ void mma16816(float* c, const uint32_t* a, uint32_t b0, uint32_t b1) {
    asm volatile("mma.sync.aligned.m16n8k16.row.col.f32.bf16.bf16.f32 "
                 "{%0,%1,%2,%3}, {%4,%5,%6,%7}, {%8,%9}, {%0,%1,%2,%3};"
                 : "+f"(c[0]), "+f"(c[1]), "+f"(c[2]), "+f"(c[3])
                 : "r"(a[0]), "r"(a[1]), "r"(a[2]), "r"(a[3]), "r"(b0), "r"(b1));
}
__device__ __forceinline__ void split2(float a, __nv_bfloat16& hi, __nv_bfloat16& lo) {
    hi = __float2bfloat16(a);
    lo = __float2bfloat16(a - __bfloat162float(hi));
}

// ---------------- embedding + sinusoidal positional encoding ----------------
__global__ __launch_bounds__(256) void embed_kernel(const int* __restrict__ ids,
                                                    const float* __restrict__ emb,
                                                    float* __restrict__ x) {
    int s = blockIdx.x;
    int id = ids[s];
    const double c = -9.210340371976184 / 1024.0;
    for (int d = threadIdx.x; d < D; d += 256) {
        int p2 = d & ~1;
        double freq = exp((double)p2 * c);
        double phase = (double)s * freq;
        double pe = (d & 1) ? cos(phase) : sin(phase);
        x[s * D + d] = emb[id * D + d] + (float)pe;
    }
}

// ---------------- LayerNorm -> fp32 out (final) ----------------
__global__ __launch_bounds__(256) void ln_kernel(const float* __restrict__ x,
                                                 const float* __restrict__ sc,
                                                 const float* __restrict__ bi,
                                                 float* __restrict__ out) {
    __shared__ float ssum[256], ssq[256];
    int s = blockIdx.x, tid = threadIdx.x;
    float4 v = ((const float4*)(x + s * D))[tid];
    ssum[tid] = v.x + v.y + v.z + v.w;
    ssq[tid]  = v.x * v.x + v.y * v.y + v.z * v.z + v.w * v.w;
    __syncthreads();
#pragma unroll
    for (int off = 128; off > 0; off >>= 1) {
        if (tid < off) { ssum[tid] += ssum[tid + off]; ssq[tid] += ssq[tid + off]; }
        __syncthreads();
    }
    float mu  = ssum[0] * (1.0f / 1024.0f);
    float var = ssq[0] * (1.0f / 1024.0f) - mu * mu;
    float rs  = rsqrtf(var + 1e-6f);
    float4 scv = ((const float4*)sc)[tid];
    float4 biv = ((const float4*)bi)[tid];
    float4 o;
    o.x = (v.x - mu) * rs * scv.x + biv.x;
    o.y = (v.y - mu) * rs * scv.y + biv.y;
    o.z = (v.z - mu) * rs * scv.z + biv.z;
    o.w = (v.w - mu) * rs * scv.w + biv.w;
    ((float4*)(out + s * D))[tid] = o;
}

// ---------------- LayerNorm -> split bf16 [hi|lo|hi] into a3 ----------------
__global__ __launch_bounds__(256) void ln_split_kernel(const float* __restrict__ x,
                                                       const float* __restrict__ sc,
                                                       const float* __restrict__ bi,
                                                       __nv_bfloat16* __restrict__ a3) {
    __shared__ float ssum[256], ssq[256];
    int s = blockIdx.x, tid = threadIdx.x;
    float4 v = ((const float4*)(x + s * D))[tid];
    ssum[tid] = v.x + v.y + v.z + v.w;
    ssq[tid]  = v.x * v.x + v.y * v.y + v.z * v.z + v.w * v.w;
    __syncthreads();
#pragma unroll
    for (int off = 128; off > 0; off >>= 1) {
        if (tid < off) { ssum[tid] += ssum[tid + off]; ssq[tid] += ssq[tid + off]; }
        __syncthreads();
    }
    float mu  = ssum[0] * (1.0f / 1024.0f);
    float var = ssq[0] * (1.0f / 1024.0f) - mu * mu;
    float rs  = rsqrtf(var + 1e-6f);
    float4 scv = ((const float4*)sc)[tid];
    float4 biv = ((const float4*)bi)[tid];
    float o[4];
    o[0] = (v.x - mu) * rs * scv.x + biv.x;
    o[1] = (v.y - mu) * rs * scv.y + biv.y;
    o[2] = (v.z - mu) * rs * scv.z + biv.z;
    o[3] = (v.w - mu) * rs * scv.w + biv.w;
    __nv_bfloat16 hi[4], lo[4];
#pragma unroll
    for (int j = 0; j < 4; j++) split2(o[j], hi[j], lo[j]);
    __nv_bfloat16* orow = a3 + (size_t)s * 3 * D + tid * 4;
    *(__nv_bfloat162*)(orow)         = __nv_bfloat162(hi[0], hi[1]);
    *(__nv_bfloat162*)(orow + 2)     = __nv_bfloat162(hi[2], hi[3]);
    *(__nv_bfloat162*)(orow + D)     = __nv_bfloat162(lo[0], lo[1]);
    *(__nv_bfloat162*)(orow + D + 2) = __nv_bfloat162(lo[2], lo[3]);
    *(__nv_bfloat162*)(orow + 2*D)     = __nv_bfloat162(hi[0], hi[1]);
    *(__nv_bfloat162*)(orow + 2*D + 2) = __nv_bfloat162(hi[2], hi[3]);
}

// ---------------- weights: W[K,N] fp32 -> Wt[N,3K] bf16 = [hi|hi|lo] ----------
__global__ __launch_bounds__(256) void convW_kernel(const float* __restrict__ W,
                                                    __nv_bfloat16* __restrict__ Wt,
                                                    int K, int N) {
    __shared__ float t[32][33];
    int k0 = blockIdx.x * 32, n0 = blockIdx.y * 32;
    int tx = threadIdx.x & 31, ty = threadIdx.x >> 5;
#pragma unroll
    for (int i = 0; i < 4; i++)
        t[ty + i * 8][tx] = W[(size_t)(k0 + ty + i * 8) * N + n0 + tx];
    __syncthreads();
#pragma unroll
    for (int i = 0; i < 4; i++) {
        int n = n0 + ty + i * 8, k = k0 + tx;
        __nv_bfloat16 hi, lo;
        split2(t[tx][ty + i * 8], hi, lo);
        __nv_bfloat16* orow = Wt + (size_t)n * 3 * K;
        orow[k] = hi; orow[K + k] = hi; orow[2 * K + k] = lo;
    }
}

// ---------------- HMMA bf16 GEMM (templated CTA M-tile: 128 or 256) ----------
// CTA MTx128, 8 warps (4x2), warp tile (MT/4)x64, BK=32, 3-stage cp.async.
template<int MT>
__global__ __launch_bounds__(256) void gemm_tpl(const __nv_bfloat16* __restrict__ A,
                                                const __nv_bfloat16* __restrict__ Bt,
                                                float* __restrict__ C,
                                                __nv_bfloat16* __restrict__ Cs, int Kout,
                                                int N, int K3,
                                                const float* __restrict__ bias,
                                                const float* residual, int relu) {
    extern __shared__ char sm[];
    constexpr int WTM = MT / 4;          // 32 or 64
    constexpr int FM = WTM / 16;         // 2 or 4
    constexpr int STAGE = (MT + 128) * 80;
    const int tid = threadIdx.x, lane = tid & 31, wid = tid >> 5;
    const int bm = blockIdx.y * MT, bn = blockIdx.x * 128;
    const int wm = (wid >> 1) * WTM, wn = (wid & 1) * 64;
    const size_t rs = (size_t)K3 * 2;
    const char* Ag = (const char*)A + (size_t)bm * rs;
    const char* Bg = (const char*)Bt + (size_t)bn * rs;
    const uint32_t smb = smem_u32(sm);

    uint32_t a_off[FM], b_off[4];
#pragma unroll
    for (int f = 0; f < FM; f++)
        a_off[f] = (uint32_t)((wm + f * 16 + (lane & 15)) * 80 + ((lane >> 4) * 16));
#pragma unroll
    for (int pi = 0; pi < 4; pi++) {
        int row = wn + pi * 16 + (lane & 7) + ((lane >> 4) << 3);
        b_off[pi] = (uint32_t)(row * 80 + (((lane >> 3) & 1) * 16));
    }

    float acc[FM][8][4];
#pragma unroll
    for (int f = 0; f < FM; f++)
#pragma unroll
        for (int ni = 0; ni < 8; ni++)
#pragma unroll
            for (int j = 0; j < 4; j++) acc[f][ni][j] = 0.0f;

    auto load_stage = [&](int buf, int kt) {
        uint32_t sa = smb + buf * STAGE, sb2 = sa + MT * 80;
        size_t gk = (size_t)kt * 64;
#pragma unroll
        for (int i = 0; i < MT / 64; i++) {
            int c = tid + i * 256, r = c >> 2, cb = (c & 3) << 4;
            cp16(sa + r * 80 + cb, Ag + (size_t)r * rs + gk + cb);
        }
#pragma unroll
        for (int i = 0; i < 2; i++) {
            int c = tid + i * 256, r = c >> 2, cb = (c & 3) << 4;
            cp16(sb2 + r * 80 + cb, Bg + (size_t)r * rs + gk + cb);
        }
    };

    const int KT = K3 >> 5;
    load_stage(0, 0); CP_COMMIT();
    load_stage(1, 1); CP_COMMIT();
    load_stage(2, 2); CP_COMMIT();

    int buf = 0;
    for (int kt = 0; kt < KT; kt++) {
        CP_WAIT2();
        __syncthreads();
        const uint32_t ab = smb + buf * STAGE, bb = ab + MT * 80;
#pragma unroll
        for (int ks = 0; ks < 2; ks++) {
            uint32_t a[FM][4];
#pragma unroll
            for (int f = 0; f < FM; f++) ldsm4(a[f], ab + a_off[f] + ks * 32);
#pragma unroll
            for (int pi = 0; pi < 4; pi++) {
                uint32_t b[4];
                ldsm4(b, bb + b_off[pi] + ks * 32);
#pragma unroll
                for (int f = 0; f < FM; f++) {
                    mma16816(acc[f][2 * pi],     a[f], b[0], b[1]);
                    mma16816(acc[f][2 * pi + 1], a[f], b[2], b[3]);
                }
            }
        }
        __syncthreads();
        if (kt + 3 < KT) load_stage(buf, kt + 3);
        CP_COMMIT();
        buf = (buf == 2) ? 0 : buf + 1;
    }

    const int erow = lane >> 2, ecol = (lane & 3) * 2;
#pragma unroll
    for (int f = 0; f < FM; f++) {
#pragma unroll
        for (int ni = 0; ni < 8; ni++) {
            float* c = acc[f][ni];
            int col = bn + wn + ni * 8 + ecol;
#pragma unroll
            for (int half = 0; half < 2; half++) {
                int row = bm + wm + f * 16 + erow + half * 8;
                float vx = c[half * 2 + 0];
                float vy = c[half * 2 + 1];
                if (bias)  { vx += bias[col]; vy += bias[col + 1]; }
                if (relu)  { vx = fmaxf(vx, 0.f); vy = fmaxf(vy, 0.f); }
                if (Cs) {   // split bf16 output [row, 3*Kout] = [hi|lo|hi]
                    __nv_bfloat16 hx, lx, hy, ly;
                    split2(vx, hx, lx); split2(vy, hy, ly);
                    __nv_bfloat16* orow = Cs + (size_t)row * 3 * Kout;
                    *(__nv_bfloat162*)(orow + col)            = __nv_bfloat162(hx, hy);
                    *(__nv_bfloat162*)(orow + Kout + col)     = __nv_bfloat162(lx, ly);
                    *(__nv_bfloat162*)(orow + 2 * Kout + col) = __nv_bfloat162(hx, hy);
                } else {
                    if (residual) {
                        const float2 rv = *(const float2*)(residual + (size_t)row * N + col);
                        vx += rv.x; vy += rv.y;
                    }
                    float2 o; o.x = vx; o.y = vy;
                    *(float2*)(C + (size_t)row * N + col) = o;
                }
            }
        }
    }
}

// ---------------- flash attention (band + global), fused-qkv input ----------
// 64-query tile x 64-key tiles; register online softmax; writes split bf16 a3.
#define AST 68   // smem row stride (floats)
__global__ __launch_bounds__(256) void attn_kernel(const float* __restrict__ qkv,
                                                   __nv_bfloat16* __restrict__ a3) {
    extern __shared__ float fsm[];
    float* Qs = fsm;                 // [64][68]
    float* Ks = Qs + 64 * AST;
    float* Vs = Ks + 64 * AST;
    float* Ps = Vs + 64 * AST;
    float* cfac = Ps + 64 * AST;     // [64]
    float* lrow = cfac + 64;         // [64]

    const int h  = blockIdx.y;
    const int q0 = blockIdx.x * 64;
    const int tid = threadIdx.x;
    const int qcol = h * HD;

    // load Q (scaled by 1/8)
#pragma unroll
    for (int i = 0; i < 4; i++) {
        int idx = tid + i * 256;          // 1024 float4 chunks
        int r = idx >> 4, c4 = (idx & 15) << 2;
        float4 qv = *(const float4*)(qkv + (size_t)(q0 + r) * QKVW + qcol + c4);
        qv.x *= 0.125f; qv.y *= 0.125f; qv.z *= 0.125f; qv.w *= 0.125f;
        *(float4*)(Qs + r * AST + c4) = qv;
    }

    // score-phase mapping: rows qbase+16i, cols kbase+16j
    const int qbase = tid >> 4;           // 0..15
    const int kbase = tid & 15;           // 0..15
    // PV-phase mapping
    const int qi_c = tid >> 2;            // row 0..63
    const int d0   = (tid & 3) * 16;

    float m[4], l[4], acc[16];
#pragma unroll
    for (int i = 0; i < 4; i++) { m[i] = -1e30f; l[i] = 0.0f; }
#pragma unroll
    for (int r = 0; r < 16; r++) acc[r] = 0.0f;

    int jlo, jhi;
    if (q0 < 64) { jlo = 0; jhi = 31; }
    else {
        int lo = q0 - 256; jlo = lo > 0 ? (lo >> 6) : 0;
        int hi = (q0 + 63 + 256) >> 6; jhi = hi < 31 ? hi : 31;
    }
    const bool extra0 = (q0 >= 64) && (jlo > 0);
    const int ntiles = (jhi - jlo + 1) + (extra0 ? 1 : 0);

    __syncthreads();

    for (int t = 0; t < ntiles; t++) {
        int jt = extra0 ? (t == 0 ? 0 : (jlo + t - 1)) : (jlo + t);
        int k0 = jt * 64;
        // load K, V tiles (float4)
#pragma unroll
        for (int i = 0; i < 8; i++) {
            int idx = tid + i * 256;                 // 0..2047
            int which = idx >> 10;                   // 0=K, 1=V
            int e = idx & 1023;
            int r = e >> 4, c4 = (e & 15) << 2;
            int col = (which ? 2048 : 1024) + qcol + c4;
            float4 vv = *(const float4*)(qkv + (size_t)(k0 + r) * QKVW + col);
            float* dst = which ? Vs : Ks;
            *(float4*)(dst + r * AST + c4) = vv;
        }
        __syncthreads();

        // scores 4x4 per thread (rows qbase+16i, cols kbase+16j)
        float sreg[4][4];
#pragma unroll
        for (int i = 0; i < 4; i++)
#pragma unroll
            for (int j = 0; j < 4; j++) sreg[i][j] = 0.0f;
#pragma unroll 4
        for (int kk = 0; kk < 64; kk += 4) {
            float4 qv[4], kv[4];
#pragma unroll
            for (int i = 0; i < 4; i++) qv[i] = *(float4*)(Qs + (qbase + 16 * i) * AST + kk);
#pragma unroll
            for (int j = 0; j < 4; j++) kv[j] = *(float4*)(Ks + (kbase + 16 * j) * AST + kk);
#pragma unroll
            for (int i = 0; i < 4; i++)
#pragma unroll
                for (int j = 0; j < 4; j++) {
                    sreg[i][j] += qv[i].x * kv[j].x + qv[i].y * kv[j].y
                                + qv[i].z * kv[j].z + qv[i].w * kv[j].w;
                }
        }

        const bool tileAll = (q0 < 64) || (k0 < 64);
        // mask + online softmax per row (half-warp = 16 lanes owns a row)
#pragma unroll
        for (int i = 0; i < 4; i++) {
            int qr = qbase + 16 * i;
            int gi = q0 + qr;
            if (!tileAll) {
#pragma unroll
                for (int j = 0; j < 4; j++) {
                    int gj = k0 + kbase + 16 * j;
                    int diff = gi - gj; if (diff < 0) diff = -diff;
                    if (diff > 256) sreg[i][j] = -1e30f;
                }
            }
            float mx = fmaxf(fmaxf(sreg[i][0], sreg[i][1]), fmaxf(sreg[i][2], sreg[i][3]));
#pragma unroll
            for (int off = 8; off > 0; off >>= 1)
                mx = fmaxf(mx, __shfl_xor_sync(0xffffffffu, mx, off, 16));
            float mnew = fmaxf(m[i], mx);
            float corr = __expf(m[i] - mnew);
            float psum = 0.0f;
#pragma unroll
            for (int j = 0; j < 4; j++) {
                float p = __expf(sreg[i][j] - mnew);
                sreg[i][j] = p;
                psum += p;
            }
#pragma unroll
            for (int off = 8; off > 0; off >>= 1)
                psum += __shfl_xor_sync(0xffffffffu, psum, off, 16);
            l[i] = l[i] * corr + psum;
            m[i] = mnew;
#pragma unroll
            for (int j = 0; j < 4; j++) Ps[qr * AST + kbase + 16 * j] = sreg[i][j];
            if (kbase == 0) cfac[qr] = corr;
        }
        __syncthreads();

        // ctx += P @ V
        float corr = cfac[qi_c];
#pragma unroll
        for (int r = 0; r < 16; r++) acc[r] *= corr;
        const float* prow = Ps + qi_c * AST;
#pragma unroll 4
        for (int j = 0; j < 64; j++) {
            float p = prow[j];
            const float* vrow = Vs + j * AST + d0;
#pragma unroll
            for (int c4 = 0; c4 < 16; c4 += 4) {
                float4 vv = *(const float4*)(vrow + c4);
                acc[c4 + 0] += p * vv.x;
                acc[c4 + 1] += p * vv.y;
                acc[c4 + 2] += p * vv.z;
                acc[c4 + 3] += p * vv.w;
            }
        }
        __syncthreads();
    }

    if (kbase == 0) {
#pragma unroll
        for (int i = 0; i < 4; i++) lrow[qbase + 16 * i] = l[i];
    }
    __syncthreads();

    float inv = 1.0f / lrow[qi_c];
    __nv_bfloat16* orow = a3 + (size_t)(q0 + qi_c) * 3 * D + qcol + d0;
#pragma unroll
    for (int r = 0; r < 16; r += 2) {
        float vx = acc[r] * inv, vy = acc[r + 1] * inv;
        __nv_bfloat16 hx, lx, hy, ly;
        split2(vx, hx, lx); split2(vy, hy, ly);
        *(__nv_bfloat162*)(orow + r)           = __nv_bfloat162(hx, hy);
        *(__nv_bfloat162*)(orow + D + r)       = __nv_bfloat162(lx, ly);
        *(__nv_bfloat162*)(orow + 2 * D + r)   = __nv_bfloat162(hx, hy);
    }
}

// ---------------- launch ----------------
extern "C" void kernel_launch(void* const* d_in, const int* in_sizes, int n_in,
                              void* d_out, int out_size) {
    const int*   ids    = (const int*)d_in[0];
    const float* emb    = (const float*)d_in[2];
    const float* wq     = (const float*)d_in[3];
    const float* wk     = (const float*)d_in[4];
    const float* wv     = (const float*)d_in[5];
    const float* wo     = (const float*)d_in[6];
    const float* ln1_s  = (const float*)d_in[7];
    const float* ln1_b  = (const float*)d_in[8];
    const float* ln2_s  = (const float*)d_in[9];
    const float* ln2_b  = (const float*)d_in[10];
    const float* w1     = (const float*)d_in[11];
    const float* b1     = (const float*)d_in[12];
    const float* w2     = (const float*)d_in[13];
    const float* b2     = (const float*)d_in[14];
    const float* lnf_s  = (const float*)d_in[15];
    const float* lnf_b  = (const float*)d_in[16];
    float* out = (float*)d_out;

    void *px, *pqkv, *pa3, *py3, *pwT;
    cudaGetSymbolAddress(&px, g_x);
    cudaGetSymbolAddress(&pqkv, g_qkv);
    cudaGetSymbolAddress(&pa3, g_a3);
    cudaGetSymbolAddress(&py3, g_y3);
    cudaGetSymbolAddress(&pwT, g_wT);
    float* x = (float*)px;
    float* qkv = (float*)pqkv;
    __nv_bfloat16* a3 = (__nv_bfloat16*)pa3;
    __nv_bfloat16* y3 = (__nv_bfloat16*)py3;
    __nv_bfloat16* wT = (__nv_bfloat16*)pwT;

    const int ATTN_SMEM = (4 * 64 * AST + 2 * 64) * (int)sizeof(float);
    cudaFuncSetAttribute(attn_kernel, cudaFuncAttributeMaxDynamicSharedMemorySize, ATTN_SMEM);
    const int SM128 = 3 * (128 + 128) * 80;
    const int SM256 = 3 * (256 + 128) * 80;
    cudaFuncSetAttribute(gemm_tpl<128>, cudaFuncAttributeMaxDynamicSharedMemorySize, SM128);
    cudaFuncSetAttribute(gemm_tpl<256>, cudaFuncAttributeMaxDynamicSharedMemorySize, SM256);

    embed_kernel<<<S, 256>>>(ids, emb, x);

    dim3 cw_dd(D / 32, D / 32);
    dim3 cw_dm(D / 32, MM / 32);
    dim3 cw_md(MM / 32, D / 32);

    for (int l = 0; l < LAY; l++) {
        size_t woff = (size_t)l * D * D;
        // LN1 -> split a3
        ln_split_kernel<<<S, 256>>>(x, ln1_s + l * D, ln1_b + l * D, a3);
        // fused qkv weights: wT rows [0..1023]=wq, [1024..2047]=wk, [2048..3071]=wv
        convW_kernel<<<cw_dd, 256>>>(wq + woff, wT, D, D);
        convW_kernel<<<cw_dd, 256>>>(wk + woff, wT + (size_t)1024 * 3 * D, D, D);
        convW_kernel<<<cw_dd, 256>>>(wv + woff, wT + (size_t)2048 * 3 * D, D, D);
        // qkv = h @ [wq|wk|wv]   (launch idx 5 on first layer -> ncu target)
        gemm_tpl<256><<<dim3(QKVW / 128, S / 256), 256, SM256>>>(
            a3, wT, qkv, nullptr, 0, QKVW, 3 * D, nullptr, nullptr, 0);
        // attention -> split a3
        attn_kernel<<<dim3(S / 64, H), 256, ATTN_SMEM>>>(qkv, a3);
        // x += ctx @ wo
        convW_kernel<<<cw_dd, 256>>>(wo + woff, wT, D, D);
        gemm_tpl<128><<<dim3(D / 128, S / 128), 256, SM128>>>(
            a3, wT, x, nullptr, 0, D, 3 * D, nullptr, x, 0);
        // LN2 -> split a3
        ln_split_kernel<<<S, 256>>>(x, ln2_s + l * D, ln2_b + l * D, a3);
        // y = relu(h @ w1 + b1) -> split y3
        convW_kernel<<<cw_dm, 256>>>(w1 + (size_t)l * D * MM, wT, D, MM);
        gemm_tpl<256><<<dim3(MM / 128, S / 256), 256, SM256>>>(
            a3, wT, nullptr, y3, MM, MM, 3 * D, b1 + (size_t)l * MM, nullptr, 1);
        // x += y @ w2 + b2
        convW_kernel<<<cw_md, 256>>>(w2 + (size_t)l * MM * D, wT, MM, D);
        gemm_tpl<128><<<dim3(D / 128, S / 128), 256, SM128>>>(
            y3, wT, x, nullptr, 0, D, 3 * MM, b2 + (size_t)l * D, x, 0);
    }
    ln_kernel<<<S, 256>>>(x, lnf_s, lnf_b, out);
}

// round 5
// speedup vs baseline: 1.3636x; 1.3636x over previous
#include <cuda_runtime.h>
#include <cuda_bf16.h>
#include <math.h>
#include <stdint.h>

#define S   2048
#define D   1024
#define H   16
#define HD  64
#define MM  4096
#define LAY 4
#define QKVW 3072

// ---------------- scratch (device globals) ----------------
__device__ float g_x[S * D];
__device__ float g_qkv[S * QKVW];
__device__ __nv_bfloat16 g_a3[S * 3 * D];
__device__ __nv_bfloat16 g_y3[S * 3 * MM];
__device__ __nv_bfloat16 g_wT[38 * 1024 * 1024];  // all 4 weight groups resident
// element offsets inside g_wT
#define WT_QKV 0
#define WT_WO  9437184u
#define WT_W1  12582912u
#define WT_W2  25165824u

// ================= PTX helpers =================
__device__ __forceinline__ uint32_t smem_u32(const void* p) {
    uint32_t a;
    asm("{ .reg .u64 t; cvta.to.shared.u64 t, %1; cvt.u32.u64 %0, t; }" : "=r"(a) : "l"(p));
    return a;
}
__device__ __forceinline__ void cp16(uint32_t saddr, const void* g) {
    asm volatile("cp.async.cg.shared.global [%0], [%1], 16;" :: "r"(saddr), "l"(g));
}
#define CP_COMMIT() asm volatile("cp.async.commit_group;" ::: "memory")
#define CP_WAIT2()  asm volatile("cp.async.wait_group 2;" ::: "memory")

__device__ __forceinline__ void ldsm4(uint32_t* r, uint32_t a) {
    asm volatile("ldmatrix.sync.aligned.m8n8.x4.shared.b16 {%0,%1,%2,%3}, [%4];"
                 : "=r"(r[0]), "=r"(r[1]), "=r"(r[2]), "=r"(r[3]) : "r"(a));
}
__device__ __forceinline__ void mma16816(float* c, const uint32_t* a, uint32_t b0, uint32_t b1) {
    asm volatile("mma.sync.aligned.m16n8k16.row.col.f32.bf16.bf16.f32 "
                 "{%0,%1,%2,%3}, {%4,%5,%6,%7}, {%8,%9}, {%0,%1,%2,%3};"
                 : "+f"(c[0]), "+f"(c[1]), "+f"(c[2]), "+f"(c[3])
                 : "r"(a[0]), "r"(a[1]), "r"(a[2]), "r"(a[3]), "r"(b0), "r"(b1));
}
__device__ __forceinline__ void split2(float a, __nv_bfloat16& hi, __nv_bfloat16& lo) {
    hi = __float2bfloat16(a);
    lo = __float2bfloat16(a - __bfloat162float(hi));
}

// ---------------- embedding + sinusoidal positional encoding ----------------
__global__ __launch_bounds__(256) void embed_kernel(const int* __restrict__ ids,
                                                    const float* __restrict__ emb,
                                                    float* __restrict__ x) {
    int s = blockIdx.x;
    int id = ids[s];
    const double c = -9.210340371976184 / 1024.0;
    for (int d = threadIdx.x; d < D; d += 256) {
        int p2 = d & ~1;
        double freq = exp((double)p2 * c);
        double phase = (double)s * freq;
        double pe = (d & 1) ? cos(phase) : sin(phase);
        x[s * D + d] = emb[id * D + d] + (float)pe;
    }
}

// ---------------- LayerNorm -> fp32 out (final) ----------------
__global__ __launch_bounds__(256) void ln_kernel(const float* __restrict__ x,
                                                 const float* __restrict__ sc,
                                                 const float* __restrict__ bi,
                                                 float* __restrict__ out) {
    __shared__ float ssum[256], ssq[256];
    int s = blockIdx.x, tid = threadIdx.x;
    float4 v = ((const float4*)(x + s * D))[tid];
    ssum[tid] = v.x + v.y + v.z + v.w;
    ssq[tid]  = v.x * v.x + v.y * v.y + v.z * v.z + v.w * v.w;
    __syncthreads();
#pragma unroll
    for (int off = 128; off > 0; off >>= 1) {
        if (tid < off) { ssum[tid] += ssum[tid + off]; ssq[tid] += ssq[tid + off]; }
        __syncthreads();
    }
    float mu  = ssum[0] * (1.0f / 1024.0f);
    float var = ssq[0] * (1.0f / 1024.0f) - mu * mu;
    float rs  = rsqrtf(var + 1e-6f);
    float4 scv = ((const float4*)sc)[tid];
    float4 biv = ((const float4*)bi)[tid];
    float4 o;
    o.x = (v.x - mu) * rs * scv.x + biv.x;
    o.y = (v.y - mu) * rs * scv.y + biv.y;
    o.z = (v.z - mu) * rs * scv.z + biv.z;
    o.w = (v.w - mu) * rs * scv.w + biv.w;
    ((float4*)(out + s * D))[tid] = o;
}

// ---------------- LayerNorm -> split bf16 [hi|lo|hi] into a3 ----------------
__global__ __launch_bounds__(256) void ln_split_kernel(const float* __restrict__ x,
                                                       const float* __restrict__ sc,
                                                       const float* __restrict__ bi,
                                                       __nv_bfloat16* __restrict__ a3) {
    __shared__ float ssum[256], ssq[256];
    int s = blockIdx.x, tid = threadIdx.x;
    float4 v = ((const float4*)(x + s * D))[tid];
    ssum[tid] = v.x + v.y + v.z + v.w;
    ssq[tid]  = v.x * v.x + v.y * v.y + v.z * v.z + v.w * v.w;
    __syncthreads();
#pragma unroll
    for (int off = 128; off > 0; off >>= 1) {
        if (tid < off) { ssum[tid] += ssum[tid + off]; ssq[tid] += ssq[tid + off]; }
        __syncthreads();
    }
    float mu  = ssum[0] * (1.0f / 1024.0f);
    float var = ssq[0] * (1.0f / 1024.0f) - mu * mu;
    float rs  = rsqrtf(var + 1e-6f);
    float4 scv = ((const float4*)sc)[tid];
    float4 biv = ((const float4*)bi)[tid];
    float o[4];
    o[0] = (v.x - mu) * rs * scv.x + biv.x;
    o[1] = (v.y - mu) * rs * scv.y + biv.y;
    o[2] = (v.z - mu) * rs * scv.z + biv.z;
    o[3] = (v.w - mu) * rs * scv.w + biv.w;
    __nv_bfloat16 hi[4], lo[4];
#pragma unroll
    for (int j = 0; j < 4; j++) split2(o[j], hi[j], lo[j]);
    __nv_bfloat16* orow = a3 + (size_t)s * 3 * D + tid * 4;
    *(__nv_bfloat162*)(orow)           = __nv_bfloat162(hi[0], hi[1]);
    *(__nv_bfloat162*)(orow + 2)       = __nv_bfloat162(hi[2], hi[3]);
    *(__nv_bfloat162*)(orow + D)       = __nv_bfloat162(lo[0], lo[1]);
    *(__nv_bfloat162*)(orow + D + 2)   = __nv_bfloat162(lo[2], lo[3]);
    *(__nv_bfloat162*)(orow + 2*D)     = __nv_bfloat162(hi[0], hi[1]);
    *(__nv_bfloat162*)(orow + 2*D + 2) = __nv_bfloat162(hi[2], hi[3]);
}

// -------- weights: W[K,N] fp32 -> Wt[N,3K] bf16 = [hi|hi|lo] (transposed) ----
__global__ __launch_bounds__(256) void convW_kernel(const float* __restrict__ W,
                                                    __nv_bfloat16* __restrict__ Wt,
                                                    int K, int N) {
    __shared__ float t[32][33];
    int k0 = blockIdx.x * 32, n0 = blockIdx.y * 32;
    int tx = threadIdx.x & 31, ty = threadIdx.x >> 5;
#pragma unroll
    for (int i = 0; i < 4; i++)
        t[ty + i * 8][tx] = W[(size_t)(k0 + ty + i * 8) * N + n0 + tx];
    __syncthreads();
#pragma unroll
    for (int i = 0; i < 4; i++) {
        int n = n0 + ty + i * 8, k = k0 + tx;
        __nv_bfloat16 hi, lo;
        split2(t[tx][ty + i * 8], hi, lo);
        __nv_bfloat16* orow = Wt + (size_t)n * 3 * K;
        orow[k] = hi; orow[K + k] = hi; orow[2 * K + k] = lo;
    }
}
// fused qkv variant: blockIdx.z selects {wq,wk,wv}; output rows offset by z*1024
__global__ __launch_bounds__(256) void convW3_kernel(const float* __restrict__ wq,
                                                     const float* __restrict__ wk,
                                                     const float* __restrict__ wv,
                                                     __nv_bfloat16* __restrict__ Wt) {
    __shared__ float t[32][33];
    const float* W = (blockIdx.z == 0) ? wq : (blockIdx.z == 1) ? wk : wv;
    const int K = D, N = D;
    int k0 = blockIdx.x * 32, n0 = blockIdx.y * 32;
    int tx = threadIdx.x & 31, ty = threadIdx.x >> 5;
#pragma unroll
    for (int i = 0; i < 4; i++)
        t[ty + i * 8][tx] = W[(size_t)(k0 + ty + i * 8) * N + n0 + tx];
    __syncthreads();
#pragma unroll
    for (int i = 0; i < 4; i++) {
        int n = n0 + ty + i * 8 + blockIdx.z * 1024, k = k0 + tx;
        __nv_bfloat16 hi, lo;
        split2(t[tx][ty + i * 8], hi, lo);
        __nv_bfloat16* orow = Wt + (size_t)n * 3 * K;
        orow[k] = hi; orow[K + k] = hi; orow[2 * K + k] = lo;
    }
}

// ---------------- HMMA bf16 GEMM, 4-stage pipeline, loads before compute ----
template<int MT>
__global__ __launch_bounds__(256) void gemm_tpl(const __nv_bfloat16* __restrict__ A,
                                                const __nv_bfloat16* __restrict__ Bt,
                                                float* __restrict__ C,
                                                __nv_bfloat16* __restrict__ Cs, int Kout,
                                                int N, int K3,
                                                const float* __restrict__ bias,
                                                const float* residual, int relu) {
    extern __shared__ char sm[];
    constexpr int WTM = MT / 4;
    constexpr int FM = WTM / 16;
    constexpr int STAGE = (MT + 128) * 80;
    const int tid = threadIdx.x, lane = tid & 31, wid = tid >> 5;
    const int bm = blockIdx.y * MT, bn = blockIdx.x * 128;
    const int wm = (wid >> 1) * WTM, wn = (wid & 1) * 64;
    const size_t rs = (size_t)K3 * 2;
    const char* Ag = (const char*)A + (size_t)bm * rs;
    const char* Bg = (const char*)Bt + (size_t)bn * rs;
    const uint32_t smb = smem_u32(sm);

    uint32_t a_off[FM], b_off[4];
#pragma unroll
    for (int f = 0; f < FM; f++)
        a_off[f] = (uint32_t)((wm + f * 16 + (lane & 15)) * 80 + ((lane >> 4) * 16));
#pragma unroll
    for (int pi = 0; pi < 4; pi++) {
        int row = wn + pi * 16 + (lane & 7) + ((lane >> 4) << 3);
        b_off[pi] = (uint32_t)(row * 80 + (((lane >> 3) & 1) * 16));
    }

    float acc[FM][8][4];
#pragma unroll
    for (int f = 0; f < FM; f++)
#pragma unroll
        for (int ni = 0; ni < 8; ni++)
#pragma unroll
            for (int j = 0; j < 4; j++) acc[f][ni][j] = 0.0f;

    auto load_stage = [&](int buf, int kt) {
        uint32_t sa = smb + buf * STAGE, sb2 = sa + MT * 80;
        size_t gk = (size_t)kt * 64;
#pragma unroll
        for (int i = 0; i < MT / 64; i++) {
            int c = tid + i * 256, r = c >> 2, cb = (c & 3) << 4;
            cp16(sa + r * 80 + cb, Ag + (size_t)r * rs + gk + cb);
        }
#pragma unroll
        for (int i = 0; i < 2; i++) {
            int c = tid + i * 256, r = c >> 2, cb = (c & 3) << 4;
            cp16(sb2 + r * 80 + cb, Bg + (size_t)r * rs + gk + cb);
        }
    };

    const int KT = K3 >> 5;
    load_stage(0, 0); CP_COMMIT();
    load_stage(1, 1); CP_COMMIT();
    load_stage(2, 2); CP_COMMIT();

    for (int kt = 0; kt < KT; kt++) {
        CP_WAIT2();
        __syncthreads();
        if (kt + 3 < KT) load_stage((kt + 3) & 3, kt + 3);   // issue ahead of compute
        CP_COMMIT();
        const uint32_t ab = smb + (kt & 3) * STAGE, bb = ab + MT * 80;
#pragma unroll
        for (int ks = 0; ks < 2; ks++) {
            uint32_t a[FM][4];
#pragma unroll
            for (int f = 0; f < FM; f++) ldsm4(a[f], ab + a_off[f] + ks * 32);
#pragma unroll
            for (int pi = 0; pi < 4; pi++) {
                uint32_t b[4];
                ldsm4(b, bb + b_off[pi] + ks * 32);
#pragma unroll
                for (int f = 0; f < FM; f++) {
                    mma16816(acc[f][2 * pi],     a[f], b[0], b[1]);
                    mma16816(acc[f][2 * pi + 1], a[f], b[2], b[3]);
                }
            }
        }
    }

    const int erow = lane >> 2, ecol = (lane & 3) * 2;
#pragma unroll
    for (int f = 0; f < FM; f++) {
#pragma unroll
        for (int ni = 0; ni < 8; ni++) {
            float* c = acc[f][ni];
            int col = bn + wn + ni * 8 + ecol;
#pragma unroll
            for (int half = 0; half < 2; half++) {
                int row = bm + wm + f * 16 + erow + half * 8;
                float vx = c[half * 2 + 0];
                float vy = c[half * 2 + 1];
                if (bias)  { vx += bias[col]; vy += bias[col + 1]; }
                if (relu)  { vx = fmaxf(vx, 0.f); vy = fmaxf(vy, 0.f); }
                if (Cs) {
                    __nv_bfloat16 hx, lx, hy, ly;
                    split2(vx, hx, lx); split2(vy, hy, ly);
                    __nv_bfloat16* orow = Cs + (size_t)row * 3 * Kout;
                    *(__nv_bfloat162*)(orow + col)            = __nv_bfloat162(hx, hy);
                    *(__nv_bfloat162*)(orow + Kout + col)     = __nv_bfloat162(lx, ly);
                    *(__nv_bfloat162*)(orow + 2 * Kout + col) = __nv_bfloat162(hx, hy);
                } else {
                    if (residual) {
                        const float2 rv = *(const float2*)(residual + (size_t)row * N + col);
                        vx += rv.x; vy += rv.y;
                    }
                    float2 o; o.x = vx; o.y = vy;
                    *(float2*)(C + (size_t)row * N + col) = o;
                }
            }
        }
    }
}

// ---------------- flash attention (band + global), fused-qkv input ----------
// 64q x 64k tiles; score 4x4/thread; PV 4rows x 4dims/thread; softmax state in regs.
#define AST 68
__global__ __launch_bounds__(256) void attn_kernel(const float* __restrict__ qkv,
                                                   __nv_bfloat16* __restrict__ a3) {
    extern __shared__ float fsm[];
    float* Qs = fsm;
    float* Ks = Qs + 64 * AST;
    float* Vs = Ks + 64 * AST;
    float* Ps = Vs + 64 * AST;

    const int h  = blockIdx.y;
    const int q0 = blockIdx.x * 64;
    const int tid = threadIdx.x;
    const int qcol = h * HD;

#pragma unroll
    for (int i = 0; i < 4; i++) {
        int idx = tid + i * 256;
        int r = idx >> 4, c4 = (idx & 15) << 2;
        float4 qv = *(const float4*)(qkv + (size_t)(q0 + r) * QKVW + qcol + c4);
        qv.x *= 0.125f; qv.y *= 0.125f; qv.z *= 0.125f; qv.w *= 0.125f;
        *(float4*)(Qs + r * AST + c4) = qv;
    }

    const int qbase = tid >> 4;           // rows qbase+16i for score, softmax, PV, output
    const int kbase = tid & 15;           // score cols kbase+16j
    const int dv    = (tid & 15) * 4;     // PV dims dv..dv+3

    float m[4], l[4], acc[4][4];
#pragma unroll
    for (int i = 0; i < 4; i++) {
        m[i] = -1e30f; l[i] = 0.0f;
#pragma unroll
        for (int j = 0; j < 4; j++) acc[i][j] = 0.0f;
    }

    int jlo, jhi;
    if (q0 < 64) { jlo = 0; jhi = 31; }
    else {
        int lo = q0 - 256; jlo = lo > 0 ? (lo >> 6) : 0;
        int hi = (q0 + 63 + 256) >> 6; jhi = hi < 31 ? hi : 31;
    }
    const bool extra0 = (q0 >= 64) && (jlo > 0);
    const int ntiles = (jhi - jlo + 1) + (extra0 ? 1 : 0);

    __syncthreads();

    for (int t = 0; t < ntiles; t++) {
        int jt = extra0 ? (t == 0 ? 0 : (jlo + t - 1)) : (jlo + t);
        int k0 = jt * 64;
#pragma unroll
        for (int i = 0; i < 8; i++) {
            int idx = tid + i * 256;
            int which = idx >> 10;
            int e = idx & 1023;
            int r = e >> 4, c4 = (e & 15) << 2;
            int col = (which ? 2048 : 1024) + qcol + c4;
            float4 vv = *(const float4*)(qkv + (size_t)(k0 + r) * QKVW + col);
            float* dst = which ? Vs : Ks;
            *(float4*)(dst + r * AST + c4) = vv;
        }
        __syncthreads();

        // scores 4x4 per thread
        float sreg[4][4];
#pragma unroll
        for (int i = 0; i < 4; i++)
#pragma unroll
            for (int j = 0; j < 4; j++) sreg[i][j] = 0.0f;
#pragma unroll 4
        for (int kk = 0; kk < 64; kk += 4) {
            float4 qv[4], kv[4];
#pragma unroll
            for (int i = 0; i < 4; i++) qv[i] = *(float4*)(Qs + (qbase + 16 * i) * AST + kk);
#pragma unroll
            for (int j = 0; j < 4; j++) kv[j] = *(float4*)(Ks + (kbase + 16 * j) * AST + kk);
#pragma unroll
            for (int i = 0; i < 4; i++)
#pragma unroll
                for (int j = 0; j < 4; j++)
                    sreg[i][j] += qv[i].x * kv[j].x + qv[i].y * kv[j].y
                                + qv[i].z * kv[j].z + qv[i].w * kv[j].w;
        }

        const bool tileAll = (q0 < 64) || (k0 < 64);
        float corr[4];
#pragma unroll
        for (int i = 0; i < 4; i++) {
            int qr = qbase + 16 * i;
            int gi = q0 + qr;
            if (!tileAll) {
#pragma unroll
                for (int j = 0; j < 4; j++) {
                    int gj = k0 + kbase + 16 * j;
                    int diff = gi - gj; if (diff < 0) diff = -diff;
                    if (diff > 256) sreg[i][j] = -1e30f;
                }
            }
            float mx = fmaxf(fmaxf(sreg[i][0], sreg[i][1]), fmaxf(sreg[i][2], sreg[i][3]));
#pragma unroll
            for (int off = 8; off > 0; off >>= 1)
                mx = fmaxf(mx, __shfl_xor_sync(0xffffffffu, mx, off, 16));
            float mnew = fmaxf(m[i], mx);
            corr[i] = __expf(m[i] - mnew);
            float psum = 0.0f;
#pragma unroll
            for (int j = 0; j < 4; j++) {
                float p = __expf(sreg[i][j] - mnew);
                sreg[i][j] = p;
                psum += p;
            }
#pragma unroll
            for (int off = 8; off > 0; off >>= 1)
                psum += __shfl_xor_sync(0xffffffffu, psum, off, 16);
            l[i] = l[i] * corr[i] + psum;
            m[i] = mnew;
#pragma unroll
            for (int j = 0; j < 4; j++) Ps[qr * AST + kbase + 16 * j] = sreg[i][j];
        }
        __syncthreads();

        // ctx = ctx*corr + P @ V ; thread: rows qbase+16i, dims dv..dv+3
#pragma unroll
        for (int i = 0; i < 4; i++) {
            acc[i][0] *= corr[i]; acc[i][1] *= corr[i];
            acc[i][2] *= corr[i]; acc[i][3] *= corr[i];
        }
#pragma unroll 4
        for (int j = 0; j < 64; j++) {
            float4 vv = *(const float4*)(Vs + j * AST + dv);
#pragma unroll
            for (int i = 0; i < 4; i++) {
                float p = Ps[(qbase + 16 * i) * AST + j];
                acc[i][0] += p * vv.x; acc[i][1] += p * vv.y;
                acc[i][2] += p * vv.z; acc[i][3] += p * vv.w;
            }
        }
        __syncthreads();
    }

    // write split bf16 ctx into a3
#pragma unroll
    for (int i = 0; i < 4; i++) {
        float inv = 1.0f / l[i];
        int row = q0 + qbase + 16 * i;
        __nv_bfloat16* orow = a3 + (size_t)row * 3 * D + qcol + dv;
        float v0 = acc[i][0] * inv, v1 = acc[i][1] * inv;
        float v2 = acc[i][2] * inv, v3 = acc[i][3] * inv;
        __nv_bfloat16 h0, l0, h1, l1, h2, l2, h3, l3;
        split2(v0, h0, l0); split2(v1, h1, l1);
        split2(v2, h2, l2); split2(v3, h3, l3);
        *(__nv_bfloat162*)(orow)             = __nv_bfloat162(h0, h1);
        *(__nv_bfloat162*)(orow + 2)         = __nv_bfloat162(h2, h3);
        *(__nv_bfloat162*)(orow + D)         = __nv_bfloat162(l0, l1);
        *(__nv_bfloat162*)(orow + D + 2)     = __nv_bfloat162(l2, l3);
        *(__nv_bfloat162*)(orow + 2 * D)     = __nv_bfloat162(h0, h1);
        *(__nv_bfloat162*)(orow + 2 * D + 2) = __nv_bfloat162(h2, h3);
    }
}

// ---------------- launch ----------------
extern "C" void kernel_launch(void* const* d_in, const int* in_sizes, int n_in,
                              void* d_out, int out_size) {
    const int*   ids    = (const int*)d_in[0];
    const float* emb    = (const float*)d_in[2];
    const float* wq     = (const float*)d_in[3];
    const float* wk     = (const float*)d_in[4];
    const float* wv     = (const float*)d_in[5];
    const float* wo     = (const float*)d_in[6];
    const float* ln1_s  = (const float*)d_in[7];
    const float* ln1_b  = (const float*)d_in[8];
    const float* ln2_s  = (const float*)d_in[9];
    const float* ln2_b  = (const float*)d_in[10];
    const float* w1     = (const float*)d_in[11];
    const float* b1     = (const float*)d_in[12];
    const float* w2     = (const float*)d_in[13];
    const float* b2     = (const float*)d_in[14];
    const float* lnf_s  = (const float*)d_in[15];
    const float* lnf_b  = (const float*)d_in[16];
    float* out = (float*)d_out;

    void *px, *pqkv, *pa3, *py3, *pwT;
    cudaGetSymbolAddress(&px, g_x);
    cudaGetSymbolAddress(&pqkv, g_qkv);
    cudaGetSymbolAddress(&pa3, g_a3);
    cudaGetSymbolAddress(&py3, g_y3);
    cudaGetSymbolAddress(&pwT, g_wT);
    float* x = (float*)px;
    float* qkv = (float*)pqkv;
    __nv_bfloat16* a3 = (__nv_bfloat16*)pa3;
    __nv_bfloat16* y3 = (__nv_bfloat16*)py3;
    __nv_bfloat16* wT = (__nv_bfloat16*)pwT;

    const int ATTN_SMEM = (4 * 64 * AST) * (int)sizeof(float);
    cudaFuncSetAttribute(attn_kernel, cudaFuncAttributeMaxDynamicSharedMemorySize, ATTN_SMEM);
    const int SM128 = 4 * (128 + 128) * 80;
    const int SM256 = 4 * (256 + 128) * 80;
    cudaFuncSetAttribute(gemm_tpl<128>, cudaFuncAttributeMaxDynamicSharedMemorySize, SM128);
    cudaFuncSetAttribute(gemm_tpl<256>, cudaFuncAttributeMaxDynamicSharedMemorySize, SM256);

    dim3 cw_dd(D / 32, D / 32);
    dim3 cw_dm(D / 32, MM / 32);
    dim3 cw_md(MM / 32, D / 32);

    // layer 0 front-loaded so ncu (-s 5 -c 1) lands on the fused QKV GEMM
    convW3_kernel<<<dim3(32, 32, 3), 256>>>(wq, wk, wv, wT + WT_QKV);      // 0
    convW_kernel<<<cw_dd, 256>>>(wo, wT + WT_WO, D, D);                    // 1
    embed_kernel<<<S, 256>>>(ids, emb, x);                                 // 2
    ln_split_kernel<<<S, 256>>>(x, ln1_s, ln1_b, a3);                      // 3

    for (int l = 0; l < LAY; l++) {
        size_t woff = (size_t)l * D * D;
        if (l > 0) {
            convW3_kernel<<<dim3(32, 32, 3), 256>>>(wq + woff, wk + woff, wv + woff, wT + WT_QKV);
            convW_kernel<<<cw_dd, 256>>>(wo + woff, wT + WT_WO, D, D);
            ln_split_kernel<<<S, 256>>>(x, ln1_s + l * D, ln1_b + l * D, a3);
        }
        gemm_tpl<256><<<dim3(QKVW / 128, S / 256), 256, SM256>>>(
            a3, wT + WT_QKV, qkv, nullptr, 0, QKVW, 3 * D, nullptr, nullptr, 0);
        attn_kernel<<<dim3(S / 64, H), 256, ATTN_SMEM>>>(qkv, a3);
        gemm_tpl<128><<<dim3(D / 128, S / 128), 256, SM128>>>(
            a3, wT + WT_WO, x, nullptr, 0, D, 3 * D, nullptr, x, 0);
        ln_split_kernel<<<S, 256>>>(x, ln2_s + l * D, ln2_b + l * D, a3);
        convW_kernel<<<cw_dm, 256>>>(w1 + (size_t)l * D * MM, wT + WT_W1, D, MM);
        gemm_tpl<256><<<dim3(MM / 128, S / 256), 256, SM256>>>(
            a3, wT + WT_W1, nullptr, y3, MM, MM, 3 * D, b1 + (size_t)l * MM, nullptr, 1);
        convW_kernel<<<cw_md, 256>>>(w2 + (size_t)l * MM * D, wT + WT_W2, MM, D);
        gemm_tpl<128><<<dim3(D / 128, S / 128), 256, SM128>>>(
            y3, wT + WT_W2, x, nullptr, 0, D, 3 * MM, b2 + (size_t)l * D, x, 0);
    }
    ln_kernel<<<S, 256>>>(x, lnf_s, lnf_b, out);
}

// round 7
// speedup vs baseline: 1.5375x; 1.1275x over previous
#include <cuda_runtime.h>
#include <cuda_bf16.h>
#include <math.h>
#include <stdint.h>

#define S   2048
#define D   1024
#define H   16
#define HD  64
#define MM  4096
#define LAY 4
#define QKVW 3072

// ---------------- scratch (device globals) ----------------
__device__ float g_x[S * D];
__device__ float g_qkv[S * QKVW];
__device__ __nv_bfloat16 g_a3[S * 3 * D];
__device__ __nv_bfloat16 g_y3[S * 3 * MM];
__device__ __nv_bfloat16 g_wT[38 * 1024 * 1024];
#define WT_QKV 0
#define WT_WO  9437184u
#define WT_W1  12582912u
#define WT_W2  25165824u

// ================= PTX helpers =================
__device__ __forceinline__ uint32_t smem_u32(const void* p) {
    uint32_t a;
    asm("{ .reg .u64 t; cvta.to.shared.u64 t, %1; cvt.u32.u64 %0, t; }" : "=r"(a) : "l"(p));
    return a;
}
__device__ __forceinline__ void cp16(uint32_t saddr, const void* g) {
    asm volatile("cp.async.cg.shared.global [%0], [%1], 16;" :: "r"(saddr), "l"(g));
}
#define CP_COMMIT() asm volatile("cp.async.commit_group;" ::: "memory")
#define CP_WAIT1()  asm volatile("cp.async.wait_group 1;" ::: "memory")

__device__ __forceinline__ void ldsm4(uint32_t* r, uint32_t a) {
    asm volatile("ldmatrix.sync.aligned.m8n8.x4.shared.b16 {%0,%1,%2,%3}, [%4];"
                 : "=r"(r[0]), "=r"(r[1]), "=r"(r[2]), "=r"(r[3]) : "r"(a));
}
__device__ __forceinline__ void mma16816(float* c, const uint32_t* a, uint32_t b0, uint32_t b1) {
    asm volatile("mma.sync.aligned.m16n8k16.row.col.f32.bf16.bf16.f32 "
                 "{%0,%1,%2,%3}, {%4,%5,%6,%7}, {%8,%9}, {%0,%1,%2,%3};"
                 : "+f"(c[0]), "+f"(c[1]), "+f"(c[2]), "+f"(c[3])
                 : "r"(a[0]), "r"(a[1]), "r"(a[2]), "r"(a[3]), "r"(b0), "r"(b1));
}
__device__ __forceinline__ void split2(float a, __nv_bfloat16& hi, __nv_bfloat16& lo) {
    hi = __float2bfloat16(a);
    lo = __float2bfloat16(a - __bfloat162float(hi));
}

// ---------------- embedding + sinusoidal positional encoding ----------------
__global__ __launch_bounds__(256) void embed_kernel(const int* __restrict__ ids,
                                                    const float* __restrict__ emb,
                                                    float* __restrict__ x) {
    int s = blockIdx.x;
    int id = ids[s];
    const double c = -9.210340371976184 / 1024.0;
    for (int d = threadIdx.x; d < D; d += 256) {
        int p2 = d & ~1;
        double freq = exp((double)p2 * c);
        double phase = (double)s * freq;
        double pe = (d & 1) ? cos(phase) : sin(phase);
        x[s * D + d] = emb[id * D + d] + (float)pe;
    }
}

// ---------------- LayerNorm -> fp32 out (final) ----------------
__global__ __launch_bounds__(256) void ln_kernel(const float* __restrict__ x,
                                                 const float* __restrict__ sc,
                                                 const float* __restrict__ bi,
                                                 float* __restrict__ out) {
    __shared__ float ssum[256], ssq[256];
    int s = blockIdx.x, tid = threadIdx.x;
    float4 v = ((const float4*)(x + s * D))[tid];
    ssum[tid] = v.x + v.y + v.z + v.w;
    ssq[tid]  = v.x * v.x + v.y * v.y + v.z * v.z + v.w * v.w;
    __syncthreads();
#pragma unroll
    for (int off = 128; off > 0; off >>= 1) {
        if (tid < off) { ssum[tid] += ssum[tid + off]; ssq[tid] += ssq[tid + off]; }
        __syncthreads();
    }
    float mu  = ssum[0] * (1.0f / 1024.0f);
    float var = ssq[0] * (1.0f / 1024.0f) - mu * mu;
    float rs  = rsqrtf(var + 1e-6f);
    float4 scv = ((const float4*)sc)[tid];
    float4 biv = ((const float4*)bi)[tid];
    float4 o;
    o.x = (v.x - mu) * rs * scv.x + biv.x;
    o.y = (v.y - mu) * rs * scv.y + biv.y;
    o.z = (v.z - mu) * rs * scv.z + biv.z;
    o.w = (v.w - mu) * rs * scv.w + biv.w;
    ((float4*)(out + s * D))[tid] = o;
}

// ---------------- LayerNorm -> split bf16 [hi|lo|hi] into a3 ----------------
__global__ __launch_bounds__(256) void ln_split_kernel(const float* __restrict__ x,
                                                       const float* __restrict__ sc,
                                                       const float* __restrict__ bi,
                                                       __nv_bfloat16* __restrict__ a3) {
    __shared__ float ssum[256], ssq[256];
    int s = blockIdx.x, tid = threadIdx.x;
    float4 v = ((const float4*)(x + s * D))[tid];
    ssum[tid] = v.x + v.y + v.z + v.w;
    ssq[tid]  = v.x * v.x + v.y * v.y + v.z * v.z + v.w * v.w;
    __syncthreads();
#pragma unroll
    for (int off = 128; off > 0; off >>= 1) {
        if (tid < off) { ssum[tid] += ssum[tid + off]; ssq[tid] += ssq[tid + off]; }
        __syncthreads();
    }
    float mu  = ssum[0] * (1.0f / 1024.0f);
    float var = ssq[0] * (1.0f / 1024.0f) - mu * mu;
    float rs  = rsqrtf(var + 1e-6f);
    float4 scv = ((const float4*)sc)[tid];
    float4 biv = ((const float4*)bi)[tid];
    float o[4];
    o[0] = (v.x - mu) * rs * scv.x + biv.x;
    o[1] = (v.y - mu) * rs * scv.y + biv.y;
    o[2] = (v.z - mu) * rs * scv.z + biv.z;
    o[3] = (v.w - mu) * rs * scv.w + biv.w;
    __nv_bfloat16 hi[4], lo[4];
#pragma unroll
    for (int j = 0; j < 4; j++) split2(o[j], hi[j], lo[j]);
    __nv_bfloat16* orow = a3 + (size_t)s * 3 * D + tid * 4;
    *(__nv_bfloat162*)(orow)           = __nv_bfloat162(hi[0], hi[1]);
    *(__nv_bfloat162*)(orow + 2)       = __nv_bfloat162(hi[2], hi[3]);
    *(__nv_bfloat162*)(orow + D)       = __nv_bfloat162(lo[0], lo[1]);
    *(__nv_bfloat162*)(orow + D + 2)   = __nv_bfloat162(lo[2], lo[3]);
    *(__nv_bfloat162*)(orow + 2*D)     = __nv_bfloat162(hi[0], hi[1]);
    *(__nv_bfloat162*)(orow + 2*D + 2) = __nv_bfloat162(hi[2], hi[3]);
}

// -------- weights: W[K,N] fp32 -> Wt[N,3K] bf16 = [hi|hi|lo] (transposed) ----
__global__ __launch_bounds__(256) void convW_kernel(const float* __restrict__ W,
                                                    __nv_bfloat16* __restrict__ Wt,
                                                    int K, int N) {
    __shared__ float t[32][33];
    int k0 = blockIdx.x * 32, n0 = blockIdx.y * 32;
    int tx = threadIdx.x & 31, ty = threadIdx.x >> 5;
#pragma unroll
    for (int i = 0; i < 4; i++)
        t[ty + i * 8][tx] = W[(size_t)(k0 + ty + i * 8) * N + n0 + tx];
    __syncthreads();
#pragma unroll
    for (int i = 0; i < 4; i++) {
        int n = n0 + ty + i * 8, k = k0 + tx;
        __nv_bfloat16 hi, lo;
        split2(t[tx][ty + i * 8], hi, lo);
        __nv_bfloat16* orow = Wt + (size_t)n * 3 * K;
        orow[k] = hi; orow[K + k] = hi; orow[2 * K + k] = lo;
    }
}
__global__ __launch_bounds__(256) void convW3_kernel(const float* __restrict__ wq,
                                                     const float* __restrict__ wk,
                                                     const float* __restrict__ wv,
                                                     __nv_bfloat16* __restrict__ Wt) {
    __shared__ float t[32][33];
    const float* W = (blockIdx.z == 0) ? wq : (blockIdx.z == 1) ? wk : wv;
    const int K = D, N = D;
    int k0 = blockIdx.x * 32, n0 = blockIdx.y * 32;
    int tx = threadIdx.x & 31, ty = threadIdx.x >> 5;
#pragma unroll
    for (int i = 0; i < 4; i++)
        t[ty + i * 8][tx] = W[(size_t)(k0 + ty + i * 8) * N + n0 + tx];
    __syncthreads();
#pragma unroll
    for (int i = 0; i < 4; i++) {
        int n = n0 + ty + i * 8 + blockIdx.z * 1024, k = k0 + tx;
        __nv_bfloat16 hi, lo;
        split2(t[tx][ty + i * 8], hi, lo);
        __nv_bfloat16* orow = Wt + (size_t)n * 3 * K;
        orow[k] = hi; orow[K + k] = hi; orow[2 * K + k] = lo;
    }
}

// ---------------- HMMA bf16 GEMM, BK=64, 3-stage pipeline ----------
template<int MT>
__global__ __launch_bounds__(256) void gemm_tpl(const __nv_bfloat16* __restrict__ A,
                                                const __nv_bfloat16* __restrict__ Bt,
                                                float* __restrict__ C,
                                                __nv_bfloat16* __restrict__ Cs, int Kout,
                                                int N, int K3,
                                                const float* __restrict__ bias,
                                                const float* residual, int relu) {
    extern __shared__ char sm[];
    constexpr int WTM = MT / 4;
    constexpr int FM = WTM / 16;
    constexpr int ROWB = 144;
    constexpr int STAGE = (MT + 128) * ROWB;
    const int tid = threadIdx.x, lane = tid & 31, wid = tid >> 5;
    const int bm = blockIdx.y * MT, bn = blockIdx.x * 128;
    const int wm = (wid >> 1) * WTM, wn = (wid & 1) * 64;
    const size_t rs = (size_t)K3 * 2;
    const char* Ag = (const char*)A + (size_t)bm * rs;
    const char* Bg = (const char*)Bt + (size_t)bn * rs;
    const uint32_t smb = smem_u32(sm);

    uint32_t a_off[FM], b_off[4];
#pragma unroll
    for (int f = 0; f < FM; f++)
        a_off[f] = (uint32_t)((wm + f * 16 + (lane & 15)) * ROWB + ((lane >> 4) * 16));
#pragma unroll
    for (int pi = 0; pi < 4; pi++) {
        int row = wn + pi * 16 + (lane & 7) + ((lane >> 4) << 3);
        b_off[pi] = (uint32_t)(row * ROWB + (((lane >> 3) & 1) * 16));
    }

    float acc[FM][8][4];
#pragma unroll
    for (int f = 0; f < FM; f++)
#pragma unroll
        for (int ni = 0; ni < 8; ni++)
#pragma unroll
            for (int j = 0; j < 4; j++) acc[f][ni][j] = 0.0f;

    auto load_stage = [&](int buf, int kt) {
        uint32_t sa = smb + buf * STAGE, sb2 = sa + MT * ROWB;
        size_t gk = (size_t)kt * 128;
#pragma unroll
        for (int i = 0; i < MT / 32; i++) {
            int c = tid + i * 256, r = c >> 3, cb = (c & 7) << 4;
            cp16(sa + r * ROWB + cb, Ag + (size_t)r * rs + gk + cb);
        }
#pragma unroll
        for (int i = 0; i < 4; i++) {
            int c = tid + i * 256, r = c >> 3, cb = (c & 7) << 4;
            cp16(sb2 + r * ROWB + cb, Bg + (size_t)r * rs + gk + cb);
        }
    };

    const int KT = K3 >> 6;
    load_stage(0, 0); CP_COMMIT();
    load_stage(1, 1); CP_COMMIT();

    int buf = 0;
    for (int kt = 0; kt < KT; kt++) {
        CP_WAIT1();
        __syncthreads();
        if (kt + 2 < KT) {
            int nbuf = buf + 2; if (nbuf >= 3) nbuf -= 3;   // ring: (buf+2)%3
            load_stage(nbuf, kt + 2);
        }
        CP_COMMIT();
        const uint32_t ab = smb + buf * STAGE, bb = ab + MT * ROWB;
#pragma unroll
        for (int ks = 0; ks < 4; ks++) {
            uint32_t a[FM][4];
#pragma unroll
            for (int f = 0; f < FM; f++) ldsm4(a[f], ab + a_off[f] + ks * 32);
#pragma unroll
            for (int pi = 0; pi < 4; pi++) {
                uint32_t b[4];
                ldsm4(b, bb + b_off[pi] + ks * 32);
#pragma unroll
                for (int f = 0; f < FM; f++) {
                    mma16816(acc[f][2 * pi],     a[f], b[0], b[1]);
                    mma16816(acc[f][2 * pi + 1], a[f], b[2], b[3]);
                }
            }
        }
        buf = (buf == 2) ? 0 : buf + 1;
    }

    const int erow = lane >> 2, ecol = (lane & 3) * 2;
#pragma unroll
    for (int f = 0; f < FM; f++) {
#pragma unroll
        for (int ni = 0; ni < 8; ni++) {
            float* c = acc[f][ni];
            int col = bn + wn + ni * 8 + ecol;
#pragma unroll
            for (int half = 0; half < 2; half++) {
                int row = bm + wm + f * 16 + erow + half * 8;
                float vx = c[half * 2 + 0];
                float vy = c[half * 2 + 1];
                if (bias)  { vx += bias[col]; vy += bias[col + 1]; }
                if (relu)  { vx = fmaxf(vx, 0.f); vy = fmaxf(vy, 0.f); }
                if (Cs) {
                    __nv_bfloat16 hx, lx, hy, ly;
                    split2(vx, hx, lx); split2(vy, hy, ly);
                    __nv_bfloat16* orow = Cs + (size_t)row * 3 * Kout;
                    *(__nv_bfloat162*)(orow + col)            = __nv_bfloat162(hx, hy);
                    *(__nv_bfloat162*)(orow + Kout + col)     = __nv_bfloat162(lx, ly);
                    *(__nv_bfloat162*)(orow + 2 * Kout + col) = __nv_bfloat162(hx, hy);
                } else {
                    if (residual) {
                        const float2 rv = *(const float2*)(residual + (size_t)row * N + col);
                        vx += rv.x; vy += rv.y;
                    }
                    float2 o; o.x = vx; o.y = vy;
                    *(float2*)(C + (size_t)row * N + col) = o;
                }
            }
        }
    }
}

// ---------------- flash attention (band + global), fused-qkv input ----------
#define AST 68
__global__ __launch_bounds__(256) void attn_kernel(const float* __restrict__ qkv,
                                                   __nv_bfloat16* __restrict__ a3) {
    extern __shared__ float fsm[];
    float* Qs = fsm;
    float* Ks = Qs + 64 * AST;
    float* Vs = Ks + 64 * AST;
    float* Ps = Vs + 64 * AST;

    const int h  = blockIdx.y;
    const int q0 = blockIdx.x * 64;
    const int tid = threadIdx.x;
    const int qcol = h * HD;

#pragma unroll
    for (int i = 0; i < 4; i++) {
        int idx = tid + i * 256;
        int r = idx >> 4, c4 = (idx & 15) << 2;
        float4 qv = *(const float4*)(qkv + (size_t)(q0 + r) * QKVW + qcol + c4);
        qv.x *= 0.125f; qv.y *= 0.125f; qv.z *= 0.125f; qv.w *= 0.125f;
        *(float4*)(Qs + r * AST + c4) = qv;
    }

    const int qbase = tid >> 4;
    const int kbase = tid & 15;
    const int dv    = (tid & 15) * 4;

    float m[4], l[4], acc[4][4];
#pragma unroll
    for (int i = 0; i < 4; i++) {
        m[i] = -1e30f; l[i] = 0.0f;
#pragma unroll
        for (int j = 0; j < 4; j++) acc[i][j] = 0.0f;
    }

    int jlo, jhi;
    if (q0 < 64) { jlo = 0; jhi = 31; }
    else {
        int lo = q0 - 256; jlo = lo > 0 ? (lo >> 6) : 0;
        int hi = (q0 + 63 + 256) >> 6; jhi = hi < 31 ? hi : 31;
    }
    const bool extra0 = (q0 >= 64) && (jlo > 0);
    const int ntiles = (jhi - jlo + 1) + (extra0 ? 1 : 0);

    __syncthreads();

    for (int t = 0; t < ntiles; t++) {
        int jt = extra0 ? (t == 0 ? 0 : (jlo + t - 1)) : (jlo + t);
        int k0 = jt * 64;
#pragma unroll
        for (int i = 0; i < 8; i++) {
            int idx = tid + i * 256;
            int which = idx >> 10;
            int e = idx & 1023;
            int r = e >> 4, c4 = (e & 15) << 2;
            int col = (which ? 2048 : 1024) + qcol + c4;
            float4 vv = *(const float4*)(qkv + (size_t)(k0 + r) * QKVW + col);
            float* dst = which ? Vs : Ks;
            *(float4*)(dst + r * AST + c4) = vv;
        }
        __syncthreads();

        float sreg[4][4];
#pragma unroll
        for (int i = 0; i < 4; i++)
#pragma unroll
            for (int j = 0; j < 4; j++) sreg[i][j] = 0.0f;
#pragma unroll 4
        for (int kk = 0; kk < 64; kk += 4) {
            float4 qv[4], kv[4];
#pragma unroll
            for (int i = 0; i < 4; i++) qv[i] = *(float4*)(Qs + (qbase + 16 * i) * AST + kk);
#pragma unroll
            for (int j = 0; j < 4; j++) kv[j] = *(float4*)(Ks + (kbase + 16 * j) * AST + kk);
#pragma unroll
            for (int i = 0; i < 4; i++)
#pragma unroll
                for (int j = 0; j < 4; j++)
                    sreg[i][j] += qv[i].x * kv[j].x + qv[i].y * kv[j].y
                                + qv[i].z * kv[j].z + qv[i].w * kv[j].w;
        }

        const bool tileAll = (q0 < 64) || (k0 < 64);
        float corr[4];
#pragma unroll
        for (int i = 0; i < 4; i++) {
            int qr = qbase + 16 * i;
            int gi = q0 + qr;
            if (!tileAll) {
#pragma unroll
                for (int j = 0; j < 4; j++) {
                    int gj = k0 + kbase + 16 * j;
                    int diff = gi - gj; if (diff < 0) diff = -diff;
                    if (diff > 256) sreg[i][j] = -1e30f;
                }
            }
            float mx = fmaxf(fmaxf(sreg[i][0], sreg[i][1]), fmaxf(sreg[i][2], sreg[i][3]));
#pragma unroll
            for (int off = 8; off > 0; off >>= 1)
                mx = fmaxf(mx, __shfl_xor_sync(0xffffffffu, mx, off, 16));
            float mnew = fmaxf(m[i], mx);
            corr[i] = __expf(m[i] - mnew);
            float psum = 0.0f;
#pragma unroll
            for (int j = 0; j < 4; j++) {
                float p = __expf(sreg[i][j] - mnew);
                sreg[i][j] = p;
                psum += p;
            }
#pragma unroll
            for (int off = 8; off > 0; off >>= 1)
                psum += __shfl_xor_sync(0xffffffffu, psum, off, 16);
            l[i] = l[i] * corr[i] + psum;
            m[i] = mnew;
#pragma unroll
            for (int j = 0; j < 4; j++) Ps[qr * AST + kbase + 16 * j] = sreg[i][j];
        }
        __syncthreads();

#pragma unroll
        for (int i = 0; i < 4; i++) {
            acc[i][0] *= corr[i]; acc[i][1] *= corr[i];
            acc[i][2] *= corr[i]; acc[i][3] *= corr[i];
        }
#pragma unroll 4
        for (int j = 0; j < 64; j++) {
            float4 vv = *(const float4*)(Vs + j * AST + dv);
#pragma unroll
            for (int i = 0; i < 4; i++) {
                float p = Ps[(qbase + 16 * i) * AST + j];
                acc[i][0] += p * vv.x; acc[i][1] += p * vv.y;
                acc[i][2] += p * vv.z; acc[i][3] += p * vv.w;
            }
        }
        __syncthreads();
    }

#pragma unroll
    for (int i = 0; i < 4; i++) {
        float inv = 1.0f / l[i];
        int row = q0 + qbase + 16 * i;
        __nv_bfloat16* orow = a3 + (size_t)row * 3 * D + qcol + dv;
        float v0 = acc[i][0] * inv, v1 = acc[i][1] * inv;
        float v2 = acc[i][2] * inv, v3 = acc[i][3] * inv;
        __nv_bfloat16 h0, l0, h1, l1, h2, l2, h3, l3;
        split2(v0, h0, l0); split2(v1, h1, l1);
        split2(v2, h2, l2); split2(v3, h3, l3);
        *(__nv_bfloat162*)(orow)             = __nv_bfloat162(h0, h1);
        *(__nv_bfloat162*)(orow + 2)         = __nv_bfloat162(h2, h3);
        *(__nv_bfloat162*)(orow + D)         = __nv_bfloat162(l0, l1);
        *(__nv_bfloat162*)(orow + D + 2)     = __nv_bfloat162(l2, l3);
        *(__nv_bfloat162*)(orow + 2 * D)     = __nv_bfloat162(h0, h1);
        *(__nv_bfloat162*)(orow + 2 * D + 2) = __nv_bfloat162(h2, h3);
    }
}

// ---------------- launch ----------------
extern "C" void kernel_launch(void* const* d_in, const int* in_sizes, int n_in,
                              void* d_out, int out_size) {
    const int*   ids    = (const int*)d_in[0];
    const float* emb    = (const float*)d_in[2];
    const float* wq     = (const float*)d_in[3];
    const float* wk     = (const float*)d_in[4];
    const float* wv     = (const float*)d_in[5];
    const float* wo     = (const float*)d_in[6];
    const float* ln1_s  = (const float*)d_in[7];
    const float* ln1_b  = (const float*)d_in[8];
    const float* ln2_s  = (const float*)d_in[9];
    const float* ln2_b  = (const float*)d_in[10];
    const float* w1     = (const float*)d_in[11];
    const float* b1     = (const float*)d_in[12];
    const float* w2     = (const float*)d_in[13];
    const float* b2     = (const float*)d_in[14];
    const float* lnf_s  = (const float*)d_in[15];
    const float* lnf_b  = (const float*)d_in[16];
    float* out = (float*)d_out;

    void *px, *pqkv, *pa3, *py3, *pwT;
    cudaGetSymbolAddress(&px, g_x);
    cudaGetSymbolAddress(&pqkv, g_qkv);
    cudaGetSymbolAddress(&pa3, g_a3);
    cudaGetSymbolAddress(&py3, g_y3);
    cudaGetSymbolAddress(&pwT, g_wT);
    float* x = (float*)px;
    float* qkv = (float*)pqkv;
    __nv_bfloat16* a3 = (__nv_bfloat16*)pa3;
    __nv_bfloat16* y3 = (__nv_bfloat16*)py3;
    __nv_bfloat16* wT = (__nv_bfloat16*)pwT;

    const int ATTN_SMEM = (4 * 64 * AST) * (int)sizeof(float);
    cudaFuncSetAttribute(attn_kernel, cudaFuncAttributeMaxDynamicSharedMemorySize, ATTN_SMEM);
    const int SM128 = 3 * (128 + 128) * 144;   // 110592
    const int SM256 = 3 * (256 + 128) * 144;   // 165888
    cudaFuncSetAttribute(gemm_tpl<128>, cudaFuncAttributeMaxDynamicSharedMemorySize, SM128);
    cudaFuncSetAttribute(gemm_tpl<256>, cudaFuncAttributeMaxDynamicSharedMemorySize, SM256);

    dim3 cw_dd(D / 32, D / 32);
    dim3 cw_dm(D / 32, MM / 32);
    dim3 cw_md(MM / 32, D / 32);

    embed_kernel<<<S, 256>>>(ids, emb, x);                               // 0
    convW3_kernel<<<dim3(32, 32, 3), 256>>>(wq, wk, wv, wT + WT_QKV);    // 1
    ln_split_kernel<<<S, 256>>>(x, ln1_s, ln1_b, a3);                    // 2

    for (int l = 0; l < LAY; l++) {
        size_t woff = (size_t)l * D * D;
        if (l > 0) {
            convW3_kernel<<<dim3(32, 32, 3), 256>>>(wq + woff, wk + woff, wv + woff, wT + WT_QKV);
            ln_split_kernel<<<S, 256>>>(x, ln1_s + l * D, ln1_b + l * D, a3);
        }
        gemm_tpl<256><<<dim3(QKVW / 128, S / 256), 256, SM256>>>(        // 3 (l=0)
            a3, wT + WT_QKV, qkv, nullptr, 0, QKVW, 3 * D, nullptr, nullptr, 0);
        attn_kernel<<<dim3(S / 64, H), 256, ATTN_SMEM>>>(qkv, a3);       // 4 (l=0)
        convW_kernel<<<cw_dd, 256>>>(wo + woff, wT + WT_WO, D, D);
        gemm_tpl<128><<<dim3(D / 128, S / 128), 256, SM128>>>(
            a3, wT + WT_WO, x, nullptr, 0, D, 3 * D, nullptr, x, 0);
        ln_split_kernel<<<S, 256>>>(x, ln2_s + l * D, ln2_b + l * D, a3);
        convW_kernel<<<cw_dm, 256>>>(w1 + (size_t)l * D * MM, wT + WT_W1, D, MM);
        gemm_tpl<256><<<dim3(MM / 128, S / 256), 256, SM256>>>(
            a3, wT + WT_W1, nullptr, y3, MM, MM, 3 * D, b1 + (size_t)l * MM, nullptr, 1);
        convW_kernel<<<cw_md, 256>>>(w2 + (size_t)l * MM * D, wT + WT_W2, MM, D);
        gemm_tpl<128><<<dim3(D / 128, S / 128), 256, SM128>>>(
            y3, wT + WT_W2, x, nullptr, 0, D, 3 * MM, b2 + (size_t)l * D, x, 0);
    }
    ln_kernel<<<S, 256>>>(x, lnf_s, lnf_b, out);
}

// round 9
// speedup vs baseline: 1.5742x; 1.0239x over previous
#include <cuda_runtime.h>
#include <cuda_bf16.h>
#include <math.h>
#include <stdint.h>

#define S   2048
#define D   1024
#define H   16
#define HD  64
#define MM  4096
#define LAY 4
#define QKVW 3072

// ---------------- scratch (device globals) ----------------
__device__ float g_x[S * D];
__device__ float g_qkv[S * QKVW];
__device__ __nv_bfloat16 g_a3[S * 3 * D];
__device__ __nv_bfloat16 g_y3[S * 3 * MM];
__device__ __nv_bfloat16 g_wT[38 * 1024 * 1024];
#define WT_QKV 0
#define WT_WO  9437184u
#define WT_W1  12582912u
#define WT_W2  25165824u

// ================= PTX helpers =================
__device__ __forceinline__ uint32_t smem_u32(const void* p) {
    uint32_t a;
    asm("{ .reg .u64 t; cvta.to.shared.u64 t, %1; cvt.u32.u64 %0, t; }" : "=r"(a) : "l"(p));
    return a;
}
__device__ __forceinline__ void cp16(uint32_t saddr, const void* g) {
    asm volatile("cp.async.cg.shared.global [%0], [%1], 16;" :: "r"(saddr), "l"(g));
}
#define CP_COMMIT() asm volatile("cp.async.commit_group;" ::: "memory")
#define CP_WAIT1()  asm volatile("cp.async.wait_group 1;" ::: "memory")

__device__ __forceinline__ void ldsm4(uint32_t* r, uint32_t a) {
    asm volatile("ldmatrix.sync.aligned.m8n8.x4.shared.b16 {%0,%1,%2,%3}, [%4];"
                 : "=r"(r[0]), "=r"(r[1]), "=r"(r[2]), "=r"(r[3]) : "r"(a));
}
__device__ __forceinline__ void mma16816(float* c, const uint32_t* a, uint32_t b0, uint32_t b1) {
    asm volatile("mma.sync.aligned.m16n8k16.row.col.f32.bf16.bf16.f32 "
                 "{%0,%1,%2,%3}, {%4,%5,%6,%7}, {%8,%9}, {%0,%1,%2,%3};"
                 : "+f"(c[0]), "+f"(c[1]), "+f"(c[2]), "+f"(c[3])
                 : "r"(a[0]), "r"(a[1]), "r"(a[2]), "r"(a[3]), "r"(b0), "r"(b1));
}
__device__ __forceinline__ void split2(float a, __nv_bfloat16& hi, __nv_bfloat16& lo) {
    hi = __float2bfloat16(a);
    lo = __float2bfloat16(a - __bfloat162float(hi));
}

// ---------------- embedding + sinusoidal positional encoding ----------------
__global__ __launch_bounds__(256) void embed_kernel(const int* __restrict__ ids,
                                                    const float* __restrict__ emb,
                                                    float* __restrict__ x) {
    int s = blockIdx.x;
    int id = ids[s];
    const double c = -9.210340371976184 / 1024.0;
    for (int d = threadIdx.x; d < D; d += 256) {
        int p2 = d & ~1;
        double freq = exp((double)p2 * c);
        double phase = (double)s * freq;
        double pe = (d & 1) ? cos(phase) : sin(phase);
        x[s * D + d] = emb[id * D + d] + (float)pe;
    }
}

// ---------------- LayerNorm -> fp32 out (final) ----------------
__global__ __launch_bounds__(256) void ln_kernel(const float* __restrict__ x,
                                                 const float* __restrict__ sc,
                                                 const float* __restrict__ bi,
                                                 float* __restrict__ out) {
    __shared__ float ssum[256], ssq[256];
    int s = blockIdx.x, tid = threadIdx.x;
    float4 v = ((const float4*)(x + s * D))[tid];
    ssum[tid] = v.x + v.y + v.z + v.w;
    ssq[tid]  = v.x * v.x + v.y * v.y + v.z * v.z + v.w * v.w;
    __syncthreads();
#pragma unroll
    for (int off = 128; off > 0; off >>= 1) {
        if (tid < off) { ssum[tid] += ssum[tid + off]; ssq[tid] += ssq[tid + off]; }
        __syncthreads();
    }
    float mu  = ssum[0] * (1.0f / 1024.0f);
    float var = ssq[0] * (1.0f / 1024.0f) - mu * mu;
    float rs  = rsqrtf(var + 1e-6f);
    float4 scv = ((const float4*)sc)[tid];
    float4 biv = ((const float4*)bi)[tid];
    float4 o;
    o.x = (v.x - mu) * rs * scv.x + biv.x;
    o.y = (v.y - mu) * rs * scv.y + biv.y;
    o.z = (v.z - mu) * rs * scv.z + biv.z;
    o.w = (v.w - mu) * rs * scv.w + biv.w;
    ((float4*)(out + s * D))[tid] = o;
}

// ---------------- LayerNorm -> split bf16 [hi|lo|hi] into a3 ----------------
__global__ __launch_bounds__(256) void ln_split_kernel(const float* __restrict__ x,
                                                       const float* __restrict__ sc,
                                                       const float* __restrict__ bi,
                                                       __nv_bfloat16* __restrict__ a3) {
    __shared__ float ssum[256], ssq[256];
    int s = blockIdx.x, tid = threadIdx.x;
    float4 v = ((const float4*)(x + s * D))[tid];
    ssum[tid] = v.x + v.y + v.z + v.w;
    ssq[tid]  = v.x * v.x + v.y * v.y + v.z * v.z + v.w * v.w;
    __syncthreads();
#pragma unroll
    for (int off = 128; off > 0; off >>= 1) {
        if (tid < off) { ssum[tid] += ssum[tid + off]; ssq[tid] += ssq[tid + off]; }
        __syncthreads();
    }
    float mu  = ssum[0] * (1.0f / 1024.0f);
    float var = ssq[0] * (1.0f / 1024.0f) - mu * mu;
    float rs  = rsqrtf(var + 1e-6f);
    float4 scv = ((const float4*)sc)[tid];
    float4 biv = ((const float4*)bi)[tid];
    float o[4];
    o[0] = (v.x - mu) * rs * scv.x + biv.x;
    o[1] = (v.y - mu) * rs * scv.y + biv.y;
    o[2] = (v.z - mu) * rs * scv.z + biv.z;
    o[3] = (v.w - mu) * rs * scv.w + biv.w;
    __nv_bfloat16 hi[4], lo[4];
#pragma unroll
    for (int j = 0; j < 4; j++) split2(o[j], hi[j], lo[j]);
    __nv_bfloat16* orow = a3 + (size_t)s * 3 * D + tid * 4;
    *(__nv_bfloat162*)(orow)           = __nv_bfloat162(hi[0], hi[1]);
    *(__nv_bfloat162*)(orow + 2)       = __nv_bfloat162(hi[2], hi[3]);
    *(__nv_bfloat162*)(orow + D)       = __nv_bfloat162(lo[0], lo[1]);
    *(__nv_bfloat162*)(orow + D + 2)   = __nv_bfloat162(lo[2], lo[3]);
    *(__nv_bfloat162*)(orow + 2*D)     = __nv_bfloat162(hi[0], hi[1]);
    *(__nv_bfloat162*)(orow + 2*D + 2) = __nv_bfloat162(hi[2], hi[3]);
}

// -------- weights: W[K,N] fp32 -> Wt[N,3K] bf16 = [hi|hi|lo] (transposed) ----
__global__ __launch_bounds__(256) void convW_kernel(const float* __restrict__ W,
                                                    __nv_bfloat16* __restrict__ Wt,
                                                    int K, int N) {
    __shared__ float t[32][33];
    int k0 = blockIdx.x * 32, n0 = blockIdx.y * 32;
    int tx = threadIdx.x & 31, ty = threadIdx.x >> 5;
#pragma unroll
    for (int i = 0; i < 4; i++)
        t[ty + i * 8][tx] = W[(size_t)(k0 + ty + i * 8) * N + n0 + tx];
    __syncthreads();
#pragma unroll
    for (int i = 0; i < 4; i++) {
        int n = n0 + ty + i * 8, k = k0 + tx;
        __nv_bfloat16 hi, lo;
        split2(t[tx][ty + i * 8], hi, lo);
        __nv_bfloat16* orow = Wt + (size_t)n * 3 * K;
        orow[k] = hi; orow[K + k] = hi; orow[2 * K + k] = lo;
    }
}
__global__ __launch_bounds__(256) void convW3_kernel(const float* __restrict__ wq,
                                                     const float* __restrict__ wk,
                                                     const float* __restrict__ wv,
                                                     __nv_bfloat16* __restrict__ Wt) {
    __shared__ float t[32][33];
    const float* W = (blockIdx.z == 0) ? wq : (blockIdx.z == 1) ? wk : wv;
    const int K = D, N = D;
    int k0 = blockIdx.x * 32, n0 = blockIdx.y * 32;
    int tx = threadIdx.x & 31, ty = threadIdx.x >> 5;
#pragma unroll
    for (int i = 0; i < 4; i++)
        t[ty + i * 8][tx] = W[(size_t)(k0 + ty + i * 8) * N + n0 + tx];
    __syncthreads();
#pragma unroll
    for (int i = 0; i < 4; i++) {
        int n = n0 + ty + i * 8 + blockIdx.z * 1024, k = k0 + tx;
        __nv_bfloat16 hi, lo;
        split2(t[tx][ty + i * 8], hi, lo);
        __nv_bfloat16* orow = Wt + (size_t)n * 3 * K;
        orow[k] = hi; orow[K + k] = hi; orow[2 * K + k] = lo;
    }
}

// ---------- HMMA bf16 GEMM, BK=64, 3-stage pipeline, 512 threads ----------
// CTA MTx128, 16 warps (4m x 4n), warp tile (MT/4)x32.
template<int MT>
__global__ __launch_bounds__(512) void gemm_tpl(const __nv_bfloat16* __restrict__ A,
                                                const __nv_bfloat16* __restrict__ Bt,
                                                float* __restrict__ C,
                                                __nv_bfloat16* __restrict__ Cs, int Kout,
                                                int N, int K3,
                                                const float* __restrict__ bias,
                                                const float* residual, int relu) {
    extern __shared__ char sm[];
    constexpr int WTM = MT / 4;          // 64 or 32
    constexpr int FM = WTM / 16;         // 4 or 2
    constexpr int ROWB = 144;
    constexpr int STAGE = (MT + 128) * ROWB;
    const int tid = threadIdx.x, lane = tid & 31, wid = tid >> 5;
    const int bm = blockIdx.y * MT, bn = blockIdx.x * 128;
    const int wm = (wid >> 2) * WTM, wn = (wid & 3) * 32;
    const size_t rs = (size_t)K3 * 2;
    const char* Ag = (const char*)A + (size_t)bm * rs;
    const char* Bg = (const char*)Bt + (size_t)bn * rs;
    const uint32_t smb = smem_u32(sm);

    uint32_t a_off[FM], b_off[2];
#pragma unroll
    for (int f = 0; f < FM; f++)
        a_off[f] = (uint32_t)((wm + f * 16 + (lane & 15)) * ROWB + ((lane >> 4) * 16));
#pragma unroll
    for (int pi = 0; pi < 2; pi++) {
        int row = wn + pi * 16 + (lane & 7) + ((lane >> 4) << 3);
        b_off[pi] = (uint32_t)(row * ROWB + (((lane >> 3) & 1) * 16));
    }

    float acc[FM][4][4];
#pragma unroll
    for (int f = 0; f < FM; f++)
#pragma unroll
        for (int ni = 0; ni < 4; ni++)
#pragma unroll
            for (int j = 0; j < 4; j++) acc[f][ni][j] = 0.0f;

    auto load_stage = [&](int buf, int kt) {
        uint32_t sa = smb + buf * STAGE, sb2 = sa + MT * ROWB;
        size_t gk = (size_t)kt * 128;
#pragma unroll
        for (int i = 0; i < MT / 64; i++) {        // A: MT*8 chunks / 512 threads
            int c = tid + i * 512, r = c >> 3, cb = (c & 7) << 4;
            cp16(sa + r * ROWB + cb, Ag + (size_t)r * rs + gk + cb);
        }
#pragma unroll
        for (int i = 0; i < 2; i++) {              // B: 1024 chunks / 512 threads
            int c = tid + i * 512, r = c >> 3, cb = (c & 7) << 4;
            cp16(sb2 + r * ROWB + cb, Bg + (size_t)r * rs + gk + cb);
        }
    };

    const int KT = K3 >> 6;
    load_stage(0, 0); CP_COMMIT();
    load_stage(1, 1); CP_COMMIT();

    int buf = 0;
    for (int kt = 0; kt < KT; kt++) {
        CP_WAIT1();
        __syncthreads();
        if (kt + 2 < KT) {
            int nbuf = buf + 2; if (nbuf >= 3) nbuf -= 3;
            load_stage(nbuf, kt + 2);
        }
        CP_COMMIT();
        const uint32_t ab = smb + buf * STAGE, bb = ab + MT * ROWB;
#pragma unroll
        for (int ks = 0; ks < 4; ks++) {
            uint32_t a[FM][4];
#pragma unroll
            for (int f = 0; f < FM; f++) ldsm4(a[f], ab + a_off[f] + ks * 32);
#pragma unroll
            for (int pi = 0; pi < 2; pi++) {
                uint32_t b[4];
                ldsm4(b, bb + b_off[pi] + ks * 32);
#pragma unroll
                for (int f = 0; f < FM; f++) {
                    mma16816(acc[f][2 * pi],     a[f], b[0], b[1]);
                    mma16816(acc[f][2 * pi + 1], a[f], b[2], b[3]);
                }
            }
        }
        buf = (buf == 2) ? 0 : buf + 1;
    }

    const int erow = lane >> 2, ecol = (lane & 3) * 2;
#pragma unroll
    for (int f = 0; f < FM; f++) {
#pragma unroll
        for (int ni = 0; ni < 4; ni++) {
            float* c = acc[f][ni];
            int col = bn + wn + ni * 8 + ecol;
#pragma unroll
            for (int half = 0; half < 2; half++) {
                int row = bm + wm + f * 16 + erow + half * 8;
                float vx = c[half * 2 + 0];
                float vy = c[half * 2 + 1];
                if (bias)  { vx += bias[col]; vy += bias[col + 1]; }
                if (relu)  { vx = fmaxf(vx, 0.f); vy = fmaxf(vy, 0.f); }
                if (Cs) {
                    __nv_bfloat16 hx, lx, hy, ly;
                    split2(vx, hx, lx); split2(vy, hy, ly);
                    __nv_bfloat16* orow = Cs + (size_t)row * 3 * Kout;
                    *(__nv_bfloat162*)(orow + col)            = __nv_bfloat162(hx, hy);
                    *(__nv_bfloat162*)(orow + Kout + col)     = __nv_bfloat162(lx, ly);
                    *(__nv_bfloat162*)(orow + 2 * Kout + col) = __nv_bfloat162(hx, hy);
                } else {
                    if (residual) {
                        const float2 rv = *(const float2*)(residual + (size_t)row * N + col);
                        vx += rv.x; vy += rv.y;
                    }
                    float2 o; o.x = vx; o.y = vy;
                    *(float2*)(C + (size_t)row * N + col) = o;
                }
            }
        }
    }
}

// ---------------- flash attention (band + global), fused-qkv input ----------
#define AST 68
__global__ __launch_bounds__(256) void attn_kernel(const float* __restrict__ qkv,
                                                   __nv_bfloat16* __restrict__ a3) {
    extern __shared__ float fsm[];
    float* Qs = fsm;
    float* Ks = Qs + 64 * AST;
    float* Vs = Ks + 64 * AST;
    float* Ps = Vs + 64 * AST;

    const int h  = blockIdx.y;
    const int q0 = blockIdx.x * 64;
    const int tid = threadIdx.x;
    const int qcol = h * HD;

#pragma unroll
    for (int i = 0; i < 4; i++) {
        int idx = tid + i * 256;
        int r = idx >> 4, c4 = (idx & 15) << 2;
        float4 qv = *(const float4*)(qkv + (size_t)(q0 + r) * QKVW + qcol + c4);
        qv.x *= 0.125f; qv.y *= 0.125f; qv.z *= 0.125f; qv.w *= 0.125f;
        *(float4*)(Qs + r * AST + c4) = qv;
    }

    const int qbase = tid >> 4;
    const int kbase = tid & 15;
    const int dv    = (tid & 15) * 4;

    float m[4], l[4], acc[4][4];
#pragma unroll
    for (int i = 0; i < 4; i++) {
        m[i] = -1e30f; l[i] = 0.0f;
#pragma unroll
        for (int j = 0; j < 4; j++) acc[i][j] = 0.0f;
    }

    int jlo, jhi;
    if (q0 < 64) { jlo = 0; jhi = 31; }
    else {
        int lo = q0 - 256; jlo = lo > 0 ? (lo >> 6) : 0;
        int hi = (q0 + 63 + 256) >> 6; jhi = hi < 31 ? hi : 31;
    }
    const bool extra0 = (q0 >= 64) && (jlo > 0);
    const int ntiles = (jhi - jlo + 1) + (extra0 ? 1 : 0);

    __syncthreads();

    for (int t = 0; t < ntiles; t++) {
        int jt = extra0 ? (t == 0 ? 0 : (jlo + t - 1)) : (jlo + t);
        int k0 = jt * 64;
#pragma unroll
        for (int i = 0; i < 8; i++) {
            int idx = tid + i * 256;
            int which = idx >> 10;
            int e = idx & 1023;
            int r = e >> 4, c4 = (e & 15) << 2;
            int col = (which ? 2048 : 1024) + qcol + c4;
            float4 vv = *(const float4*)(qkv + (size_t)(k0 + r) * QKVW + col);
            float* dst = which ? Vs : Ks;
            *(float4*)(dst + r * AST + c4) = vv;
        }
        __syncthreads();

        float sreg[4][4];
#pragma unroll
        for (int i = 0; i < 4; i++)
#pragma unroll
            for (int j = 0; j < 4; j++) sreg[i][j] = 0.0f;
#pragma unroll 4
        for (int kk = 0; kk < 64; kk += 4) {
            float4 qv[4], kv[4];
#pragma unroll
            for (int i = 0; i < 4; i++) qv[i] = *(float4*)(Qs + (qbase + 16 * i) * AST + kk);
#pragma unroll
            for (int j = 0; j < 4; j++) kv[j] = *(float4*)(Ks + (kbase + 16 * j) * AST + kk);
#pragma unroll
            for (int i = 0; i < 4; i++)
#pragma unroll
                for (int j = 0; j < 4; j++)
                    sreg[i][j] += qv[i].x * kv[j].x + qv[i].y * kv[j].y
                                + qv[i].z * kv[j].z + qv[i].w * kv[j].w;
        }

        const bool tileAll = (q0 < 64) || (k0 < 64);
        float corr[4];
#pragma unroll
        for (int i = 0; i < 4; i++) {
            int qr = qbase + 16 * i;
            int gi = q0 + qr;
            if (!tileAll) {
#pragma unroll
                for (int j = 0; j < 4; j++) {
                    int gj = k0 + kbase + 16 * j;
                    int diff = gi - gj; if (diff < 0) diff = -diff;
                    if (diff > 256) sreg[i][j] = -1e30f;
                }
            }
            float mx = fmaxf(fmaxf(sreg[i][0], sreg[i][1]), fmaxf(sreg[i][2], sreg[i][3]));
#pragma unroll
            for (int off = 8; off > 0; off >>= 1)
                mx = fmaxf(mx, __shfl_xor_sync(0xffffffffu, mx, off, 16));
            float mnew = fmaxf(m[i], mx);
            corr[i] = __expf(m[i] - mnew);
            float psum = 0.0f;
#pragma unroll
            for (int j = 0; j < 4; j++) {
                float p = __expf(sreg[i][j] - mnew);
                sreg[i][j] = p;
                psum += p;
            }
#pragma unroll
            for (int off = 8; off > 0; off >>= 1)
                psum += __shfl_xor_sync(0xffffffffu, psum, off, 16);
            l[i] = l[i] * corr[i] + psum;
            m[i] = mnew;
#pragma unroll
            for (int j = 0; j < 4; j++) Ps[qr * AST + kbase + 16 * j] = sreg[i][j];
        }
        __syncthreads();

#pragma unroll
        for (int i = 0; i < 4; i++) {
            acc[i][0] *= corr[i]; acc[i][1] *= corr[i];
            acc[i][2] *= corr[i]; acc[i][3] *= corr[i];
        }
#pragma unroll 4
        for (int j = 0; j < 64; j++) {
            float4 vv = *(const float4*)(Vs + j * AST + dv);
#pragma unroll
            for (int i = 0; i < 4; i++) {
                float p = Ps[(qbase + 16 * i) * AST + j];
                acc[i][0] += p * vv.x; acc[i][1] += p * vv.y;
                acc[i][2] += p * vv.z; acc[i][3] += p * vv.w;
            }
        }
        __syncthreads();
    }

#pragma unroll
    for (int i = 0; i < 4; i++) {
        float inv = 1.0f / l[i];
        int row = q0 + qbase + 16 * i;
        __nv_bfloat16* orow = a3 + (size_t)row * 3 * D + qcol + dv;
        float v0 = acc[i][0] * inv, v1 = acc[i][1] * inv;
        float v2 = acc[i][2] * inv, v3 = acc[i][3] * inv;
        __nv_bfloat16 h0, l0, h1, l1, h2, l2, h3, l3;
        split2(v0, h0, l0); split2(v1, h1, l1);
        split2(v2, h2, l2); split2(v3, h3, l3);
        *(__nv_bfloat162*)(orow)             = __nv_bfloat162(h0, h1);
        *(__nv_bfloat162*)(orow + 2)         = __nv_bfloat162(h2, h3);
        *(__nv_bfloat162*)(orow + D)         = __nv_bfloat162(l0, l1);
        *(__nv_bfloat162*)(orow + D + 2)     = __nv_bfloat162(l2, l3);
        *(__nv_bfloat162*)(orow + 2 * D)     = __nv_bfloat162(h0, h1);
        *(__nv_bfloat162*)(orow + 2 * D + 2) = __nv_bfloat162(h2, h3);
    }
}

// ---------------- launch ----------------
extern "C" void kernel_launch(void* const* d_in, const int* in_sizes, int n_in,
                              void* d_out, int out_size) {
    const int*   ids    = (const int*)d_in[0];
    const float* emb    = (const float*)d_in[2];
    const float* wq     = (const float*)d_in[3];
    const float* wk     = (const float*)d_in[4];
    const float* wv     = (const float*)d_in[5];
    const float* wo     = (const float*)d_in[6];
    const float* ln1_s  = (const float*)d_in[7];
    const float* ln1_b  = (const float*)d_in[8];
    const float* ln2_s  = (const float*)d_in[9];
    const float* ln2_b  = (const float*)d_in[10];
    const float* w1     = (const float*)d_in[11];
    const float* b1     = (const float*)d_in[12];
    const float* w2     = (const float*)d_in[13];
    const float* b2     = (const float*)d_in[14];
    const float* lnf_s  = (const float*)d_in[15];
    const float* lnf_b  = (const float*)d_in[16];
    float* out = (float*)d_out;

    void *px, *pqkv, *pa3, *py3, *pwT;
    cudaGetSymbolAddress(&px, g_x);
    cudaGetSymbolAddress(&pqkv, g_qkv);
    cudaGetSymbolAddress(&pa3, g_a3);
    cudaGetSymbolAddress(&py3, g_y3);
    cudaGetSymbolAddress(&pwT, g_wT);
    float* x = (float*)px;
    float* qkv = (float*)pqkv;
    __nv_bfloat16* a3 = (__nv_bfloat16*)pa3;
    __nv_bfloat16* y3 = (__nv_bfloat16*)py3;
    __nv_bfloat16* wT = (__nv_bfloat16*)pwT;

    const int ATTN_SMEM = (4 * 64 * AST) * (int)sizeof(float);
    cudaFuncSetAttribute(attn_kernel, cudaFuncAttributeMaxDynamicSharedMemorySize, ATTN_SMEM);
    const int SM128 = 3 * (128 + 128) * 144;   // 110592
    const int SM256 = 3 * (256 + 128) * 144;   // 165888
    cudaFuncSetAttribute(gemm_tpl<128>, cudaFuncAttributeMaxDynamicSharedMemorySize, SM128);
    cudaFuncSetAttribute(gemm_tpl<256>, cudaFuncAttributeMaxDynamicSharedMemorySize, SM256);

    dim3 cw_dd(D / 32, D / 32);
    dim3 cw_dm(D / 32, MM / 32);
    dim3 cw_md(MM / 32, D / 32);

    embed_kernel<<<S, 256>>>(ids, emb, x);                               // 0
    convW3_kernel<<<dim3(32, 32, 3), 256>>>(wq, wk, wv, wT + WT_QKV);    // 1
    ln_split_kernel<<<S, 256>>>(x, ln1_s, ln1_b, a3);                    // 2

    for (int l = 0; l < LAY; l++) {
        size_t woff = (size_t)l * D * D;
        if (l > 0) {
            convW3_kernel<<<dim3(32, 32, 3), 256>>>(wq + woff, wk + woff, wv + woff, wT + WT_QKV);
            ln_split_kernel<<<S, 256>>>(x, ln1_s + l * D, ln1_b + l * D, a3);
        }
        gemm_tpl<256><<<dim3(QKVW / 128, S / 256), 512, SM256>>>(        // 3 (l=0)
            a3, wT + WT_QKV, qkv, nullptr, 0, QKVW, 3 * D, nullptr, nullptr, 0);
        attn_kernel<<<dim3(S / 64, H), 256, ATTN_SMEM>>>(qkv, a3);       // 4 (l=0)
        convW_kernel<<<cw_dd, 256>>>(wo + woff, wT + WT_WO, D, D);
        gemm_tpl<128><<<dim3(D / 128, S / 128), 512, SM128>>>(
            a3, wT + WT_WO, x, nullptr, 0, D, 3 * D, nullptr, x, 0);
        ln_split_kernel<<<S, 256>>>(x, ln2_s + l * D, ln2_b + l * D, a3);
        convW_kernel<<<cw_dm, 256>>>(w1 + (size_t)l * D * MM, wT + WT_W1, D, MM);
        gemm_tpl<256><<<dim3(MM / 128, S / 256), 512, SM256>>>(
            a3, wT + WT_W1, nullptr, y3, MM, MM, 3 * D, b1 + (size_t)l * MM, nullptr, 1);
        convW_kernel<<<cw_md, 256>>>(w2 + (size_t)l * MM * D, wT + WT_W2, MM, D);
        gemm_tpl<128><<<dim3(D / 128, S / 128), 512, SM128>>>(
            y3, wT + WT_W2, x, nullptr, 0, D, 3 * MM, b2 + (size_t)l * D, x, 0);
    }
    ln_kernel<<<S, 256>>>(x, lnf_s, lnf_b, out);
}

// round 10
// speedup vs baseline: 1.6350x; 1.0386x over previous
#include <cuda_runtime.h>
#include <cuda_bf16.h>
#include <math.h>
#include <stdint.h>

#define S   2048
#define D   1024
#define H   16
#define HD  64
#define MM  4096
#define LAY 4
#define QKVW 3072

// ---------------- scratch (device globals) ----------------
__device__ float g_x[S * D];
__device__ float g_qkv[S * QKVW];
__device__ __nv_bfloat16 g_a3[S * 3 * D];
__device__ __nv_bfloat16 g_y3[S * 3 * MM];
__device__ __nv_bfloat16 g_wT[38 * 1024 * 1024];
#define WT_QKV 0
#define WT_WO  9437184u
#define WT_W1  12582912u
#define WT_W2  25165824u

// ================= PTX helpers =================
__device__ __forceinline__ uint32_t smem_u32(const void* p) {
    uint32_t a;
    asm("{ .reg .u64 t; cvta.to.shared.u64 t, %1; cvt.u32.u64 %0, t; }" : "=r"(a) : "l"(p));
    return a;
}
__device__ __forceinline__ void cp16(uint32_t saddr, const void* g) {
    asm volatile("cp.async.cg.shared.global [%0], [%1], 16;" :: "r"(saddr), "l"(g));
}
#define CP_COMMIT() asm volatile("cp.async.commit_group;" ::: "memory")
#define CP_WAIT1()  asm volatile("cp.async.wait_group 1;" ::: "memory")

__device__ __forceinline__ void ldsm4(uint32_t* r, uint32_t a) {
    asm volatile("ldmatrix.sync.aligned.m8n8.x4.shared.b16 {%0,%1,%2,%3}, [%4];"
                 : "=r"(r[0]), "=r"(r[1]), "=r"(r[2]), "=r"(r[3]) : "r"(a));
}
__device__ __forceinline__ void mma16816(float* c, const uint32_t* a, uint32_t b0, uint32_t b1) {
    asm volatile("mma.sync.aligned.m16n8k16.row.col.f32.bf16.bf16.f32 "
                 "{%0,%1,%2,%3}, {%4,%5,%6,%7}, {%8,%9}, {%0,%1,%2,%3};"
                 : "+f"(c[0]), "+f"(c[1]), "+f"(c[2]), "+f"(c[3])
                 : "r"(a[0]), "r"(a[1]), "r"(a[2]), "r"(a[3]), "r"(b0), "r"(b1));
}
__device__ __forceinline__ void split2(float a, __nv_bfloat16& hi, __nv_bfloat16& lo) {
    hi = __float2bfloat16(a);
    lo = __float2bfloat16(a - __bfloat162float(hi));
}

// ---------------- embedding + sinusoidal positional encoding ----------------
__global__ __launch_bounds__(256) void embed_kernel(const int* __restrict__ ids,
                                                    const float* __restrict__ emb,
                                                    float* __restrict__ x) {
    int s = blockIdx.x;
    int id = ids[s];
    const double c = -9.210340371976184 / 1024.0;
    for (int d = threadIdx.x; d < D; d += 256) {
        int p2 = d & ~1;
        double freq = exp((double)p2 * c);
        double phase = (double)s * freq;
        double pe = (d & 1) ? cos(phase) : sin(phase);
        x[s * D + d] = emb[id * D + d] + (float)pe;
    }
}

// ---------------- LayerNorm -> fp32 out (final) ----------------
__global__ __launch_bounds__(256) void ln_kernel(const float* __restrict__ x,
                                                 const float* __restrict__ sc,
                                                 const float* __restrict__ bi,
                                                 float* __restrict__ out) {
    __shared__ float ssum[256], ssq[256];
    int s = blockIdx.x, tid = threadIdx.x;
    float4 v = ((const float4*)(x + s * D))[tid];
    ssum[tid] = v.x + v.y + v.z + v.w;
    ssq[tid]  = v.x * v.x + v.y * v.y + v.z * v.z + v.w * v.w;
    __syncthreads();
#pragma unroll
    for (int off = 128; off > 0; off >>= 1) {
        if (tid < off) { ssum[tid] += ssum[tid + off]; ssq[tid] += ssq[tid + off]; }
        __syncthreads();
    }
    float mu  = ssum[0] * (1.0f / 1024.0f);
    float var = ssq[0] * (1.0f / 1024.0f) - mu * mu;
    float rs  = rsqrtf(var + 1e-6f);
    float4 scv = ((const float4*)sc)[tid];
    float4 biv = ((const float4*)bi)[tid];
    float4 o;
    o.x = (v.x - mu) * rs * scv.x + biv.x;
    o.y = (v.y - mu) * rs * scv.y + biv.y;
    o.z = (v.z - mu) * rs * scv.z + biv.z;
    o.w = (v.w - mu) * rs * scv.w + biv.w;
    ((float4*)(out + s * D))[tid] = o;
}

// ---------------- LayerNorm -> split bf16 [hi|lo|hi] into a3 ----------------
__global__ __launch_bounds__(256) void ln_split_kernel(const float* __restrict__ x,
                                                       const float* __restrict__ sc,
                                                       const float* __restrict__ bi,
                                                       __nv_bfloat16* __restrict__ a3) {
    __shared__ float ssum[256], ssq[256];
    int s = blockIdx.x, tid = threadIdx.x;
    float4 v = ((const float4*)(x + s * D))[tid];
    ssum[tid] = v.x + v.y + v.z + v.w;
    ssq[tid]  = v.x * v.x + v.y * v.y + v.z * v.z + v.w * v.w;
    __syncthreads();
#pragma unroll
    for (int off = 128; off > 0; off >>= 1) {
        if (tid < off) { ssum[tid] += ssum[tid + off]; ssq[tid] += ssq[tid + off]; }
        __syncthreads();
    }
    float mu  = ssum[0] * (1.0f / 1024.0f);
    float var = ssq[0] * (1.0f / 1024.0f) - mu * mu;
    float rs  = rsqrtf(var + 1e-6f);
    float4 scv = ((const float4*)sc)[tid];
    float4 biv = ((const float4*)bi)[tid];
    float o[4];
    o[0] = (v.x - mu) * rs * scv.x + biv.x;
    o[1] = (v.y - mu) * rs * scv.y + biv.y;
    o[2] = (v.z - mu) * rs * scv.z + biv.z;
    o[3] = (v.w - mu) * rs * scv.w + biv.w;
    __nv_bfloat16 hi[4], lo[4];
#pragma unroll
    for (int j = 0; j < 4; j++) split2(o[j], hi[j], lo[j]);
    __nv_bfloat16* orow = a3 + (size_t)s * 3 * D + tid * 4;
    *(__nv_bfloat162*)(orow)           = __nv_bfloat162(hi[0], hi[1]);
    *(__nv_bfloat162*)(orow + 2)       = __nv_bfloat162(hi[2], hi[3]);
    *(__nv_bfloat162*)(orow + D)       = __nv_bfloat162(lo[0], lo[1]);
    *(__nv_bfloat162*)(orow + D + 2)   = __nv_bfloat162(lo[2], lo[3]);
    *(__nv_bfloat162*)(orow + 2*D)     = __nv_bfloat162(hi[0], hi[1]);
    *(__nv_bfloat162*)(orow + 2*D + 2) = __nv_bfloat162(hi[2], hi[3]);
}

// -------- weights: W[K,N] fp32 -> Wt[N,3K] bf16 = [hi|hi|lo] (transposed) ----
__global__ __launch_bounds__(256) void convW_kernel(const float* __restrict__ W,
                                                    __nv_bfloat16* __restrict__ Wt,
                                                    int K, int N) {
    __shared__ float t[32][33];
    int k0 = blockIdx.x * 32, n0 = blockIdx.y * 32;
    int tx = threadIdx.x & 31, ty = threadIdx.x >> 5;
#pragma unroll
    for (int i = 0; i < 4; i++)
        t[ty + i * 8][tx] = W[(size_t)(k0 + ty + i * 8) * N + n0 + tx];
    __syncthreads();
#pragma unroll
    for (int i = 0; i < 4; i++) {
        int n = n0 + ty + i * 8, k = k0 + tx;
        __nv_bfloat16 hi, lo;
        split2(t[tx][ty + i * 8], hi, lo);
        __nv_bfloat16* orow = Wt + (size_t)n * 3 * K;
        orow[k] = hi; orow[K + k] = hi; orow[2 * K + k] = lo;
    }
}
__global__ __launch_bounds__(256) void convW3_kernel(const float* __restrict__ wq,
                                                     const float* __restrict__ wk,
                                                     const float* __restrict__ wv,
                                                     __nv_bfloat16* __restrict__ Wt) {
    __shared__ float t[32][33];
    const float* W = (blockIdx.z == 0) ? wq : (blockIdx.z == 1) ? wk : wv;
    const int K = D, N = D;
    int k0 = blockIdx.x * 32, n0 = blockIdx.y * 32;
    int tx = threadIdx.x & 31, ty = threadIdx.x >> 5;
#pragma unroll
    for (int i = 0; i < 4; i++)
        t[ty + i * 8][tx] = W[(size_t)(k0 + ty + i * 8) * N + n0 + tx];
    __syncthreads();
#pragma unroll
    for (int i = 0; i < 4; i++) {
        int n = n0 + ty + i * 8 + blockIdx.z * 1024, k = k0 + tx;
        __nv_bfloat16 hi, lo;
        split2(t[tx][ty + i * 8], hi, lo);
        __nv_bfloat16* orow = Wt + (size_t)n * 3 * K;
        orow[k] = hi; orow[K + k] = hi; orow[2 * K + k] = lo;
    }
}

// ---- HMMA bf16 GEMM: 128x128 CTA, 256 threads, 2 CTAs/SM, BK=64, 3 stages ----
// 8 warps (2m x 4n), warp tile 64x32. SMEM rows 144B. launch_bounds forces 2 CTAs/SM.
__global__ __launch_bounds__(256, 2) void gemm_kernel(const __nv_bfloat16* __restrict__ A,
                                                      const __nv_bfloat16* __restrict__ Bt,
                                                      float* __restrict__ C,
                                                      __nv_bfloat16* __restrict__ Cs, int Kout,
                                                      int N, int K3,
                                                      const float* __restrict__ bias,
                                                      const float* residual, int relu) {
    extern __shared__ char sm[];
    constexpr int ROWB = 144;
    constexpr int STAGE = 256 * ROWB;          // (128 A + 128 B) rows
    const int tid = threadIdx.x, lane = tid & 31, wid = tid >> 5;
    const int bm = blockIdx.y * 128, bn = blockIdx.x * 128;
    const int wm = (wid >> 2) * 64, wn = (wid & 3) * 32;
    const size_t rs = (size_t)K3 * 2;
    const char* Ag = (const char*)A + (size_t)bm * rs;
    const char* Bg = (const char*)Bt + (size_t)bn * rs;
    const uint32_t smb = smem_u32(sm);

    uint32_t a_off[4], b_off[2];
#pragma unroll
    for (int f = 0; f < 4; f++)
        a_off[f] = (uint32_t)((wm + f * 16 + (lane & 15)) * ROWB + ((lane >> 4) * 16));
#pragma unroll
    for (int pi = 0; pi < 2; pi++) {
        int row = wn + pi * 16 + (lane & 7) + ((lane >> 4) << 3);
        b_off[pi] = (uint32_t)(row * ROWB + (((lane >> 3) & 1) * 16));
    }

    float acc[4][4][4];
#pragma unroll
    for (int f = 0; f < 4; f++)
#pragma unroll
        for (int ni = 0; ni < 4; ni++)
#pragma unroll
            for (int j = 0; j < 4; j++) acc[f][ni][j] = 0.0f;

    auto load_stage = [&](int buf, int kt) {
        uint32_t sa = smb + buf * STAGE, sb2 = sa + 128 * ROWB;
        size_t gk = (size_t)kt * 128;
#pragma unroll
        for (int i = 0; i < 4; i++) {              // A: 1024 chunks / 256 threads
            int c = tid + i * 256, r = c >> 3, cb = (c & 7) << 4;
            cp16(sa + r * ROWB + cb, Ag + (size_t)r * rs + gk + cb);
        }
#pragma unroll
        for (int i = 0; i < 4; i++) {              // B: 1024 chunks / 256 threads
            int c = tid + i * 256, r = c >> 3, cb = (c & 7) << 4;
            cp16(sb2 + r * ROWB + cb, Bg + (size_t)r * rs + gk + cb);
        }
    };

    const int KT = K3 >> 6;
    load_stage(0, 0); CP_COMMIT();
    load_stage(1, 1); CP_COMMIT();

    int buf = 0;
    for (int kt = 0; kt < KT; kt++) {
        CP_WAIT1();
        __syncthreads();
        if (kt + 2 < KT) {
            int nbuf = buf + 2; if (nbuf >= 3) nbuf -= 3;
            load_stage(nbuf, kt + 2);
        }
        CP_COMMIT();
        const uint32_t ab = smb + buf * STAGE, bb = ab + 128 * ROWB;
#pragma unroll
        for (int ks = 0; ks < 4; ks++) {
            uint32_t a[4][4];
#pragma unroll
            for (int f = 0; f < 4; f++) ldsm4(a[f], ab + a_off[f] + ks * 32);
#pragma unroll
            for (int pi = 0; pi < 2; pi++) {
                uint32_t b[4];
                ldsm4(b, bb + b_off[pi] + ks * 32);
#pragma unroll
                for (int f = 0; f < 4; f++) {
                    mma16816(acc[f][2 * pi],     a[f], b[0], b[1]);
                    mma16816(acc[f][2 * pi + 1], a[f], b[2], b[3]);
                }
            }
        }
        buf = (buf == 2) ? 0 : buf + 1;
    }

    const int erow = lane >> 2, ecol = (lane & 3) * 2;
#pragma unroll
    for (int f = 0; f < 4; f++) {
#pragma unroll
        for (int ni = 0; ni < 4; ni++) {
            float* c = acc[f][ni];
            int col = bn + wn + ni * 8 + ecol;
#pragma unroll
            for (int half = 0; half < 2; half++) {
                int row = bm + wm + f * 16 + erow + half * 8;
                float vx = c[half * 2 + 0];
                float vy = c[half * 2 + 1];
                if (bias)  { vx += bias[col]; vy += bias[col + 1]; }
                if (relu)  { vx = fmaxf(vx, 0.f); vy = fmaxf(vy, 0.f); }
                if (Cs) {
                    __nv_bfloat16 hx, lx, hy, ly;
                    split2(vx, hx, lx); split2(vy, hy, ly);
                    __nv_bfloat16* orow = Cs + (size_t)row * 3 * Kout;
                    *(__nv_bfloat162*)(orow + col)            = __nv_bfloat162(hx, hy);
                    *(__nv_bfloat162*)(orow + Kout + col)     = __nv_bfloat162(lx, ly);
                    *(__nv_bfloat162*)(orow + 2 * Kout + col) = __nv_bfloat162(hx, hy);
                } else {
                    if (residual) {
                        const float2 rv = *(const float2*)(residual + (size_t)row * N + col);
                        vx += rv.x; vy += rv.y;
                    }
                    float2 o; o.x = vx; o.y = vy;
                    *(float2*)(C + (size_t)row * N + col) = o;
                }
            }
        }
    }
}

// ---------------- flash attention (band + global), fused-qkv input ----------
#define AST 68
__global__ __launch_bounds__(256) void attn_kernel(const float* __restrict__ qkv,
                                                   __nv_bfloat16* __restrict__ a3) {
    extern __shared__ float fsm[];
    float* Qs = fsm;
    float* Ks = Qs + 64 * AST;
    float* Vs = Ks + 64 * AST;
    float* Ps = Vs + 64 * AST;

    const int h  = blockIdx.y;
    const int q0 = blockIdx.x * 64;
    const int tid = threadIdx.x;
    const int qcol = h * HD;

#pragma unroll
    for (int i = 0; i < 4; i++) {
        int idx = tid + i * 256;
        int r = idx >> 4, c4 = (idx & 15) << 2;
        float4 qv = *(const float4*)(qkv + (size_t)(q0 + r) * QKVW + qcol + c4);
        qv.x *= 0.125f; qv.y *= 0.125f; qv.z *= 0.125f; qv.w *= 0.125f;
        *(float4*)(Qs + r * AST + c4) = qv;
    }

    const int qbase = tid >> 4;
    const int kbase = tid & 15;
    const int dv    = (tid & 15) * 4;

    float m[4], l[4], acc[4][4];
#pragma unroll
    for (int i = 0; i < 4; i++) {
        m[i] = -1e30f; l[i] = 0.0f;
#pragma unroll
        for (int j = 0; j < 4; j++) acc[i][j] = 0.0f;
    }

    int jlo, jhi;
    if (q0 < 64) { jlo = 0; jhi = 31; }
    else {
        int lo = q0 - 256; jlo = lo > 0 ? (lo >> 6) : 0;
        int hi = (q0 + 63 + 256) >> 6; jhi = hi < 31 ? hi : 31;
    }
    const bool extra0 = (q0 >= 64) && (jlo > 0);
    const int ntiles = (jhi - jlo + 1) + (extra0 ? 1 : 0);

    __syncthreads();

    for (int t = 0; t < ntiles; t++) {
        int jt = extra0 ? (t == 0 ? 0 : (jlo + t - 1)) : (jlo + t);
        int k0 = jt * 64;
#pragma unroll
        for (int i = 0; i < 8; i++) {
            int idx = tid + i * 256;
            int which = idx >> 10;
            int e = idx & 1023;
            int r = e >> 4, c4 = (e & 15) << 2;
            int col = (which ? 2048 : 1024) + qcol + c4;
            float4 vv = *(const float4*)(qkv + (size_t)(k0 + r) * QKVW + col);
            float* dst = which ? Vs : Ks;
            *(float4*)(dst + r * AST + c4) = vv;
        }
        __syncthreads();

        float sreg[4][4];
#pragma unroll
        for (int i = 0; i < 4; i++)
#pragma unroll
            for (int j = 0; j < 4; j++) sreg[i][j] = 0.0f;
#pragma unroll 4
        for (int kk = 0; kk < 64; kk += 4) {
            float4 qv[4], kv[4];
#pragma unroll
            for (int i = 0; i < 4; i++) qv[i] = *(float4*)(Qs + (qbase + 16 * i) * AST + kk);
#pragma unroll
            for (int j = 0; j < 4; j++) kv[j] = *(float4*)(Ks + (kbase + 16 * j) * AST + kk);
#pragma unroll
            for (int i = 0; i < 4; i++)
#pragma unroll
                for (int j = 0; j < 4; j++)
                    sreg[i][j] += qv[i].x * kv[j].x + qv[i].y * kv[j].y
                                + qv[i].z * kv[j].z + qv[i].w * kv[j].w;
        }

        const bool tileAll = (q0 < 64) || (k0 < 64);
        float corr[4];
#pragma unroll
        for (int i = 0; i < 4; i++) {
            int qr = qbase + 16 * i;
            int gi = q0 + qr;
            if (!tileAll) {
#pragma unroll
                for (int j = 0; j < 4; j++) {
                    int gj = k0 + kbase + 16 * j;
                    int diff = gi - gj; if (diff < 0) diff = -diff;
                    if (diff > 256) sreg[i][j] = -1e30f;
                }
            }
            float mx = fmaxf(fmaxf(sreg[i][0], sreg[i][1]), fmaxf(sreg[i][2], sreg[i][3]));
#pragma unroll
            for (int off = 8; off > 0; off >>= 1)
                mx = fmaxf(mx, __shfl_xor_sync(0xffffffffu, mx, off, 16));
            float mnew = fmaxf(m[i], mx);
            corr[i] = __expf(m[i] - mnew);
            float psum = 0.0f;
#pragma unroll
            for (int j = 0; j < 4; j++) {
                float p = __expf(sreg[i][j] - mnew);
                sreg[i][j] = p;
                psum += p;
            }
#pragma unroll
            for (int off = 8; off > 0; off >>= 1)
                psum += __shfl_xor_sync(0xffffffffu, psum, off, 16);
            l[i] = l[i] * corr[i] + psum;
            m[i] = mnew;
#pragma unroll
            for (int j = 0; j < 4; j++) Ps[qr * AST + kbase + 16 * j] = sreg[i][j];
        }
        __syncthreads();

#pragma unroll
        for (int i = 0; i < 4; i++) {
            acc[i][0] *= corr[i]; acc[i][1] *= corr[i];
            acc[i][2] *= corr[i]; acc[i][3] *= corr[i];
        }
#pragma unroll 4
        for (int j = 0; j < 64; j++) {
            float4 vv = *(const float4*)(Vs + j * AST + dv);
#pragma unroll
            for (int i = 0; i < 4; i++) {
                float p = Ps[(qbase + 16 * i) * AST + j];
                acc[i][0] += p * vv.x; acc[i][1] += p * vv.y;
                acc[i][2] += p * vv.z; acc[i][3] += p * vv.w;
            }
        }
        __syncthreads();
    }

#pragma unroll
    for (int i = 0; i < 4; i++) {
        float inv = 1.0f / l[i];
        int row = q0 + qbase + 16 * i;
        __nv_bfloat16* orow = a3 + (size_t)row * 3 * D + qcol + dv;
        float v0 = acc[i][0] * inv, v1 = acc[i][1] * inv;
        float v2 = acc[i][2] * inv, v3 = acc[i][3] * inv;
        __nv_bfloat16 h0, l0, h1, l1, h2, l2, h3, l3;
        split2(v0, h0, l0); split2(v1, h1, l1);
        split2(v2, h2, l2); split2(v3, h3, l3);
        *(__nv_bfloat162*)(orow)             = __nv_bfloat162(h0, h1);
        *(__nv_bfloat162*)(orow + 2)         = __nv_bfloat162(h2, h3);
        *(__nv_bfloat162*)(orow + D)         = __nv_bfloat162(l0, l1);
        *(__nv_bfloat162*)(orow + D + 2)     = __nv_bfloat162(l2, l3);
        *(__nv_bfloat162*)(orow + 2 * D)     = __nv_bfloat162(h0, h1);
        *(__nv_bfloat162*)(orow + 2 * D + 2) = __nv_bfloat162(h2, h3);
    }
}

// ---------------- launch ----------------
extern "C" void kernel_launch(void* const* d_in, const int* in_sizes, int n_in,
                              void* d_out, int out_size) {
    const int*   ids    = (const int*)d_in[0];
    const float* emb    = (const float*)d_in[2];
    const float* wq     = (const float*)d_in[3];
    const float* wk     = (const float*)d_in[4];
    const float* wv     = (const float*)d_in[5];
    const float* wo     = (const float*)d_in[6];
    const float* ln1_s  = (const float*)d_in[7];
    const float* ln1_b  = (const float*)d_in[8];
    const float* ln2_s  = (const float*)d_in[9];
    const float* ln2_b  = (const float*)d_in[10];
    const float* w1     = (const float*)d_in[11];
    const float* b1     = (const float*)d_in[12];
    const float* w2     = (const float*)d_in[13];
    const float* b2     = (const float*)d_in[14];
    const float* lnf_s  = (const float*)d_in[15];
    const float* lnf_b  = (const float*)d_in[16];
    float* out = (float*)d_out;

    void *px, *pqkv, *pa3, *py3, *pwT;
    cudaGetSymbolAddress(&px, g_x);
    cudaGetSymbolAddress(&pqkv, g_qkv);
    cudaGetSymbolAddress(&pa3, g_a3);
    cudaGetSymbolAddress(&py3, g_y3);
    cudaGetSymbolAddress(&pwT, g_wT);
    float* x = (float*)px;
    float* qkv = (float*)pqkv;
    __nv_bfloat16* a3 = (__nv_bfloat16*)pa3;
    __nv_bfloat16* y3 = (__nv_bfloat16*)py3;
    __nv_bfloat16* wT = (__nv_bfloat16*)pwT;

    const int ATTN_SMEM = (4 * 64 * AST) * (int)sizeof(float);
    cudaFuncSetAttribute(attn_kernel, cudaFuncAttributeMaxDynamicSharedMemorySize, ATTN_SMEM);
    const int GS = 3 * 256 * 144;   // 110592 bytes, 2 CTAs/SM
    cudaFuncSetAttribute(gemm_kernel, cudaFuncAttributeMaxDynamicSharedMemorySize, GS);

    dim3 cw_dd(D / 32, D / 32);
    dim3 cw_dm(D / 32, MM / 32);
    dim3 cw_md(MM / 32, D / 32);

    embed_kernel<<<S, 256>>>(ids, emb, x);                               // 0
    convW3_kernel<<<dim3(32, 32, 3), 256>>>(wq, wk, wv, wT + WT_QKV);    // 1
    ln_split_kernel<<<S, 256>>>(x, ln1_s, ln1_b, a3);                    // 2

    for (int l = 0; l < LAY; l++) {
        size_t woff = (size_t)l * D * D;
        if (l > 0) {
            convW3_kernel<<<dim3(32, 32, 3), 256>>>(wq + woff, wk + woff, wv + woff, wT + WT_QKV);
            ln_split_kernel<<<S, 256>>>(x, ln1_s + l * D, ln1_b + l * D, a3);
        }
        gemm_kernel<<<dim3(QKVW / 128, S / 128), 256, GS>>>(             // 3 (l=0)
            a3, wT + WT_QKV, qkv, nullptr, 0, QKVW, 3 * D, nullptr, nullptr, 0);
        attn_kernel<<<dim3(S / 64, H), 256, ATTN_SMEM>>>(qkv, a3);       // 4 (l=0)
        convW_kernel<<<cw_dd, 256>>>(wo + woff, wT + WT_WO, D, D);
        gemm_kernel<<<dim3(D / 128, S / 128), 256, GS>>>(
            a3, wT + WT_WO, x, nullptr, 0, D, 3 * D, nullptr, x, 0);
        ln_split_kernel<<<S, 256>>>(x, ln2_s + l * D, ln2_b + l * D, a3);
        convW_kernel<<<cw_dm, 256>>>(w1 + (size_t)l * D * MM, wT + WT_W1, D, MM);
        gemm_kernel<<<dim3(MM / 128, S / 128), 256, GS>>>(
            a3, wT + WT_W1, nullptr, y3, MM, MM, 3 * D, b1 + (size_t)l * MM, nullptr, 1);
        convW_kernel<<<cw_md, 256>>>(w2 + (size_t)l * MM * D, wT + WT_W2, MM, D);
        gemm_kernel<<<dim3(D / 128, S / 128), 256, GS>>>(
            y3, wT + WT_W2, x, nullptr, 0, D, 3 * MM, b2 + (size_t)l * D, x, 0);
    }
    ln_kernel<<<S, 256>>>(x, lnf_s, lnf_b, out);
}

// round 11
// speedup vs baseline: 1.7556x; 1.0737x over previous
#include <cuda_runtime.h>
#include <cuda_bf16.h>
#include <math.h>
#include <stdint.h>

#define S   2048
#define D   1024
#define H   16
#define HD  64
#define MM  4096
#define LAY 4
#define QKVW 3072

// ---------------- scratch (device globals) ----------------
__device__ float g_x[S * D];
__device__ float g_qkv[S * QKVW];
__device__ __nv_bfloat16 g_a3[S * 3 * D];
__device__ __nv_bfloat16 g_y3[S * 3 * MM];
__device__ __nv_bfloat16 g_wT[38 * 1024 * 1024];
#define WT_QKV 0
#define WT_WO  9437184u
#define WT_W1  12582912u
#define WT_W2  25165824u

// ================= PTX helpers =================
__device__ __forceinline__ uint32_t smem_u32(const void* p) {
    uint32_t a;
    asm("{ .reg .u64 t; cvta.to.shared.u64 t, %1; cvt.u32.u64 %0, t; }" : "=r"(a) : "l"(p));
    return a;
}
__device__ __forceinline__ void cp16(uint32_t saddr, const void* g) {
    asm volatile("cp.async.cg.shared.global [%0], [%1], 16;" :: "r"(saddr), "l"(g));
}
#define CP_COMMIT() asm volatile("cp.async.commit_group;" ::: "memory")
#define CP_WAIT1()  asm volatile("cp.async.wait_group 1;" ::: "memory")

__device__ __forceinline__ void ldsm4(uint32_t* r, uint32_t a) {
    asm volatile("ldmatrix.sync.aligned.m8n8.x4.shared.b16 {%0,%1,%2,%3}, [%4];"
                 : "=r"(r[0]), "=r"(r[1]), "=r"(r[2]), "=r"(r[3]) : "r"(a));
}
__device__ __forceinline__ void ldsm4t(uint32_t* r, uint32_t a) {
    asm volatile("ldmatrix.sync.aligned.m8n8.x4.trans.shared.b16 {%0,%1,%2,%3}, [%4];"
                 : "=r"(r[0]), "=r"(r[1]), "=r"(r[2]), "=r"(r[3]) : "r"(a));
}
__device__ __forceinline__ void mma16816(float* c, const uint32_t* a, uint32_t b0, uint32_t b1) {
    asm volatile("mma.sync.aligned.m16n8k16.row.col.f32.bf16.bf16.f32 "
                 "{%0,%1,%2,%3}, {%4,%5,%6,%7}, {%8,%9}, {%0,%1,%2,%3};"
                 : "+f"(c[0]), "+f"(c[1]), "+f"(c[2]), "+f"(c[3])
                 : "r"(a[0]), "r"(a[1]), "r"(a[2]), "r"(a[3]), "r"(b0), "r"(b1));
}
__device__ __forceinline__ void split2(float a, __nv_bfloat16& hi, __nv_bfloat16& lo) {
    hi = __float2bfloat16(a);
    lo = __float2bfloat16(a - __bfloat162float(hi));
}

// ---------------- embedding + sinusoidal positional encoding ----------------
__global__ __launch_bounds__(256) void embed_kernel(const int* __restrict__ ids,
                                                    const float* __restrict__ emb,
                                                    float* __restrict__ x) {
    int s = blockIdx.x;
    int id = ids[s];
    const double c = -9.210340371976184 / 1024.0;
    for (int d = threadIdx.x; d < D; d += 256) {
        int p2 = d & ~1;
        double freq = exp((double)p2 * c);
        double phase = (double)s * freq;
        double pe = (d & 1) ? cos(phase) : sin(phase);
        x[s * D + d] = emb[id * D + d] + (float)pe;
    }
}

// ---------------- LayerNorm -> fp32 out (final) ----------------
__global__ __launch_bounds__(256) void ln_kernel(const float* __restrict__ x,
                                                 const float* __restrict__ sc,
                                                 const float* __restrict__ bi,
                                                 float* __restrict__ out) {
    __shared__ float ssum[256], ssq[256];
    int s = blockIdx.x, tid = threadIdx.x;
    float4 v = ((const float4*)(x + s * D))[tid];
    ssum[tid] = v.x + v.y + v.z + v.w;
    ssq[tid]  = v.x * v.x + v.y * v.y + v.z * v.z + v.w * v.w;
    __syncthreads();
#pragma unroll
    for (int off = 128; off > 0; off >>= 1) {
        if (tid < off) { ssum[tid] += ssum[tid + off]; ssq[tid] += ssq[tid + off]; }
        __syncthreads();
    }
    float mu  = ssum[0] * (1.0f / 1024.0f);
    float var = ssq[0] * (1.0f / 1024.0f) - mu * mu;
    float rs  = rsqrtf(var + 1e-6f);
    float4 scv = ((const float4*)sc)[tid];
    float4 biv = ((const float4*)bi)[tid];
    float4 o;
    o.x = (v.x - mu) * rs * scv.x + biv.x;
    o.y = (v.y - mu) * rs * scv.y + biv.y;
    o.z = (v.z - mu) * rs * scv.z + biv.z;
    o.w = (v.w - mu) * rs * scv.w + biv.w;
    ((float4*)(out + s * D))[tid] = o;
}

// ---------------- LayerNorm -> split bf16 [hi|lo|hi] into a3 ----------------
__global__ __launch_bounds__(256) void ln_split_kernel(const float* __restrict__ x,
                                                       const float* __restrict__ sc,
                                                       const float* __restrict__ bi,
                                                       __nv_bfloat16* __restrict__ a3) {
    __shared__ float ssum[256], ssq[256];
    int s = blockIdx.x, tid = threadIdx.x;
    float4 v = ((const float4*)(x + s * D))[tid];
    ssum[tid] = v.x + v.y + v.z + v.w;
    ssq[tid]  = v.x * v.x + v.y * v.y + v.z * v.z + v.w * v.w;
    __syncthreads();
#pragma unroll
    for (int off = 128; off > 0; off >>= 1) {
        if (tid < off) { ssum[tid] += ssum[tid + off]; ssq[tid] += ssq[tid + off]; }
        __syncthreads();
    }
    float mu  = ssum[0] * (1.0f / 1024.0f);
    float var = ssq[0] * (1.0f / 1024.0f) - mu * mu;
    float rs  = rsqrtf(var + 1e-6f);
    float4 scv = ((const float4*)sc)[tid];
    float4 biv = ((const float4*)bi)[tid];
    float o[4];
    o[0] = (v.x - mu) * rs * scv.x + biv.x;
    o[1] = (v.y - mu) * rs * scv.y + biv.y;
    o[2] = (v.z - mu) * rs * scv.z + biv.z;
    o[3] = (v.w - mu) * rs * scv.w + biv.w;
    __nv_bfloat16 hi[4], lo[4];
#pragma unroll
    for (int j = 0; j < 4; j++) split2(o[j], hi[j], lo[j]);
    __nv_bfloat16* orow = a3 + (size_t)s * 3 * D + tid * 4;
    *(__nv_bfloat162*)(orow)           = __nv_bfloat162(hi[0], hi[1]);
    *(__nv_bfloat162*)(orow + 2)       = __nv_bfloat162(hi[2], hi[3]);
    *(__nv_bfloat162*)(orow + D)       = __nv_bfloat162(lo[0], lo[1]);
    *(__nv_bfloat162*)(orow + D + 2)   = __nv_bfloat162(lo[2], lo[3]);
    *(__nv_bfloat162*)(orow + 2*D)     = __nv_bfloat162(hi[0], hi[1]);
    *(__nv_bfloat162*)(orow + 2*D + 2) = __nv_bfloat162(hi[2], hi[3]);
}

// -------- weights: W[K,N] fp32 -> Wt[N,3K] bf16 = [hi|hi|lo] (transposed) ----
__global__ __launch_bounds__(256) void convW_kernel(const float* __restrict__ W,
                                                    __nv_bfloat16* __restrict__ Wt,
                                                    int K, int N) {
    __shared__ float t[32][33];
    int k0 = blockIdx.x * 32, n0 = blockIdx.y * 32;
    int tx = threadIdx.x & 31, ty = threadIdx.x >> 5;
#pragma unroll
    for (int i = 0; i < 4; i++)
        t[ty + i * 8][tx] = W[(size_t)(k0 + ty + i * 8) * N + n0 + tx];
    __syncthreads();
#pragma unroll
    for (int i = 0; i < 4; i++) {
        int n = n0 + ty + i * 8, k = k0 + tx;
        __nv_bfloat16 hi, lo;
        split2(t[tx][ty + i * 8], hi, lo);
        __nv_bfloat16* orow = Wt + (size_t)n * 3 * K;
        orow[k] = hi; orow[K + k] = hi; orow[2 * K + k] = lo;
    }
}
__global__ __launch_bounds__(256) void convW3_kernel(const float* __restrict__ wq,
                                                     const float* __restrict__ wk,
                                                     const float* __restrict__ wv,
                                                     __nv_bfloat16* __restrict__ Wt) {
    __shared__ float t[32][33];
    const float* W = (blockIdx.z == 0) ? wq : (blockIdx.z == 1) ? wk : wv;
    const int K = D, N = D;
    int k0 = blockIdx.x * 32, n0 = blockIdx.y * 32;
    int tx = threadIdx.x & 31, ty = threadIdx.x >> 5;
#pragma unroll
    for (int i = 0; i < 4; i++)
        t[ty + i * 8][tx] = W[(size_t)(k0 + ty + i * 8) * N + n0 + tx];
    __syncthreads();
#pragma unroll
    for (int i = 0; i < 4; i++) {
        int n = n0 + ty + i * 8 + blockIdx.z * 1024, k = k0 + tx;
        __nv_bfloat16 hi, lo;
        split2(t[tx][ty + i * 8], hi, lo);
        __nv_bfloat16* orow = Wt + (size_t)n * 3 * K;
        orow[k] = hi; orow[K + k] = hi; orow[2 * K + k] = lo;
    }
}

// ---- HMMA bf16 GEMM: MTx128 CTA, 256 threads, 2 CTAs/SM, BK=64, 3 stages ----
// 8 warps (2m x 4n), warp tile (MT/2)x32.
template<int MT>
__global__ __launch_bounds__(256, 2) void gemm_tpl(const __nv_bfloat16* __restrict__ A,
                                                   const __nv_bfloat16* __restrict__ Bt,
                                                   float* __restrict__ C,
                                                   __nv_bfloat16* __restrict__ Cs, int Kout,
                                                   int N, int K3,
                                                   const float* __restrict__ bias,
                                                   const float* residual, int relu) {
    extern __shared__ char sm[];
    constexpr int WTM = MT / 2;          // 64 or 32
    constexpr int FM = WTM / 16;         // 4 or 2
    constexpr int ROWB = 144;
    constexpr int STAGE = (MT + 128) * ROWB;
    const int tid = threadIdx.x, lane = tid & 31, wid = tid >> 5;
    const int bm = blockIdx.y * MT, bn = blockIdx.x * 128;
    const int wm = (wid >> 2) * WTM, wn = (wid & 3) * 32;
    const size_t rs = (size_t)K3 * 2;
    const char* Ag = (const char*)A + (size_t)bm * rs;
    const char* Bg = (const char*)Bt + (size_t)bn * rs;
    const uint32_t smb = smem_u32(sm);

    uint32_t a_off[FM], b_off[2];
#pragma unroll
    for (int f = 0; f < FM; f++)
        a_off[f] = (uint32_t)((wm + f * 16 + (lane & 15)) * ROWB + ((lane >> 4) * 16));
#pragma unroll
    for (int pi = 0; pi < 2; pi++) {
        int row = wn + pi * 16 + (lane & 7) + ((lane >> 4) << 3);
        b_off[pi] = (uint32_t)(row * ROWB + (((lane >> 3) & 1) * 16));
    }

    float acc[FM][4][4];
#pragma unroll
    for (int f = 0; f < FM; f++)
#pragma unroll
        for (int ni = 0; ni < 4; ni++)
#pragma unroll
            for (int j = 0; j < 4; j++) acc[f][ni][j] = 0.0f;

    auto load_stage = [&](int buf, int kt) {
        uint32_t sa = smb + buf * STAGE, sb2 = sa + MT * ROWB;
        size_t gk = (size_t)kt * 128;
#pragma unroll
        for (int i = 0; i < MT / 32; i++) {
            int c = tid + i * 256, r = c >> 3, cb = (c & 7) << 4;
            cp16(sa + r * ROWB + cb, Ag + (size_t)r * rs + gk + cb);
        }
#pragma unroll
        for (int i = 0; i < 4; i++) {
            int c = tid + i * 256, r = c >> 3, cb = (c & 7) << 4;
            cp16(sb2 + r * ROWB + cb, Bg + (size_t)r * rs + gk + cb);
        }
    };

    const int KT = K3 >> 6;
    load_stage(0, 0); CP_COMMIT();
    load_stage(1, 1); CP_COMMIT();

    int buf = 0;
    for (int kt = 0; kt < KT; kt++) {
        CP_WAIT1();
        __syncthreads();
        if (kt + 2 < KT) {
            int nbuf = buf + 2; if (nbuf >= 3) nbuf -= 3;
            load_stage(nbuf, kt + 2);
        }
        CP_COMMIT();
        const uint32_t ab = smb + buf * STAGE, bb = ab + MT * ROWB;
#pragma unroll
        for (int ks = 0; ks < 4; ks++) {
            uint32_t a[FM][4];
#pragma unroll
            for (int f = 0; f < FM; f++) ldsm4(a[f], ab + a_off[f] + ks * 32);
#pragma unroll
            for (int pi = 0; pi < 2; pi++) {
                uint32_t b[4];
                ldsm4(b, bb + b_off[pi] + ks * 32);
#pragma unroll
                for (int f = 0; f < FM; f++) {
                    mma16816(acc[f][2 * pi],     a[f], b[0], b[1]);
                    mma16816(acc[f][2 * pi + 1], a[f], b[2], b[3]);
                }
            }
        }
        buf = (buf == 2) ? 0 : buf + 1;
    }

    const int erow = lane >> 2, ecol = (lane & 3) * 2;
#pragma unroll
    for (int f = 0; f < FM; f++) {
#pragma unroll
        for (int ni = 0; ni < 4; ni++) {
            float* c = acc[f][ni];
            int col = bn + wn + ni * 8 + ecol;
#pragma unroll
            for (int half = 0; half < 2; half++) {
                int row = bm + wm + f * 16 + erow + half * 8;
                float vx = c[half * 2 + 0];
                float vy = c[half * 2 + 1];
                if (bias)  { vx += bias[col]; vy += bias[col + 1]; }
                if (relu)  { vx = fmaxf(vx, 0.f); vy = fmaxf(vy, 0.f); }
                if (Cs) {
                    __nv_bfloat16 hx, lx, hy, ly;
                    split2(vx, hx, lx); split2(vy, hy, ly);
                    __nv_bfloat16* orow = Cs + (size_t)row * 3 * Kout;
                    *(__nv_bfloat162*)(orow + col)            = __nv_bfloat162(hx, hy);
                    *(__nv_bfloat162*)(orow + Kout + col)     = __nv_bfloat162(lx, ly);
                    *(__nv_bfloat162*)(orow + 2 * Kout + col) = __nv_bfloat162(hx, hy);
                } else {
                    if (residual) {
                        const float2 rv = *(const float2*)(residual + (size_t)row * N + col);
                        vx += rv.x; vy += rv.y;
                    }
                    float2 o; o.x = vx; o.y = vy;
                    *(float2*)(C + (size_t)row * N + col) = o;
                }
            }
        }
    }
}

// ------------- tensor-core flash attention (band + global) ------------------
// smem byte offsets
#define A_Q3   0u          // 64 rows x 400B  (Q split [hi|lo|hi] over 192)
#define A_K3   25600u      // 64 rows x 400B  (K split [hi|hi|lo])
#define A_P3   51200u      // 64 rows x 400B  (P split [hi|lo|hi])
#define A_V3   76800u      // 192 rows x 144B (V rows [hi(0-63)|hi(64-127)|lo(128-191)], cols=64 dims)
#define A_PS   104448u     // 64 x 68 fp32 scores
#define A_CORR 121856u     // 64 fp32
#define A_LROW 122112u     // 64 fp32
#define ATTN_SMEM_BYTES 122368

__global__ __launch_bounds__(256) void attn_kernel(const float* __restrict__ qkv,
                                                   __nv_bfloat16* __restrict__ a3) {
    extern __shared__ char smem[];
    const uint32_t sb = smem_u32(smem);
    float* Ps   = (float*)(smem + A_PS);
    float* corr_s = (float*)(smem + A_CORR);
    float* lrow = (float*)(smem + A_LROW);

    const int h  = blockIdx.y;
    const int q0 = blockIdx.x * 64;
    const int tid = threadIdx.x, lane = tid & 31, wid = tid >> 5;
    const int qcol = h * HD;

    // ---- build Q split tile (scaled by 1/8) ----
#pragma unroll
    for (int i = 0; i < 4; i++) {
        int idx = tid + i * 256;                 // 1024 float4
        int r = idx >> 4, c4 = (idx & 15) << 2;
        float4 qv = *(const float4*)(qkv + (size_t)(q0 + r) * QKVW + qcol + c4);
        qv.x *= 0.125f; qv.y *= 0.125f; qv.z *= 0.125f; qv.w *= 0.125f;
        __nv_bfloat16 h0, l0, h1, l1, h2, l2, h3, l3;
        split2(qv.x, h0, l0); split2(qv.y, h1, l1);
        split2(qv.z, h2, l2); split2(qv.w, h3, l3);
        char* row = smem + A_Q3 + r * 400 + 2 * c4;
        *(__nv_bfloat162*)(row)           = __nv_bfloat162(h0, h1);
        *(__nv_bfloat162*)(row + 4)       = __nv_bfloat162(h2, h3);
        *(__nv_bfloat162*)(row + 128)     = __nv_bfloat162(l0, l1);
        *(__nv_bfloat162*)(row + 132)     = __nv_bfloat162(l2, l3);
        *(__nv_bfloat162*)(row + 256)     = __nv_bfloat162(h0, h1);
        *(__nv_bfloat162*)(row + 260)     = __nv_bfloat162(h2, h3);
    }

    // warp layout (both QK and PV): 4 m-warps x 2 n-warps; warp tile 16 x 32
    const int wm = (wid >> 1) * 16;
    const int wn = (wid & 1) * 32;
    const int erow = lane >> 2, ecol = (lane & 3) * 2;

    // ldsm offsets
    const uint32_t aq_off = sb + A_Q3 + (wm + (lane & 15)) * 400 + ((lane >> 4) * 16);
    const uint32_t ap_off = sb + A_P3 + (wm + (lane & 15)) * 400 + ((lane >> 4) * 16);
    uint32_t bk_off[2], bv_off[2];
#pragma unroll
    for (int pi = 0; pi < 2; pi++) {
        int row = wn + pi * 16 + (lane & 7) + ((lane >> 4) << 3);
        bk_off[pi] = sb + A_K3 + row * 400 + (((lane >> 3) & 1) * 16);
        int vrow = (lane & 7) + (((lane >> 3) & 1) << 3);
        bv_off[pi] = sb + A_V3 + vrow * 144 + (wn + pi * 16) * 2 + ((lane >> 4) * 16);
    }

    // softmax thread mapping (rows qbase+16i, cols kbase+16j)
    const int qbase = tid >> 4, kbase = tid & 15;

    float m[4], l[4];
#pragma unroll
    for (int i = 0; i < 4; i++) { m[i] = -1e30f; l[i] = 0.0f; }
    float acc[4][4];
#pragma unroll
    for (int ni = 0; ni < 4; ni++)
#pragma unroll
        for (int j = 0; j < 4; j++) acc[ni][j] = 0.0f;

    int jlo, jhi;
    if (q0 < 64) { jlo = 0; jhi = 31; }
    else {
        int lo = q0 - 256; jlo = lo > 0 ? (lo >> 6) : 0;
        int hi = (q0 + 63 + 256) >> 6; jhi = hi < 31 ? hi : 31;
    }
    const bool extra0 = (q0 >= 64) && (jlo > 0);
    const int ntiles = (jhi - jlo + 1) + (extra0 ? 1 : 0);

    __syncthreads();

    for (int t = 0; t < ntiles; t++) {
        int jt = extra0 ? (t == 0 ? 0 : (jlo + t - 1)) : (jlo + t);
        int k0 = jt * 64;

        // ---- load K (split [hi|hi|lo] over dims) and V (split rows) ----
#pragma unroll
        for (int i = 0; i < 4; i++) {
            int idx = tid + i * 256;
            int r = idx >> 4, c4 = (idx & 15) << 2;
            float4 kv = *(const float4*)(qkv + (size_t)(k0 + r) * QKVW + 1024 + qcol + c4);
            __nv_bfloat16 h0, l0, h1, l1, h2, l2, h3, l3;
            split2(kv.x, h0, l0); split2(kv.y, h1, l1);
            split2(kv.z, h2, l2); split2(kv.w, h3, l3);
            char* row = smem + A_K3 + r * 400 + 2 * c4;
            *(__nv_bfloat162*)(row)       = __nv_bfloat162(h0, h1);
            *(__nv_bfloat162*)(row + 4)   = __nv_bfloat162(h2, h3);
            *(__nv_bfloat162*)(row + 128) = __nv_bfloat162(h0, h1);
            *(__nv_bfloat162*)(row + 132) = __nv_bfloat162(h2, h3);
            *(__nv_bfloat162*)(row + 256) = __nv_bfloat162(l0, l1);
            *(__nv_bfloat162*)(row + 260) = __nv_bfloat162(l2, l3);
        }
#pragma unroll
        for (int i = 0; i < 4; i++) {
            int idx = tid + i * 256;
            int r = idx >> 4, c4 = (idx & 15) << 2;
            float4 vv = *(const float4*)(qkv + (size_t)(k0 + r) * QKVW + 2048 + qcol + c4);
            __nv_bfloat16 h0, l0, h1, l1, h2, l2, h3, l3;
            split2(vv.x, h0, l0); split2(vv.y, h1, l1);
            split2(vv.z, h2, l2); split2(vv.w, h3, l3);
            char* r0 = smem + A_V3 + r * 144 + 2 * c4;
            *(__nv_bfloat162*)(r0)            = __nv_bfloat162(h0, h1);
            *(__nv_bfloat162*)(r0 + 4)        = __nv_bfloat162(h2, h3);
            *(__nv_bfloat162*)(r0 + 64 * 144) = __nv_bfloat162(h0, h1);
            *(__nv_bfloat162*)(r0 + 64 * 144 + 4) = __nv_bfloat162(h2, h3);
            *(__nv_bfloat162*)(r0 + 128 * 144) = __nv_bfloat162(l0, l1);
            *(__nv_bfloat162*)(r0 + 128 * 144 + 4) = __nv_bfloat162(l2, l3);
        }
        __syncthreads();

        // ---- S = Q' K'^T via mma (m16 x n32 per warp, k=192) ----
        float cq[4][4];
#pragma unroll
        for (int ni = 0; ni < 4; ni++)
#pragma unroll
            for (int j = 0; j < 4; j++) cq[ni][j] = 0.0f;
#pragma unroll
        for (int ks = 0; ks < 12; ks++) {
            uint32_t a[4];
            ldsm4(a, aq_off + ks * 32);
#pragma unroll
            for (int pi = 0; pi < 2; pi++) {
                uint32_t b[4];
                ldsm4(b, bk_off[pi] + ks * 32);
                mma16816(cq[2 * pi],     a, b[0], b[1]);
                mma16816(cq[2 * pi + 1], a, b[2], b[3]);
            }
        }
        // write scores to Ps
#pragma unroll
        for (int ni = 0; ni < 4; ni++) {
            int col = wn + ni * 8 + ecol;
            float2 s0; s0.x = cq[ni][0]; s0.y = cq[ni][1];
            float2 s1; s1.x = cq[ni][2]; s1.y = cq[ni][3];
            *(float2*)(Ps + (wm + erow) * 68 + col)     = s0;
            *(float2*)(Ps + (wm + erow + 8) * 68 + col) = s1;
        }
        __syncthreads();

        // ---- mask + online softmax (rows qbase+16i, 16 lanes per row) ----
        const bool tileAll = (q0 < 64) || (k0 < 64);
#pragma unroll
        for (int i = 0; i < 4; i++) {
            int qr = qbase + 16 * i;
            int gi = q0 + qr;
            float sreg[4];
#pragma unroll
            for (int j = 0; j < 4; j++) {
                sreg[j] = Ps[qr * 68 + kbase + 16 * j];
                if (!tileAll) {
                    int gj = k0 + kbase + 16 * j;
                    int diff = gi - gj; if (diff < 0) diff = -diff;
                    if (diff > 256) sreg[j] = -1e30f;
                }
            }
            float mx = fmaxf(fmaxf(sreg[0], sreg[1]), fmaxf(sreg[2], sreg[3]));
#pragma unroll
            for (int off = 8; off > 0; off >>= 1)
                mx = fmaxf(mx, __shfl_xor_sync(0xffffffffu, mx, off, 16));
            float mnew = fmaxf(m[i], mx);
            float corr = __expf(m[i] - mnew);
            float psum = 0.0f;
#pragma unroll
            for (int j = 0; j < 4; j++) {
                float p = __expf(sreg[j] - mnew);
                sreg[j] = p;
                psum += p;
            }
#pragma unroll
            for (int off = 8; off > 0; off >>= 1)
                psum += __shfl_xor_sync(0xffffffffu, psum, off, 16);
            l[i] = l[i] * corr + psum;
            m[i] = mnew;
            // split P into P3 [hi | lo | hi]
            char* prow = smem + A_P3 + qr * 400;
#pragma unroll
            for (int j = 0; j < 4; j++) {
                int col = kbase + 16 * j;
                __nv_bfloat16 ph, pl;
                split2(sreg[j], ph, pl);
                *(__nv_bfloat16*)(prow + 2 * col)       = ph;
                *(__nv_bfloat16*)(prow + 128 + 2 * col) = pl;
                *(__nv_bfloat16*)(prow + 256 + 2 * col) = ph;
            }
            if (kbase == 0) corr_s[qr] = corr;
        }
        __syncthreads();

        // ---- ctx: P3 @ V3 via mma (m16 x n32dims per warp, k=192 keys) ----
        float cv[4][4];
#pragma unroll
        for (int ni = 0; ni < 4; ni++)
#pragma unroll
            for (int j = 0; j < 4; j++) cv[ni][j] = 0.0f;
#pragma unroll
        for (int ks = 0; ks < 12; ks++) {
            uint32_t a[4];
            ldsm4(a, ap_off + ks * 32);
#pragma unroll
            for (int pi = 0; pi < 2; pi++) {
                uint32_t b[4];
                ldsm4t(b, bv_off[pi] + ks * 16 * 144);
                mma16816(cv[2 * pi],     a, b[0], b[1]);
                mma16816(cv[2 * pi + 1], a, b[2], b[3]);
            }
        }
        float c0 = corr_s[wm + erow], c1 = corr_s[wm + erow + 8];
#pragma unroll
        for (int ni = 0; ni < 4; ni++) {
            acc[ni][0] = acc[ni][0] * c0 + cv[ni][0];
            acc[ni][1] = acc[ni][1] * c0 + cv[ni][1];
            acc[ni][2] = acc[ni][2] * c1 + cv[ni][2];
            acc[ni][3] = acc[ni][3] * c1 + cv[ni][3];
        }
        __syncthreads();
    }

    // publish l
    if (kbase == 0) {
#pragma unroll
        for (int i = 0; i < 4; i++) lrow[qbase + 16 * i] = l[i];
    }
    __syncthreads();

    float inv0 = 1.0f / lrow[wm + erow];
    float inv1 = 1.0f / lrow[wm + erow + 8];
    int row0 = q0 + wm + erow, row1 = row0 + 8;
#pragma unroll
    for (int ni = 0; ni < 4; ni++) {
        int col = wn + ni * 8 + ecol;
        float v0 = acc[ni][0] * inv0, v1 = acc[ni][1] * inv0;
        float v2 = acc[ni][2] * inv1, v3 = acc[ni][3] * inv1;
        __nv_bfloat16 h0, l0h, h1, l1h, h2, l2h, h3, l3h;
        split2(v0, h0, l0h); split2(v1, h1, l1h);
        split2(v2, h2, l2h); split2(v3, h3, l3h);
        __nv_bfloat16* o0 = a3 + (size_t)row0 * 3 * D + qcol + col;
        __nv_bfloat16* o1 = a3 + (size_t)row1 * 3 * D + qcol + col;
        *(__nv_bfloat162*)(o0)         = __nv_bfloat162(h0, h1);
        *(__nv_bfloat162*)(o0 + D)     = __nv_bfloat162(l0h, l1h);
        *(__nv_bfloat162*)(o0 + 2 * D) = __nv_bfloat162(h0, h1);
        *(__nv_bfloat162*)(o1)         = __nv_bfloat162(h2, h3);
        *(__nv_bfloat162*)(o1 + D)     = __nv_bfloat162(l2h, l3h);
        *(__nv_bfloat162*)(o1 + 2 * D) = __nv_bfloat162(h2, h3);
    }
}

// ---------------- launch ----------------
extern "C" void kernel_launch(void* const* d_in, const int* in_sizes, int n_in,
                              void* d_out, int out_size) {
    const int*   ids    = (const int*)d_in[0];
    const float* emb    = (const float*)d_in[2];
    const float* wq     = (const float*)d_in[3];
    const float* wk     = (const float*)d_in[4];
    const float* wv     = (const float*)d_in[5];
    const float* wo     = (const float*)d_in[6];
    const float* ln1_s  = (const float*)d_in[7];
    const float* ln1_b  = (const float*)d_in[8];
    const float* ln2_s  = (const float*)d_in[9];
    const float* ln2_b  = (const float*)d_in[10];
    const float* w1     = (const float*)d_in[11];
    const float* b1     = (const float*)d_in[12];
    const float* w2     = (const float*)d_in[13];
    const float* b2     = (const float*)d_in[14];
    const float* lnf_s  = (const float*)d_in[15];
    const float* lnf_b  = (const float*)d_in[16];
    float* out = (float*)d_out;

    void *px, *pqkv, *pa3, *py3, *pwT;
    cudaGetSymbolAddress(&px, g_x);
    cudaGetSymbolAddress(&pqkv, g_qkv);
    cudaGetSymbolAddress(&pa3, g_a3);
    cudaGetSymbolAddress(&py3, g_y3);
    cudaGetSymbolAddress(&pwT, g_wT);
    float* x = (float*)px;
    float* qkv = (float*)pqkv;
    __nv_bfloat16* a3 = (__nv_bfloat16*)pa3;
    __nv_bfloat16* y3 = (__nv_bfloat16*)py3;
    __nv_bfloat16* wT = (__nv_bfloat16*)pwT;

    cudaFuncSetAttribute(attn_kernel, cudaFuncAttributeMaxDynamicSharedMemorySize, ATTN_SMEM_BYTES);
    const int GS128 = 3 * 256 * 144;   // 110592
    const int GS64  = 3 * 192 * 144;   // 82944
    cudaFuncSetAttribute(gemm_tpl<128>, cudaFuncAttributeMaxDynamicSharedMemorySize, GS128);
    cudaFuncSetAttribute(gemm_tpl<64>,  cudaFuncAttributeMaxDynamicSharedMemorySize, GS64);

    dim3 cw_dd(D / 32, D / 32);
    dim3 cw_dm(D / 32, MM / 32);
    dim3 cw_md(MM / 32, D / 32);

    embed_kernel<<<S, 256>>>(ids, emb, x);
    convW3_kernel<<<dim3(32, 32, 3), 256>>>(wq, wk, wv, wT + WT_QKV);
    ln_split_kernel<<<S, 256>>>(x, ln1_s, ln1_b, a3);

    for (int l = 0; l < LAY; l++) {
        size_t woff = (size_t)l * D * D;
        if (l > 0) {
            convW3_kernel<<<dim3(32, 32, 3), 256>>>(wq + woff, wk + woff, wv + woff, wT + WT_QKV);
            ln_split_kernel<<<S, 256>>>(x, ln1_s + l * D, ln1_b + l * D, a3);
        }
        gemm_tpl<128><<<dim3(QKVW / 128, S / 128), 256, GS128>>>(
            a3, wT + WT_QKV, qkv, nullptr, 0, QKVW, 3 * D, nullptr, nullptr, 0);
        attn_kernel<<<dim3(S / 64, H), 256, ATTN_SMEM_BYTES>>>(qkv, a3);
        convW_kernel<<<cw_dd, 256>>>(wo + woff, wT + WT_WO, D, D);
        gemm_tpl<64><<<dim3(D / 128, S / 64), 256, GS64>>>(
            a3, wT + WT_WO, x, nullptr, 0, D, 3 * D, nullptr, x, 0);
        ln_split_kernel<<<S, 256>>>(x, ln2_s + l * D, ln2_b + l * D, a3);
        convW_kernel<<<cw_dm, 256>>>(w1 + (size_t)l * D * MM, wT + WT_W1, D, MM);
        gemm_tpl<128><<<dim3(MM / 128, S / 128), 256, GS128>>>(
            a3, wT + WT_W1, nullptr, y3, MM, MM, 3 * D, b1 + (size_t)l * MM, nullptr, 1);
        convW_kernel<<<cw_md, 256>>>(w2 + (size_t)l * MM * D, wT + WT_W2, MM, D);
        gemm_tpl<64><<<dim3(D / 128, S / 64), 256, GS64>>>(
            y3, wT + WT_W2, x, nullptr, 0, D, 3 * MM, b2 + (size_t)l * D, x, 0);
    }
    ln_kernel<<<S, 256>>>(x, lnf_s, lnf_b, out);
}

// round 12
// speedup vs baseline: 2.4764x; 1.4106x over previous
#include <cuda_runtime.h>
#include <cuda_fp16.h>
#include <math.h>
#include <stdint.h>

#define S   2048
#define D   1024
#define H   16
#define HD  64
#define MM  4096
#define LAY 4
#define QKVW 3072

// ---------------- scratch (device globals) ----------------
__device__ float g_x[S * D];
__device__ float g_qkv[S * QKVW];
__device__ __half g_a3[S * 2 * D];
__device__ __half g_y3[S * 2 * MM];
__device__ __half g_wT[26 * 1024 * 1024];
#define WT_QKV 0
#define WT_WO  6291456u
#define WT_W1  8388608u
#define WT_W2  16777216u

// ================= PTX helpers =================
__device__ __forceinline__ uint32_t smem_u32(const void* p) {
    uint32_t a;
    asm("{ .reg .u64 t; cvta.to.shared.u64 t, %1; cvt.u32.u64 %0, t; }" : "=r"(a) : "l"(p));
    return a;
}
__device__ __forceinline__ void cp16(uint32_t saddr, const void* g) {
    asm volatile("cp.async.cg.shared.global [%0], [%1], 16;" :: "r"(saddr), "l"(g));
}
#define CP_COMMIT() asm volatile("cp.async.commit_group;" ::: "memory")
#define CP_WAIT1()  asm volatile("cp.async.wait_group 1;" ::: "memory")

__device__ __forceinline__ void ldsm4(uint32_t* r, uint32_t a) {
    asm volatile("ldmatrix.sync.aligned.m8n8.x4.shared.b16 {%0,%1,%2,%3}, [%4];"
                 : "=r"(r[0]), "=r"(r[1]), "=r"(r[2]), "=r"(r[3]) : "r"(a));
}
__device__ __forceinline__ void ldsm4t(uint32_t* r, uint32_t a) {
    asm volatile("ldmatrix.sync.aligned.m8n8.x4.trans.shared.b16 {%0,%1,%2,%3}, [%4];"
                 : "=r"(r[0]), "=r"(r[1]), "=r"(r[2]), "=r"(r[3]) : "r"(a));
}
__device__ __forceinline__ void mma16816(float* c, const uint32_t* a, uint32_t b0, uint32_t b1) {
    asm volatile("mma.sync.aligned.m16n8k16.row.col.f32.f16.f16.f32 "
                 "{%0,%1,%2,%3}, {%4,%5,%6,%7}, {%8,%9}, {%0,%1,%2,%3};"
                 : "+f"(c[0]), "+f"(c[1]), "+f"(c[2]), "+f"(c[3])
                 : "r"(a[0]), "r"(a[1]), "r"(a[2]), "r"(a[3]), "r"(b0), "r"(b1));
}
__device__ __forceinline__ void hsplit(float a, __half& hi, __half& lo) {
    hi = __float2half_rn(a);
    lo = __float2half_rn(a - __half2float(hi));
}

// ---------------- embedding + sinusoidal positional encoding ----------------
__global__ __launch_bounds__(256) void embed_kernel(const int* __restrict__ ids,
                                                    const float* __restrict__ emb,
                                                    float* __restrict__ x) {
    int s = blockIdx.x;
    int id = ids[s];
    const double c = -9.210340371976184 / 1024.0;
    for (int d = threadIdx.x; d < D; d += 256) {
        int p2 = d & ~1;
        double freq = exp((double)p2 * c);
        double phase = (double)s * freq;
        double pe = (d & 1) ? cos(phase) : sin(phase);
        x[s * D + d] = emb[id * D + d] + (float)pe;
    }
}

// ---------------- LayerNorm -> fp32 out (final) ----------------
__global__ __launch_bounds__(256) void ln_kernel(const float* __restrict__ x,
                                                 const float* __restrict__ sc,
                                                 const float* __restrict__ bi,
                                                 float* __restrict__ out) {
    __shared__ float ssum[256], ssq[256];
    int s = blockIdx.x, tid = threadIdx.x;
    float4 v = ((const float4*)(x + s * D))[tid];
    ssum[tid] = v.x + v.y + v.z + v.w;
    ssq[tid]  = v.x * v.x + v.y * v.y + v.z * v.z + v.w * v.w;
    __syncthreads();
#pragma unroll
    for (int off = 128; off > 0; off >>= 1) {
        if (tid < off) { ssum[tid] += ssum[tid + off]; ssq[tid] += ssq[tid + off]; }
        __syncthreads();
    }
    float mu  = ssum[0] * (1.0f / 1024.0f);
    float var = ssq[0] * (1.0f / 1024.0f) - mu * mu;
    float rs  = rsqrtf(var + 1e-6f);
    float4 scv = ((const float4*)sc)[tid];
    float4 biv = ((const float4*)bi)[tid];
    float4 o;
    o.x = (v.x - mu) * rs * scv.x + biv.x;
    o.y = (v.y - mu) * rs * scv.y + biv.y;
    o.z = (v.z - mu) * rs * scv.z + biv.z;
    o.w = (v.w - mu) * rs * scv.w + biv.w;
    ((float4*)(out + s * D))[tid] = o;
}

// ---------------- LayerNorm -> split fp16 [hi|lo] into a3 ----------------
__global__ __launch_bounds__(256) void ln_split_kernel(const float* __restrict__ x,
                                                       const float* __restrict__ sc,
                                                       const float* __restrict__ bi,
                                                       __half* __restrict__ a3) {
    __shared__ float ssum[256], ssq[256];
    int s = blockIdx.x, tid = threadIdx.x;
    float4 v = ((const float4*)(x + s * D))[tid];
    ssum[tid] = v.x + v.y + v.z + v.w;
    ssq[tid]  = v.x * v.x + v.y * v.y + v.z * v.z + v.w * v.w;
    __syncthreads();
#pragma unroll
    for (int off = 128; off > 0; off >>= 1) {
        if (tid < off) { ssum[tid] += ssum[tid + off]; ssq[tid] += ssq[tid + off]; }
        __syncthreads();
    }
    float mu  = ssum[0] * (1.0f / 1024.0f);
    float var = ssq[0] * (1.0f / 1024.0f) - mu * mu;
    float rs  = rsqrtf(var + 1e-6f);
    float4 scv = ((const float4*)sc)[tid];
    float4 biv = ((const float4*)bi)[tid];
    float o[4];
    o[0] = (v.x - mu) * rs * scv.x + biv.x;
    o[1] = (v.y - mu) * rs * scv.y + biv.y;
    o[2] = (v.z - mu) * rs * scv.z + biv.z;
    o[3] = (v.w - mu) * rs * scv.w + biv.w;
    __half hi[4], lo[4];
#pragma unroll
    for (int j = 0; j < 4; j++) hsplit(o[j], hi[j], lo[j]);
    __half* orow = a3 + (size_t)s * 2 * D + tid * 4;
    *(__half2*)(orow)         = __halves2half2(hi[0], hi[1]);
    *(__half2*)(orow + 2)     = __halves2half2(hi[2], hi[3]);
    *(__half2*)(orow + D)     = __halves2half2(lo[0], lo[1]);
    *(__half2*)(orow + D + 2) = __halves2half2(lo[2], lo[3]);
}

// -------- weights: W[K,N] fp32 -> Wt[N,2K] fp16 = [hi|hi] (transposed) ----
__global__ __launch_bounds__(256) void convW_kernel(const float* __restrict__ W,
                                                    __half* __restrict__ Wt,
                                                    int K, int N) {
    __shared__ float t[32][33];
    int k0 = blockIdx.x * 32, n0 = blockIdx.y * 32;
    int tx = threadIdx.x & 31, ty = threadIdx.x >> 5;
#pragma unroll
    for (int i = 0; i < 4; i++)
        t[ty + i * 8][tx] = W[(size_t)(k0 + ty + i * 8) * N + n0 + tx];
    __syncthreads();
#pragma unroll
    for (int i = 0; i < 4; i++) {
        int n = n0 + ty + i * 8, k = k0 + tx;
        __half hi = __float2half_rn(t[tx][ty + i * 8]);
        __half* orow = Wt + (size_t)n * 2 * K;
        orow[k] = hi; orow[K + k] = hi;
    }
}
__global__ __launch_bounds__(256) void convW3_kernel(const float* __restrict__ wq,
                                                     const float* __restrict__ wk,
                                                     const float* __restrict__ wv,
                                                     __half* __restrict__ Wt) {
    __shared__ float t[32][33];
    const float* W = (blockIdx.z == 0) ? wq : (blockIdx.z == 1) ? wk : wv;
    const int K = D, N = D;
    int k0 = blockIdx.x * 32, n0 = blockIdx.y * 32;
    int tx = threadIdx.x & 31, ty = threadIdx.x >> 5;
#pragma unroll
    for (int i = 0; i < 4; i++)
        t[ty + i * 8][tx] = W[(size_t)(k0 + ty + i * 8) * N + n0 + tx];
    __syncthreads();
#pragma unroll
    for (int i = 0; i < 4; i++) {
        int n = n0 + ty + i * 8 + blockIdx.z * 1024, k = k0 + tx;
        __half hi = __float2half_rn(t[tx][ty + i * 8]);
        __half* orow = Wt + (size_t)n * 2 * K;
        orow[k] = hi; orow[K + k] = hi;
    }
}

// ---- HMMA fp16 GEMM: MTx128 CTA, 256 threads, 2 CTAs/SM, BK=64, 3 stages ----
template<int MT>
__global__ __launch_bounds__(256, 2) void gemm_tpl(const __half* __restrict__ A,
                                                   const __half* __restrict__ Bt,
                                                   float* __restrict__ C,
                                                   __half* __restrict__ Cs, int Kout,
                                                   int N, int K2,
                                                   const float* __restrict__ bias,
                                                   const float* residual, int relu) {
    extern __shared__ char sm[];
    constexpr int WTM = MT / 2;
    constexpr int FM = WTM / 16;
    constexpr int ROWB = 144;
    constexpr int STAGE = (MT + 128) * ROWB;
    const int tid = threadIdx.x, lane = tid & 31, wid = tid >> 5;
    const int bm = blockIdx.y * MT, bn = blockIdx.x * 128;
    const int wm = (wid >> 2) * WTM, wn = (wid & 3) * 32;
    const size_t rs = (size_t)K2 * 2;
    const char* Ag = (const char*)A + (size_t)bm * rs;
    const char* Bg = (const char*)Bt + (size_t)bn * rs;
    const uint32_t smb = smem_u32(sm);

    uint32_t a_off[FM], b_off[2];
#pragma unroll
    for (int f = 0; f < FM; f++)
        a_off[f] = (uint32_t)((wm + f * 16 + (lane & 15)) * ROWB + ((lane >> 4) * 16));
#pragma unroll
    for (int pi = 0; pi < 2; pi++) {
        int row = wn + pi * 16 + (lane & 7) + ((lane >> 4) << 3);
        b_off[pi] = (uint32_t)(row * ROWB + (((lane >> 3) & 1) * 16));
    }

    float acc[FM][4][4];
#pragma unroll
    for (int f = 0; f < FM; f++)
#pragma unroll
        for (int ni = 0; ni < 4; ni++)
#pragma unroll
            for (int j = 0; j < 4; j++) acc[f][ni][j] = 0.0f;

    auto load_stage = [&](int buf, int kt) {
        uint32_t sa = smb + buf * STAGE, sb2 = sa + MT * ROWB;
        size_t gk = (size_t)kt * 128;
#pragma unroll
        for (int i = 0; i < MT / 32; i++) {
            int c = tid + i * 256, r = c >> 3, cb = (c & 7) << 4;
            cp16(sa + r * ROWB + cb, Ag + (size_t)r * rs + gk + cb);
        }
#pragma unroll
        for (int i = 0; i < 4; i++) {
            int c = tid + i * 256, r = c >> 3, cb = (c & 7) << 4;
            cp16(sb2 + r * ROWB + cb, Bg + (size_t)r * rs + gk + cb);
        }
    };

    const int KT = K2 >> 6;
    load_stage(0, 0); CP_COMMIT();
    load_stage(1, 1); CP_COMMIT();

    int buf = 0;
    for (int kt = 0; kt < KT; kt++) {
        CP_WAIT1();
        __syncthreads();
        if (kt + 2 < KT) {
            int nbuf = buf + 2; if (nbuf >= 3) nbuf -= 3;
            load_stage(nbuf, kt + 2);
        }
        CP_COMMIT();
        const uint32_t ab = smb + buf * STAGE, bb = ab + MT * ROWB;
#pragma unroll
        for (int ks = 0; ks < 4; ks++) {
            uint32_t a[FM][4];
#pragma unroll
            for (int f = 0; f < FM; f++) ldsm4(a[f], ab + a_off[f] + ks * 32);
#pragma unroll
            for (int pi = 0; pi < 2; pi++) {
                uint32_t b[4];
                ldsm4(b, bb + b_off[pi] + ks * 32);
#pragma unroll
                for (int f = 0; f < FM; f++) {
                    mma16816(acc[f][2 * pi],     a[f], b[0], b[1]);
                    mma16816(acc[f][2 * pi + 1], a[f], b[2], b[3]);
                }
            }
        }
        buf = (buf == 2) ? 0 : buf + 1;
    }

    const int erow = lane >> 2, ecol = (lane & 3) * 2;
#pragma unroll
    for (int f = 0; f < FM; f++) {
#pragma unroll
        for (int ni = 0; ni < 4; ni++) {
            float* c = acc[f][ni];
            int col = bn + wn + ni * 8 + ecol;
#pragma unroll
            for (int half = 0; half < 2; half++) {
                int row = bm + wm + f * 16 + erow + half * 8;
                float vx = c[half * 2 + 0];
                float vy = c[half * 2 + 1];
                if (bias)  { vx += bias[col]; vy += bias[col + 1]; }
                if (relu)  { vx = fmaxf(vx, 0.f); vy = fmaxf(vy, 0.f); }
                if (Cs) {
                    __half hx, lx, hy, ly;
                    hsplit(vx, hx, lx); hsplit(vy, hy, ly);
                    __half* orow = Cs + (size_t)row * 2 * Kout;
                    *(__half2*)(orow + col)        = __halves2half2(hx, hy);
                    *(__half2*)(orow + Kout + col) = __halves2half2(lx, ly);
                } else {
                    if (residual) {
                        const float2 rv = *(const float2*)(residual + (size_t)row * N + col);
                        vx += rv.x; vy += rv.y;
                    }
                    float2 o; o.x = vx; o.y = vy;
                    *(float2*)(C + (size_t)row * N + col) = o;
                }
            }
        }
    }
}

// ------------- tensor-core flash attention (band + global), fp16 2-term -----
// Q/K/P rows: 272B stride ([128B hi | 128B second] + 16B pad)
// V: 128 rows x 144B (rows 0-63 hi, rows 64-127 hi duplicate)
#define A_Q2   0u
#define A_K2   17408u
#define A_P2   34816u
#define A_V2   52224u
#define A_PS   70656u
#define A_CORR 88064u
#define A_LROW 88320u
#define ATTN_SMEM_BYTES 88576

__global__ __launch_bounds__(256) void attn_kernel(const float* __restrict__ qkv,
                                                   __half* __restrict__ a3) {
    extern __shared__ char smem[];
    const uint32_t sb = smem_u32(smem);
    float* Ps   = (float*)(smem + A_PS);
    float* corr_s = (float*)(smem + A_CORR);
    float* lrow = (float*)(smem + A_LROW);

    const int h  = blockIdx.y;
    const int q0 = blockIdx.x * 64;
    const int tid = threadIdx.x, lane = tid & 31, wid = tid >> 5;
    const int qcol = h * HD;

    // ---- build Q split tile [hi | lo] (scaled by 1/8) ----
#pragma unroll
    for (int i = 0; i < 4; i++) {
        int idx = tid + i * 256;
        int r = idx >> 4, c4 = (idx & 15) << 2;
        float4 qv = *(const float4*)(qkv + (size_t)(q0 + r) * QKVW + qcol + c4);
        qv.x *= 0.125f; qv.y *= 0.125f; qv.z *= 0.125f; qv.w *= 0.125f;
        __half h0, l0, h1, l1, h2, l2, h3, l3;
        hsplit(qv.x, h0, l0); hsplit(qv.y, h1, l1);
        hsplit(qv.z, h2, l2); hsplit(qv.w, h3, l3);
        char* row = smem + A_Q2 + r * 272 + 2 * c4;
        *(__half2*)(row)       = __halves2half2(h0, h1);
        *(__half2*)(row + 4)   = __halves2half2(h2, h3);
        *(__half2*)(row + 128) = __halves2half2(l0, l1);
        *(__half2*)(row + 132) = __halves2half2(l2, l3);
    }

    // warp layout: 4 m-warps x 2 n-warps; warp tile 16 x 32
    const int wm = (wid >> 1) * 16;
    const int wn = (wid & 1) * 32;
    const int erow = lane >> 2, ecol = (lane & 3) * 2;

    const uint32_t aq_off = sb + A_Q2 + (wm + (lane & 15)) * 272 + ((lane >> 4) * 16);
    const uint32_t ap_off = sb + A_P2 + (wm + (lane & 15)) * 272 + ((lane >> 4) * 16);
    uint32_t bk_off[2], bv_off[2];
#pragma unroll
    for (int pi = 0; pi < 2; pi++) {
        int row = wn + pi * 16 + (lane & 7) + ((lane >> 4) << 3);
        bk_off[pi] = sb + A_K2 + row * 272 + (((lane >> 3) & 1) * 16);
        int vrow = (lane & 7) + (((lane >> 3) & 1) << 3);
        bv_off[pi] = sb + A_V2 + vrow * 144 + (wn + pi * 16) * 2 + ((lane >> 4) * 16);
    }

    const int qbase = tid >> 4, kbase = tid & 15;

    float m[4], l[4];
#pragma unroll
    for (int i = 0; i < 4; i++) { m[i] = -1e30f; l[i] = 0.0f; }
    float acc[4][4];
#pragma unroll
    for (int ni = 0; ni < 4; ni++)
#pragma unroll
        for (int j = 0; j < 4; j++) acc[ni][j] = 0.0f;

    int jlo, jhi;
    if (q0 < 64) { jlo = 0; jhi = 31; }
    else {
        int lo = q0 - 256; jlo = lo > 0 ? (lo >> 6) : 0;
        int hi = (q0 + 63 + 256) >> 6; jhi = hi < 31 ? hi : 31;
    }
    const bool extra0 = (q0 >= 64) && (jlo > 0);
    const int ntiles = (jhi - jlo + 1) + (extra0 ? 1 : 0);

    __syncthreads();

    for (int t = 0; t < ntiles; t++) {
        int jt = extra0 ? (t == 0 ? 0 : (jlo + t - 1)) : (jlo + t);
        int k0 = jt * 64;

        // ---- K tile [hi | hi], V tile rows duplicated hi ----
#pragma unroll
        for (int i = 0; i < 4; i++) {
            int idx = tid + i * 256;
            int r = idx >> 4, c4 = (idx & 15) << 2;
            float4 kv = *(const float4*)(qkv + (size_t)(k0 + r) * QKVW + 1024 + qcol + c4);
            __half h0 = __float2half_rn(kv.x), h1 = __float2half_rn(kv.y);
            __half h2 = __float2half_rn(kv.z), h3 = __float2half_rn(kv.w);
            char* row = smem + A_K2 + r * 272 + 2 * c4;
            *(__half2*)(row)       = __halves2half2(h0, h1);
            *(__half2*)(row + 4)   = __halves2half2(h2, h3);
            *(__half2*)(row + 128) = __halves2half2(h0, h1);
            *(__half2*)(row + 132) = __halves2half2(h2, h3);
        }
#pragma unroll
        for (int i = 0; i < 4; i++) {
            int idx = tid + i * 256;
            int r = idx >> 4, c4 = (idx & 15) << 2;
            float4 vv = *(const float4*)(qkv + (size_t)(k0 + r) * QKVW + 2048 + qcol + c4);
            __half h0 = __float2half_rn(vv.x), h1 = __float2half_rn(vv.y);
            __half h2 = __float2half_rn(vv.z), h3 = __float2half_rn(vv.w);
            char* r0 = smem + A_V2 + r * 144 + 2 * c4;
            *(__half2*)(r0)                = __halves2half2(h0, h1);
            *(__half2*)(r0 + 4)            = __halves2half2(h2, h3);
            *(__half2*)(r0 + 64 * 144)     = __halves2half2(h0, h1);
            *(__half2*)(r0 + 64 * 144 + 4) = __halves2half2(h2, h3);
        }
        __syncthreads();

        // ---- S = Q' K'^T (k = 128) ----
        float cq[4][4];
#pragma unroll
        for (int ni = 0; ni < 4; ni++)
#pragma unroll
            for (int j = 0; j < 4; j++) cq[ni][j] = 0.0f;
#pragma unroll
        for (int ks = 0; ks < 8; ks++) {
            uint32_t a[4];
            ldsm4(a, aq_off + ks * 32);
#pragma unroll
            for (int pi = 0; pi < 2; pi++) {
                uint32_t b[4];
                ldsm4(b, bk_off[pi] + ks * 32);
                mma16816(cq[2 * pi],     a, b[0], b[1]);
                mma16816(cq[2 * pi + 1], a, b[2], b[3]);
            }
        }
#pragma unroll
        for (int ni = 0; ni < 4; ni++) {
            int col = wn + ni * 8 + ecol;
            float2 s0; s0.x = cq[ni][0]; s0.y = cq[ni][1];
            float2 s1; s1.x = cq[ni][2]; s1.y = cq[ni][3];
            *(float2*)(Ps + (wm + erow) * 68 + col)     = s0;
            *(float2*)(Ps + (wm + erow + 8) * 68 + col) = s1;
        }
        __syncthreads();

        // ---- mask + online softmax ----
        const bool tileAll = (q0 < 64) || (k0 < 64);
#pragma unroll
        for (int i = 0; i < 4; i++) {
            int qr = qbase + 16 * i;
            int gi = q0 + qr;
            float sreg[4];
#pragma unroll
            for (int j = 0; j < 4; j++) {
                sreg[j] = Ps[qr * 68 + kbase + 16 * j];
                if (!tileAll) {
                    int gj = k0 + kbase + 16 * j;
                    int diff = gi - gj; if (diff < 0) diff = -diff;
                    if (diff > 256) sreg[j] = -1e30f;
                }
            }
            float mx = fmaxf(fmaxf(sreg[0], sreg[1]), fmaxf(sreg[2], sreg[3]));
#pragma unroll
            for (int off = 8; off > 0; off >>= 1)
                mx = fmaxf(mx, __shfl_xor_sync(0xffffffffu, mx, off, 16));
            float mnew = fmaxf(m[i], mx);
            float corr = __expf(m[i] - mnew);
            float psum = 0.0f;
#pragma unroll
            for (int j = 0; j < 4; j++) {
                float p = __expf(sreg[j] - mnew);
                sreg[j] = p;
                psum += p;
            }
#pragma unroll
            for (int off = 8; off > 0; off >>= 1)
                psum += __shfl_xor_sync(0xffffffffu, psum, off, 16);
            l[i] = l[i] * corr + psum;
            m[i] = mnew;
            char* prow = smem + A_P2 + qr * 272;
#pragma unroll
            for (int j = 0; j < 4; j++) {
                int col = kbase + 16 * j;
                __half ph, pl;
                hsplit(sreg[j], ph, pl);
                *(__half*)(prow + 2 * col)       = ph;
                *(__half*)(prow + 128 + 2 * col) = pl;
            }
            if (kbase == 0) corr_s[qr] = corr;
        }
        __syncthreads();

        // ---- ctx: P2 @ V2 (k = 128 rows) ----
        float cv[4][4];
#pragma unroll
        for (int ni = 0; ni < 4; ni++)
#pragma unroll
            for (int j = 0; j < 4; j++) cv[ni][j] = 0.0f;
#pragma unroll
        for (int ks = 0; ks < 8; ks++) {
            uint32_t a[4];
            ldsm4(a, ap_off + ks * 32);
#pragma unroll
            for (int pi = 0; pi < 2; pi++) {
                uint32_t b[4];
                ldsm4t(b, bv_off[pi] + ks * 16 * 144);
                mma16816(cv[2 * pi],     a, b[0], b[1]);
                mma16816(cv[2 * pi + 1], a, b[2], b[3]);
            }
        }
        float c0 = corr_s[wm + erow], c1 = corr_s[wm + erow + 8];
#pragma unroll
        for (int ni = 0; ni < 4; ni++) {
            acc[ni][0] = acc[ni][0] * c0 + cv[ni][0];
            acc[ni][1] = acc[ni][1] * c0 + cv[ni][1];
            acc[ni][2] = acc[ni][2] * c1 + cv[ni][2];
            acc[ni][3] = acc[ni][3] * c1 + cv[ni][3];
        }
        __syncthreads();
    }

    if (kbase == 0) {
#pragma unroll
        for (int i = 0; i < 4; i++) lrow[qbase + 16 * i] = l[i];
    }
    __syncthreads();

    float inv0 = 1.0f / lrow[wm + erow];
    float inv1 = 1.0f / lrow[wm + erow + 8];
    int row0 = q0 + wm + erow, row1 = row0 + 8;
#pragma unroll
    for (int ni = 0; ni < 4; ni++) {
        int col = wn + ni * 8 + ecol;
        float v0 = acc[ni][0] * inv0, v1 = acc[ni][1] * inv0;
        float v2 = acc[ni][2] * inv1, v3 = acc[ni][3] * inv1;
        __half h0, l0h, h1, l1h, h2, l2h, h3, l3h;
        hsplit(v0, h0, l0h); hsplit(v1, h1, l1h);
        hsplit(v2, h2, l2h); hsplit(v3, h3, l3h);
        __half* o0 = a3 + (size_t)row0 * 2 * D + qcol + col;
        __half* o1 = a3 + (size_t)row1 * 2 * D + qcol + col;
        *(__half2*)(o0)     = __halves2half2(h0, h1);
        *(__half2*)(o0 + D) = __halves2half2(l0h, l1h);
        *(__half2*)(o1)     = __halves2half2(h2, h3);
        *(__half2*)(o1 + D) = __halves2half2(l2h, l3h);
    }
}

// ---------------- launch ----------------
extern "C" void kernel_launch(void* const* d_in, const int* in_sizes, int n_in,
                              void* d_out, int out_size) {
    const int*   ids    = (const int*)d_in[0];
    const float* emb    = (const float*)d_in[2];
    const float* wq     = (const float*)d_in[3];
    const float* wk     = (const float*)d_in[4];
    const float* wv     = (const float*)d_in[5];
    const float* wo     = (const float*)d_in[6];
    const float* ln1_s  = (const float*)d_in[7];
    const float* ln1_b  = (const float*)d_in[8];
    const float* ln2_s  = (const float*)d_in[9];
    const float* ln2_b  = (const float*)d_in[10];
    const float* w1     = (const float*)d_in[11];
    const float* b1     = (const float*)d_in[12];
    const float* w2     = (const float*)d_in[13];
    const float* b2     = (const float*)d_in[14];
    const float* lnf_s  = (const float*)d_in[15];
    const float* lnf_b  = (const float*)d_in[16];
    float* out = (float*)d_out;

    void *px, *pqkv, *pa3, *py3, *pwT;
    cudaGetSymbolAddress(&px, g_x);
    cudaGetSymbolAddress(&pqkv, g_qkv);
    cudaGetSymbolAddress(&pa3, g_a3);
    cudaGetSymbolAddress(&py3, g_y3);
    cudaGetSymbolAddress(&pwT, g_wT);
    float* x = (float*)px;
    float* qkv = (float*)pqkv;
    __half* a3 = (__half*)pa3;
    __half* y3 = (__half*)py3;
    __half* wT = (__half*)pwT;

    cudaFuncSetAttribute(attn_kernel, cudaFuncAttributeMaxDynamicSharedMemorySize, ATTN_SMEM_BYTES);
    const int GS128 = 3 * 256 * 144;
    const int GS64  = 3 * 192 * 144;
    cudaFuncSetAttribute(gemm_tpl<128>, cudaFuncAttributeMaxDynamicSharedMemorySize, GS128);
    cudaFuncSetAttribute(gemm_tpl<64>,  cudaFuncAttributeMaxDynamicSharedMemorySize, GS64);

    dim3 cw_dd(D / 32, D / 32);
    dim3 cw_dm(D / 32, MM / 32);
    dim3 cw_md(MM / 32, D / 32);

    embed_kernel<<<S, 256>>>(ids, emb, x);
    convW3_kernel<<<dim3(32, 32, 3), 256>>>(wq, wk, wv, wT + WT_QKV);
    ln_split_kernel<<<S, 256>>>(x, ln1_s, ln1_b, a3);

    for (int l = 0; l < LAY; l++) {
        size_t woff = (size_t)l * D * D;
        if (l > 0) {
            convW3_kernel<<<dim3(32, 32, 3), 256>>>(wq + woff, wk + woff, wv + woff, wT + WT_QKV);
            ln_split_kernel<<<S, 256>>>(x, ln1_s + l * D, ln1_b + l * D, a3);
        }
        gemm_tpl<128><<<dim3(QKVW / 128, S / 128), 256, GS128>>>(
            a3, wT + WT_QKV, qkv, nullptr, 0, QKVW, 2 * D, nullptr, nullptr, 0);
        attn_kernel<<<dim3(S / 64, H), 256, ATTN_SMEM_BYTES>>>(qkv, a3);
        convW_kernel<<<cw_dd, 256>>>(wo + woff, wT + WT_WO, D, D);
        gemm_tpl<64><<<dim3(D / 128, S / 64), 256, GS64>>>(
            a3, wT + WT_WO, x, nullptr, 0, D, 2 * D, nullptr, x, 0);
        ln_split_kernel<<<S, 256>>>(x, ln2_s + l * D, ln2_b + l * D, a3);
        convW_kernel<<<cw_dm, 256>>>(w1 + (size_t)l * D * MM, wT + WT_W1, D, MM);
        gemm_tpl<128><<<dim3(MM / 128, S / 128), 256, GS128>>>(
            a3, wT + WT_W1, nullptr, y3, MM, MM, 2 * D, b1 + (size_t)l * MM, nullptr, 1);
        convW_kernel<<<cw_md, 256>>>(w2 + (size_t)l * MM * D, wT + WT_W2, MM, D);
        gemm_tpl<64><<<dim3(D / 128, S / 64), 256, GS64>>>(
            y3, wT + WT_W2, x, nullptr, 0, D, 2 * MM, b2 + (size_t)l * D, x, 0);
    }
    ln_kernel<<<S, 256>>>(x, lnf_s, lnf_b, out);
}

// round 13
// speedup vs baseline: 2.5440x; 1.0273x over previous
#include <cuda_runtime.h>
#include <cuda_fp16.h>
#include <math.h>
#include <stdint.h>

#define S   2048
#define D   1024
#define H   16
#define HD  64
#define MM  4096
#define LAY 4
#define QKVW 3072

// ---------------- scratch (device globals) ----------------
__device__ float g_x[S * D];
__device__ float g_qkv[S * QKVW];
__device__ __half g_a3[S * 2 * D];
__device__ __half g_y3[S * 2 * MM];
__device__ __half g_wT[26 * 1024 * 1024];
#define WT_QKV 0
#define WT_WO  6291456u
#define WT_W1  8388608u
#define WT_W2  16777216u

// ================= PTX helpers =================
__device__ __forceinline__ uint32_t smem_u32(const void* p) {
    uint32_t a;
    asm("{ .reg .u64 t; cvta.to.shared.u64 t, %1; cvt.u32.u64 %0, t; }" : "=r"(a) : "l"(p));
    return a;
}
__device__ __forceinline__ void cp16(uint32_t saddr, const void* g) {
    asm volatile("cp.async.cg.shared.global [%0], [%1], 16;" :: "r"(saddr), "l"(g));
}
#define CP_COMMIT() asm volatile("cp.async.commit_group;" ::: "memory")
#define CP_WAIT1()  asm volatile("cp.async.wait_group 1;" ::: "memory")

__device__ __forceinline__ void ldsm4(uint32_t* r, uint32_t a) {
    asm volatile("ldmatrix.sync.aligned.m8n8.x4.shared.b16 {%0,%1,%2,%3}, [%4];"
                 : "=r"(r[0]), "=r"(r[1]), "=r"(r[2]), "=r"(r[3]) : "r"(a));
}
__device__ __forceinline__ void ldsm4t(uint32_t* r, uint32_t a) {
    asm volatile("ldmatrix.sync.aligned.m8n8.x4.trans.shared.b16 {%0,%1,%2,%3}, [%4];"
                 : "=r"(r[0]), "=r"(r[1]), "=r"(r[2]), "=r"(r[3]) : "r"(a));
}
__device__ __forceinline__ void mma16816(float* c, const uint32_t* a, uint32_t b0, uint32_t b1) {
    asm volatile("mma.sync.aligned.m16n8k16.row.col.f32.f16.f16.f32 "
                 "{%0,%1,%2,%3}, {%4,%5,%6,%7}, {%8,%9}, {%0,%1,%2,%3};"
                 : "+f"(c[0]), "+f"(c[1]), "+f"(c[2]), "+f"(c[3])
                 : "r"(a[0]), "r"(a[1]), "r"(a[2]), "r"(a[3]), "r"(b0), "r"(b1));
}
__device__ __forceinline__ void hsplit(float a, __half& hi, __half& lo) {
    hi = __float2half_rn(a);
    lo = __float2half_rn(a - __half2float(hi));
}

// ---------------- embedding + sinusoidal positional encoding ----------------
__global__ __launch_bounds__(256) void embed_kernel(const int* __restrict__ ids,
                                                    const float* __restrict__ emb,
                                                    float* __restrict__ x) {
    int s = blockIdx.x;
    int id = ids[s];
    const double c = -9.210340371976184 / 1024.0;
    for (int d = threadIdx.x; d < D; d += 256) {
        int p2 = d & ~1;
        double freq = exp((double)p2 * c);
        double phase = (double)s * freq;
        double pe = (d & 1) ? cos(phase) : sin(phase);
        x[s * D + d] = emb[id * D + d] + (float)pe;
    }
}

// ---------------- LayerNorm -> fp32 out (final) ----------------
__global__ __launch_bounds__(256) void ln_kernel(const float* __restrict__ x,
                                                 const float* __restrict__ sc,
                                                 const float* __restrict__ bi,
                                                 float* __restrict__ out) {
    __shared__ float ssum[256], ssq[256];
    int s = blockIdx.x, tid = threadIdx.x;
    float4 v = ((const float4*)(x + s * D))[tid];
    ssum[tid] = v.x + v.y + v.z + v.w;
    ssq[tid]  = v.x * v.x + v.y * v.y + v.z * v.z + v.w * v.w;
    __syncthreads();
#pragma unroll
    for (int off = 128; off > 0; off >>= 1) {
        if (tid < off) { ssum[tid] += ssum[tid + off]; ssq[tid] += ssq[tid + off]; }
        __syncthreads();
    }
    float mu  = ssum[0] * (1.0f / 1024.0f);
    float var = ssq[0] * (1.0f / 1024.0f) - mu * mu;
    float rs  = rsqrtf(var + 1e-6f);
    float4 scv = ((const float4*)sc)[tid];
    float4 biv = ((const float4*)bi)[tid];
    float4 o;
    o.x = (v.x - mu) * rs * scv.x + biv.x;
    o.y = (v.y - mu) * rs * scv.y + biv.y;
    o.z = (v.z - mu) * rs * scv.z + biv.z;
    o.w = (v.w - mu) * rs * scv.w + biv.w;
    ((float4*)(out + s * D))[tid] = o;
}

// ---------------- LayerNorm -> split fp16 [hi|lo] into a3 ----------------
__global__ __launch_bounds__(256) void ln_split_kernel(const float* __restrict__ x,
                                                       const float* __restrict__ sc,
                                                       const float* __restrict__ bi,
                                                       __half* __restrict__ a3) {
    __shared__ float ssum[256], ssq[256];
    int s = blockIdx.x, tid = threadIdx.x;
    float4 v = ((const float4*)(x + s * D))[tid];
    ssum[tid] = v.x + v.y + v.z + v.w;
    ssq[tid]  = v.x * v.x + v.y * v.y + v.z * v.z + v.w * v.w;
    __syncthreads();
#pragma unroll
    for (int off = 128; off > 0; off >>= 1) {
        if (tid < off) { ssum[tid] += ssum[tid + off]; ssq[tid] += ssq[tid + off]; }
        __syncthreads();
    }
    float mu  = ssum[0] * (1.0f / 1024.0f);
    float var = ssq[0] * (1.0f / 1024.0f) - mu * mu;
    float rs  = rsqrtf(var + 1e-6f);
    float4 scv = ((const float4*)sc)[tid];
    float4 biv = ((const float4*)bi)[tid];
    float o[4];
    o[0] = (v.x - mu) * rs * scv.x + biv.x;
    o[1] = (v.y - mu) * rs * scv.y + biv.y;
    o[2] = (v.z - mu) * rs * scv.z + biv.z;
    o[3] = (v.w - mu) * rs * scv.w + biv.w;
    __half hi[4], lo[4];
#pragma unroll
    for (int j = 0; j < 4; j++) hsplit(o[j], hi[j], lo[j]);
    __half* orow = a3 + (size_t)s * 2 * D + tid * 4;
    *(__half2*)(orow)         = __halves2half2(hi[0], hi[1]);
    *(__half2*)(orow + 2)     = __halves2half2(hi[2], hi[3]);
    *(__half2*)(orow + D)     = __halves2half2(lo[0], lo[1]);
    *(__half2*)(orow + D + 2) = __halves2half2(lo[2], lo[3]);
}

// ---- fused weight conversion: z in {0,1,2}=wq/wk/wv -> WT_QKV rows z*1024,
//      z=3 -> wo into WT_WO. All 1024x1024. ----
__global__ __launch_bounds__(256) void convW4_kernel(const float* __restrict__ wq,
                                                     const float* __restrict__ wk,
                                                     const float* __restrict__ wv,
                                                     const float* __restrict__ wo,
                                                     __half* __restrict__ Wqkv,
                                                     __half* __restrict__ Wo) {
    __shared__ float t[32][33];
    int z = blockIdx.z;
    const float* W = (z == 0) ? wq : (z == 1) ? wk : (z == 2) ? wv : wo;
    const int K = D, N = D;
    int k0 = blockIdx.x * 32, n0 = blockIdx.y * 32;
    int tx = threadIdx.x & 31, ty = threadIdx.x >> 5;
#pragma unroll
    for (int i = 0; i < 4; i++)
        t[ty + i * 8][tx] = W[(size_t)(k0 + ty + i * 8) * N + n0 + tx];
    __syncthreads();
#pragma unroll
    for (int i = 0; i < 4; i++) {
        int nloc = n0 + ty + i * 8, k = k0 + tx;
        __half hi = __float2half_rn(t[tx][ty + i * 8]);
        __half* orow = (z < 3) ? (Wqkv + (size_t)(nloc + z * 1024) * 2 * K)
                               : (Wo + (size_t)nloc * 2 * K);
        orow[k] = hi; orow[K + k] = hi;
    }
}
// ---- fused w1 (K=1024,N=4096) z=0 and w2 (K=4096,N=1024) z=1; 4096 blocks each ----
__global__ __launch_bounds__(256) void convW12_kernel(const float* __restrict__ w1,
                                                      const float* __restrict__ w2,
                                                      __half* __restrict__ Wt1,
                                                      __half* __restrict__ Wt2) {
    __shared__ float t[32][33];
    int z = blockIdx.y;
    const float* W = z ? w2 : w1;
    __half* Wt = z ? Wt2 : Wt1;
    const int K = z ? MM : D, N = z ? D : MM;
    int bx = blockIdx.x;
    int kb = z ? (bx & 127) : (bx & 31);
    int nb = z ? (bx >> 7)  : (bx >> 5);
    int k0 = kb * 32, n0 = nb * 32;
    int tx = threadIdx.x & 31, ty = threadIdx.x >> 5;
#pragma unroll
    for (int i = 0; i < 4; i++)
        t[ty + i * 8][tx] = W[(size_t)(k0 + ty + i * 8) * N + n0 + tx];
    __syncthreads();
#pragma unroll
    for (int i = 0; i < 4; i++) {
        int n = n0 + ty + i * 8, k = k0 + tx;
        __half hi = __float2half_rn(t[tx][ty + i * 8]);
        __half* orow = Wt + (size_t)n * 2 * K;
        orow[k] = hi; orow[K + k] = hi;
    }
}

// ---- HMMA fp16 GEMM: MTx128 CTA, 256 threads, 2 CTAs/SM, BK=64, 3 stages ----
template<int MT>
__global__ __launch_bounds__(256, 2) void gemm_tpl(const __half* __restrict__ A,
                                                   const __half* __restrict__ Bt,
                                                   float* __restrict__ C,
                                                   __half* __restrict__ Cs, int Kout,
                                                   int N, int K2,
                                                   const float* __restrict__ bias,
                                                   const float* residual, int relu) {
    extern __shared__ char sm[];
    constexpr int WTM = MT / 2;
    constexpr int FM = WTM / 16;
    constexpr int ROWB = 144;
    constexpr int STAGE = (MT + 128) * ROWB;
    const int tid = threadIdx.x, lane = tid & 31, wid = tid >> 5;
    const int bm = blockIdx.y * MT, bn = blockIdx.x * 128;
    const int wm = (wid >> 2) * WTM, wn = (wid & 3) * 32;
    const size_t rs = (size_t)K2 * 2;
    const char* Ag = (const char*)A + (size_t)bm * rs;
    const char* Bg = (const char*)Bt + (size_t)bn * rs;
    const uint32_t smb = smem_u32(sm);

    uint32_t a_off[FM], b_off[2];
#pragma unroll
    for (int f = 0; f < FM; f++)
        a_off[f] = (uint32_t)((wm + f * 16 + (lane & 15)) * ROWB + ((lane >> 4) * 16));
#pragma unroll
    for (int pi = 0; pi < 2; pi++) {
        int row = wn + pi * 16 + (lane & 7) + ((lane >> 4) << 3);
        b_off[pi] = (uint32_t)(row * ROWB + (((lane >> 3) & 1) * 16));
    }

    float acc[FM][4][4];
#pragma unroll
    for (int f = 0; f < FM; f++)
#pragma unroll
        for (int ni = 0; ni < 4; ni++)
#pragma unroll
            for (int j = 0; j < 4; j++) acc[f][ni][j] = 0.0f;

    auto load_stage = [&](int buf, int kt) {
        uint32_t sa = smb + buf * STAGE, sb2 = sa + MT * ROWB;
        size_t gk = (size_t)kt * 128;
#pragma unroll
        for (int i = 0; i < MT / 32; i++) {
            int c = tid + i * 256, r = c >> 3, cb = (c & 7) << 4;
            cp16(sa + r * ROWB + cb, Ag + (size_t)r * rs + gk + cb);
        }
#pragma unroll
        for (int i = 0; i < 4; i++) {
            int c = tid + i * 256, r = c >> 3, cb = (c & 7) << 4;
            cp16(sb2 + r * ROWB + cb, Bg + (size_t)r * rs + gk + cb);
        }
    };

    const int KT = K2 >> 6;
    load_stage(0, 0); CP_COMMIT();
    load_stage(1, 1); CP_COMMIT();

    int buf = 0;
    for (int kt = 0; kt < KT; kt++) {
        CP_WAIT1();
        __syncthreads();
        if (kt + 2 < KT) {
            int nbuf = buf + 2; if (nbuf >= 3) nbuf -= 3;
            load_stage(nbuf, kt + 2);
        }
        CP_COMMIT();
        const uint32_t ab = smb + buf * STAGE, bb = ab + MT * ROWB;
#pragma unroll
        for (int ks = 0; ks < 4; ks++) {
            uint32_t a[FM][4];
#pragma unroll
            for (int f = 0; f < FM; f++) ldsm4(a[f], ab + a_off[f] + ks * 32);
#pragma unroll
            for (int pi = 0; pi < 2; pi++) {
                uint32_t b[4];
                ldsm4(b, bb + b_off[pi] + ks * 32);
#pragma unroll
                for (int f = 0; f < FM; f++) {
                    mma16816(acc[f][2 * pi],     a[f], b[0], b[1]);
                    mma16816(acc[f][2 * pi + 1], a[f], b[2], b[3]);
                }
            }
        }
        buf = (buf == 2) ? 0 : buf + 1;
    }

    const int erow = lane >> 2, ecol = (lane & 3) * 2;
#pragma unroll
    for (int f = 0; f < FM; f++) {
#pragma unroll
        for (int ni = 0; ni < 4; ni++) {
            float* c = acc[f][ni];
            int col = bn + wn + ni * 8 + ecol;
#pragma unroll
            for (int half = 0; half < 2; half++) {
                int row = bm + wm + f * 16 + erow + half * 8;
                float vx = c[half * 2 + 0];
                float vy = c[half * 2 + 1];
                if (bias)  { vx += bias[col]; vy += bias[col + 1]; }
                if (relu)  { vx = fmaxf(vx, 0.f); vy = fmaxf(vy, 0.f); }
                if (Cs) {
                    __half hx, lx, hy, ly;
                    hsplit(vx, hx, lx); hsplit(vy, hy, ly);
                    __half* orow = Cs + (size_t)row * 2 * Kout;
                    *(__half2*)(orow + col)        = __halves2half2(hx, hy);
                    *(__half2*)(orow + Kout + col) = __halves2half2(lx, ly);
                } else {
                    if (residual) {
                        const float2 rv = *(const float2*)(residual + (size_t)row * N + col);
                        vx += rv.x; vy += rv.y;
                    }
                    float2 o; o.x = vx; o.y = vy;
                    *(float2*)(C + (size_t)row * N + col) = o;
                }
            }
        }
    }
}

// ------------- tensor-core flash attention, fp16; Q 2-term, P 1-term --------
// Q/K rows: 272B stride ([128B hi | 128B second] + 16B pad)
// P rows: 144B stride (128B hi + pad). V: 64 rows x 144B (single copy).
#define A_Q2   0u
#define A_K2   17408u
#define A_P2   34816u
#define A_V2   44032u
#define A_PS   53248u
#define A_CORR 70656u
#define A_LROW 70912u
#define ATTN_SMEM_BYTES 71168

__global__ __launch_bounds__(256) void attn_kernel(const float* __restrict__ qkv,
                                                   __half* __restrict__ a3) {
    extern __shared__ char smem[];
    const uint32_t sb = smem_u32(smem);
    float* Ps   = (float*)(smem + A_PS);
    float* corr_s = (float*)(smem + A_CORR);
    float* lrow = (float*)(smem + A_LROW);

    const int h  = blockIdx.y;
    const int q0 = blockIdx.x * 64;
    const int tid = threadIdx.x, lane = tid & 31, wid = tid >> 5;
    const int qcol = h * HD;

    // ---- Q split tile [hi | lo], scaled by 1/8 ----
#pragma unroll
    for (int i = 0; i < 4; i++) {
        int idx = tid + i * 256;
        int r = idx >> 4, c4 = (idx & 15) << 2;
        float4 qv = *(const float4*)(qkv + (size_t)(q0 + r) * QKVW + qcol + c4);
        qv.x *= 0.125f; qv.y *= 0.125f; qv.z *= 0.125f; qv.w *= 0.125f;
        __half h0, l0, h1, l1, h2, l2, h3, l3;
        hsplit(qv.x, h0, l0); hsplit(qv.y, h1, l1);
        hsplit(qv.z, h2, l2); hsplit(qv.w, h3, l3);
        char* row = smem + A_Q2 + r * 272 + 2 * c4;
        *(__half2*)(row)       = __halves2half2(h0, h1);
        *(__half2*)(row + 4)   = __halves2half2(h2, h3);
        *(__half2*)(row + 128) = __halves2half2(l0, l1);
        *(__half2*)(row + 132) = __halves2half2(l2, l3);
    }

    const int wm = (wid >> 1) * 16;
    const int wn = (wid & 1) * 32;
    const int erow = lane >> 2, ecol = (lane & 3) * 2;

    const uint32_t aq_off = sb + A_Q2 + (wm + (lane & 15)) * 272 + ((lane >> 4) * 16);
    const uint32_t ap_off = sb + A_P2 + (wm + (lane & 15)) * 144 + ((lane >> 4) * 16);
    uint32_t bk_off[2], bv_off[2];
#pragma unroll
    for (int pi = 0; pi < 2; pi++) {
        int row = wn + pi * 16 + (lane & 7) + ((lane >> 4) << 3);
        bk_off[pi] = sb + A_K2 + row * 272 + (((lane >> 3) & 1) * 16);
        int vrow = (lane & 7) + (((lane >> 3) & 1) << 3);
        bv_off[pi] = sb + A_V2 + vrow * 144 + (wn + pi * 16) * 2 + ((lane >> 4) * 16);
    }

    const int qbase = tid >> 4, kbase = tid & 15;

    float m[4], l[4];
#pragma unroll
    for (int i = 0; i < 4; i++) { m[i] = -1e30f; l[i] = 0.0f; }
    float acc[4][4];
#pragma unroll
    for (int ni = 0; ni < 4; ni++)
#pragma unroll
        for (int j = 0; j < 4; j++) acc[ni][j] = 0.0f;

    int jlo, jhi;
    if (q0 < 64) { jlo = 0; jhi = 31; }
    else {
        int lo = q0 - 256; jlo = lo > 0 ? (lo >> 6) : 0;
        int hi = (q0 + 63 + 256) >> 6; jhi = hi < 31 ? hi : 31;
    }
    const bool extra0 = (q0 >= 64) && (jlo > 0);
    const int ntiles = (jhi - jlo + 1) + (extra0 ? 1 : 0);

    __syncthreads();

    for (int t = 0; t < ntiles; t++) {
        int jt = extra0 ? (t == 0 ? 0 : (jlo + t - 1)) : (jlo + t);
        int k0 = jt * 64;

        // ---- K tile [hi | hi], V tile single copy ----
#pragma unroll
        for (int i = 0; i < 4; i++) {
            int idx = tid + i * 256;
            int r = idx >> 4, c4 = (idx & 15) << 2;
            float4 kv = *(const float4*)(qkv + (size_t)(k0 + r) * QKVW + 1024 + qcol + c4);
            __half h0 = __float2half_rn(kv.x), h1 = __float2half_rn(kv.y);
            __half h2 = __float2half_rn(kv.z), h3 = __float2half_rn(kv.w);
            char* row = smem + A_K2 + r * 272 + 2 * c4;
            *(__half2*)(row)       = __halves2half2(h0, h1);
            *(__half2*)(row + 4)   = __halves2half2(h2, h3);
            *(__half2*)(row + 128) = __halves2half2(h0, h1);
            *(__half2*)(row + 132) = __halves2half2(h2, h3);
        }
#pragma unroll
        for (int i = 0; i < 4; i++) {
            int idx = tid + i * 256;
            int r = idx >> 4, c4 = (idx & 15) << 2;
            float4 vv = *(const float4*)(qkv + (size_t)(k0 + r) * QKVW + 2048 + qcol + c4);
            __half h0 = __float2half_rn(vv.x), h1 = __float2half_rn(vv.y);
            __half h2 = __float2half_rn(vv.z), h3 = __float2half_rn(vv.w);
            char* r0 = smem + A_V2 + r * 144 + 2 * c4;
            *(__half2*)(r0)     = __halves2half2(h0, h1);
            *(__half2*)(r0 + 4) = __halves2half2(h2, h3);
        }
        __syncthreads();

        // ---- S = Q' K'^T (k = 128) ----
        float cq[4][4];
#pragma unroll
        for (int ni = 0; ni < 4; ni++)
#pragma unroll
            for (int j = 0; j < 4; j++) cq[ni][j] = 0.0f;
#pragma unroll
        for (int ks = 0; ks < 8; ks++) {
            uint32_t a[4];
            ldsm4(a, aq_off + ks * 32);
#pragma unroll
            for (int pi = 0; pi < 2; pi++) {
                uint32_t b[4];
                ldsm4(b, bk_off[pi] + ks * 32);
                mma16816(cq[2 * pi],     a, b[0], b[1]);
                mma16816(cq[2 * pi + 1], a, b[2], b[3]);
            }
        }
#pragma unroll
        for (int ni = 0; ni < 4; ni++) {
            int col = wn + ni * 8 + ecol;
            float2 s0; s0.x = cq[ni][0]; s0.y = cq[ni][1];
            float2 s1; s1.x = cq[ni][2]; s1.y = cq[ni][3];
            *(float2*)(Ps + (wm + erow) * 68 + col)     = s0;
            *(float2*)(Ps + (wm + erow + 8) * 68 + col) = s1;
        }
        __syncthreads();

        // ---- mask + online softmax ----
        const bool tileAll = (q0 < 64) || (k0 < 64);
#pragma unroll
        for (int i = 0; i < 4; i++) {
            int qr = qbase + 16 * i;
            int gi = q0 + qr;
            float sreg[4];
#pragma unroll
            for (int j = 0; j < 4; j++) {
                sreg[j] = Ps[qr * 68 + kbase + 16 * j];
                if (!tileAll) {
                    int gj = k0 + kbase + 16 * j;
                    int diff = gi - gj; if (diff < 0) diff = -diff;
                    if (diff > 256) sreg[j] = -1e30f;
                }
            }
            float mx = fmaxf(fmaxf(sreg[0], sreg[1]), fmaxf(sreg[2], sreg[3]));
#pragma unroll
            for (int off = 8; off > 0; off >>= 1)
                mx = fmaxf(mx, __shfl_xor_sync(0xffffffffu, mx, off, 16));
            float mnew = fmaxf(m[i], mx);
            float corr = __expf(m[i] - mnew);
            float psum = 0.0f;
#pragma unroll
            for (int j = 0; j < 4; j++) {
                float p = __expf(sreg[j] - mnew);
                sreg[j] = p;
                psum += p;
            }
#pragma unroll
            for (int off = 8; off > 0; off >>= 1)
                psum += __shfl_xor_sync(0xffffffffu, psum, off, 16);
            l[i] = l[i] * corr + psum;
            m[i] = mnew;
            char* prow = smem + A_P2 + qr * 144;
#pragma unroll
            for (int j = 0; j < 4; j++) {
                int col = kbase + 16 * j;
                *(__half*)(prow + 2 * col) = __float2half_rn(sreg[j]);
            }
            if (kbase == 0) corr_s[qr] = corr;
        }
        __syncthreads();

        // ---- ctx: P @ V (k = 64 rows) ----
        float cv[4][4];
#pragma unroll
        for (int ni = 0; ni < 4; ni++)
#pragma unroll
            for (int j = 0; j < 4; j++) cv[ni][j] = 0.0f;
#pragma unroll
        for (int ks = 0; ks < 4; ks++) {
            uint32_t a[4];
            ldsm4(a, ap_off + ks * 32);
#pragma unroll
            for (int pi = 0; pi < 2; pi++) {
                uint32_t b[4];
                ldsm4t(b, bv_off[pi] + ks * 16 * 144);
                mma16816(cv[2 * pi],     a, b[0], b[1]);
                mma16816(cv[2 * pi + 1], a, b[2], b[3]);
            }
        }
        float c0 = corr_s[wm + erow], c1 = corr_s[wm + erow + 8];
#pragma unroll
        for (int ni = 0; ni < 4; ni++) {
            acc[ni][0] = acc[ni][0] * c0 + cv[ni][0];
            acc[ni][1] = acc[ni][1] * c0 + cv[ni][1];
            acc[ni][2] = acc[ni][2] * c1 + cv[ni][2];
            acc[ni][3] = acc[ni][3] * c1 + cv[ni][3];
        }
        __syncthreads();
    }

    if (kbase == 0) {
#pragma unroll
        for (int i = 0; i < 4; i++) lrow[qbase + 16 * i] = l[i];
    }
    __syncthreads();

    float inv0 = 1.0f / lrow[wm + erow];
    float inv1 = 1.0f / lrow[wm + erow + 8];
    int row0 = q0 + wm + erow, row1 = row0 + 8;
#pragma unroll
    for (int ni = 0; ni < 4; ni++) {
        int col = wn + ni * 8 + ecol;
        float v0 = acc[ni][0] * inv0, v1 = acc[ni][1] * inv0;
        float v2 = acc[ni][2] * inv1, v3 = acc[ni][3] * inv1;
        __half h0, l0h, h1, l1h, h2, l2h, h3, l3h;
        hsplit(v0, h0, l0h); hsplit(v1, h1, l1h);
        hsplit(v2, h2, l2h); hsplit(v3, h3, l3h);
        __half* o0 = a3 + (size_t)row0 * 2 * D + qcol + col;
        __half* o1 = a3 + (size_t)row1 * 2 * D + qcol + col;
        *(__half2*)(o0)     = __halves2half2(h0, h1);
        *(__half2*)(o0 + D) = __halves2half2(l0h, l1h);
        *(__half2*)(o1)     = __halves2half2(h2, h3);
        *(__half2*)(o1 + D) = __halves2half2(l2h, l3h);
    }
}

// ---------------- launch ----------------
extern "C" void kernel_launch(void* const* d_in, const int* in_sizes, int n_in,
                              void* d_out, int out_size) {
    const int*   ids    = (const int*)d_in[0];
    const float* emb    = (const float*)d_in[2];
    const float* wq     = (const float*)d_in[3];
    const float* wk     = (const float*)d_in[4];
    const float* wv     = (const float*)d_in[5];
    const float* wo     = (const float*)d_in[6];
    const float* ln1_s  = (const float*)d_in[7];
    const float* ln1_b  = (const float*)d_in[8];
    const float* ln2_s  = (const float*)d_in[9];
    const float* ln2_b  = (const float*)d_in[10];
    const float* w1     = (const float*)d_in[11];
    const float* b1     = (const float*)d_in[12];
    const float* w2     = (const float*)d_in[13];
    const float* b2     = (const float*)d_in[14];
    const float* lnf_s  = (const float*)d_in[15];
    const float* lnf_b  = (const float*)d_in[16];
    float* out = (float*)d_out;

    void *px, *pqkv, *pa3, *py3, *pwT;
    cudaGetSymbolAddress(&px, g_x);
    cudaGetSymbolAddress(&pqkv, g_qkv);
    cudaGetSymbolAddress(&pa3, g_a3);
    cudaGetSymbolAddress(&py3, g_y3);
    cudaGetSymbolAddress(&pwT, g_wT);
    float* x = (float*)px;
    float* qkv = (float*)pqkv;
    __half* a3 = (__half*)pa3;
    __half* y3 = (__half*)py3;
    __half* wT = (__half*)pwT;

    cudaFuncSetAttribute(attn_kernel, cudaFuncAttributeMaxDynamicSharedMemorySize, ATTN_SMEM_BYTES);
    const int GS128 = 3 * 256 * 144;
    const int GS64  = 3 * 192 * 144;
    cudaFuncSetAttribute(gemm_tpl<128>, cudaFuncAttributeMaxDynamicSharedMemorySize, GS128);
    cudaFuncSetAttribute(gemm_tpl<64>,  cudaFuncAttributeMaxDynamicSharedMemorySize, GS64);

    embed_kernel<<<S, 256>>>(ids, emb, x);
    convW4_kernel<<<dim3(32, 32, 4), 256>>>(wq, wk, wv, wo, wT + WT_QKV, wT + WT_WO);
    ln_split_kernel<<<S, 256>>>(x, ln1_s, ln1_b, a3);

    for (int l = 0; l < LAY; l++) {
        size_t woff = (size_t)l * D * D;
        if (l > 0) {
            convW4_kernel<<<dim3(32, 32, 4), 256>>>(wq + woff, wk + woff, wv + woff,
                                                    wo + woff, wT + WT_QKV, wT + WT_WO);
            ln_split_kernel<<<S, 256>>>(x, ln1_s + l * D, ln1_b + l * D, a3);
        }
        convW12_kernel<<<dim3(4096, 2), 256>>>(w1 + (size_t)l * D * MM,
                                               w2 + (size_t)l * MM * D,
                                               wT + WT_W1, wT + WT_W2);
        gemm_tpl<64><<<dim3(QKVW / 128, S / 64), 256, GS64>>>(
            a3, wT + WT_QKV, qkv, nullptr, 0, QKVW, 2 * D, nullptr, nullptr, 0);
        attn_kernel<<<dim3(S / 64, H), 256, ATTN_SMEM_BYTES>>>(qkv, a3);
        gemm_tpl<64><<<dim3(D / 128, S / 64), 256, GS64>>>(
            a3, wT + WT_WO, x, nullptr, 0, D, 2 * D, nullptr, x, 0);
        ln_split_kernel<<<S, 256>>>(x, ln2_s + l * D, ln2_b + l * D, a3);
        gemm_tpl<128><<<dim3(MM / 128, S / 128), 256, GS128>>>(
            a3, wT + WT_W1, nullptr, y3, MM, MM, 2 * D, b1 + (size_t)l * MM, nullptr, 1);
        gemm_tpl<64><<<dim3(D / 128, S / 64), 256, GS64>>>(
            y3, wT + WT_W2, x, nullptr, 0, D, 2 * MM, b2 + (size_t)l * D, x, 0);
    }
    ln_kernel<<<S, 256>>>(x, lnf_s, lnf_b, out);
}

// round 14
// speedup vs baseline: 2.5618x; 1.0070x over previous
#include <cuda_runtime.h>
#include <cuda_fp16.h>
#include <math.h>
#include <stdint.h>

#define S   2048
#define D   1024
#define H   16
#define HD  64
#define MM  4096
#define LAY 4
#define QKVW 3072
#define WT_LAYER 25165824u   // halves per layer block
#define WT_WO    6291456u
#define WT_W1    8388608u
#define WT_W2    16777216u

// ---------------- scratch (device globals) ----------------
__device__ float g_x[S * D];
__device__ __half g_a3[S * 2 * D];
__device__ __half g_y3[S * 2 * MM];
__device__ __half g_wT[4 * WT_LAYER];          // all layers converted once
__device__ __half g_q[H * S * 128];            // [h][s][hi64|lo64] (scaled 1/8)
__device__ __half g_k[H * S * 128];            // [h][s][hi64|hi64]
__device__ __half g_v[H * S * 64];             // [h][s][64]

// ================= PTX helpers =================
__device__ __forceinline__ uint32_t smem_u32(const void* p) {
    uint32_t a;
    asm("{ .reg .u64 t; cvta.to.shared.u64 t, %1; cvt.u32.u64 %0, t; }" : "=r"(a) : "l"(p));
    return a;
}
__device__ __forceinline__ void cp16(uint32_t saddr, const void* g) {
    asm volatile("cp.async.cg.shared.global [%0], [%1], 16;" :: "r"(saddr), "l"(g));
}
#define CP_COMMIT() asm volatile("cp.async.commit_group;" ::: "memory")
#define CP_WAIT1()  asm volatile("cp.async.wait_group 1;" ::: "memory")

__device__ __forceinline__ void ldsm4(uint32_t* r, uint32_t a) {
    asm volatile("ldmatrix.sync.aligned.m8n8.x4.shared.b16 {%0,%1,%2,%3}, [%4];"
                 : "=r"(r[0]), "=r"(r[1]), "=r"(r[2]), "=r"(r[3]) : "r"(a));
}
__device__ __forceinline__ void ldsm4t(uint32_t* r, uint32_t a) {
    asm volatile("ldmatrix.sync.aligned.m8n8.x4.trans.shared.b16 {%0,%1,%2,%3}, [%4];"
                 : "=r"(r[0]), "=r"(r[1]), "=r"(r[2]), "=r"(r[3]) : "r"(a));
}
__device__ __forceinline__ void mma16816(float* c, const uint32_t* a, uint32_t b0, uint32_t b1) {
    asm volatile("mma.sync.aligned.m16n8k16.row.col.f32.f16.f16.f32 "
                 "{%0,%1,%2,%3}, {%4,%5,%6,%7}, {%8,%9}, {%0,%1,%2,%3};"
                 : "+f"(c[0]), "+f"(c[1]), "+f"(c[2]), "+f"(c[3])
                 : "r"(a[0]), "r"(a[1]), "r"(a[2]), "r"(a[3]), "r"(b0), "r"(b1));
}
__device__ __forceinline__ void hsplit(float a, __half& hi, __half& lo) {
    hi = __float2half_rn(a);
    lo = __float2half_rn(a - __half2float(hi));
}

// ---------------- embedding + sinusoidal positional encoding ----------------
__global__ __launch_bounds__(256) void embed_kernel(const int* __restrict__ ids,
                                                    const float* __restrict__ emb,
                                                    float* __restrict__ x) {
    int s = blockIdx.x;
    int id = ids[s];
    const double c = -9.210340371976184 / 1024.0;
    for (int d = threadIdx.x; d < D; d += 256) {
        int p2 = d & ~1;
        double freq = exp((double)p2 * c);
        double phase = (double)s * freq;
        double pe = (d & 1) ? cos(phase) : sin(phase);
        x[s * D + d] = emb[id * D + d] + (float)pe;
    }
}

// ---------------- LayerNorm -> fp32 out (final) ----------------
__global__ __launch_bounds__(256) void ln_kernel(const float* __restrict__ x,
                                                 const float* __restrict__ sc,
                                                 const float* __restrict__ bi,
                                                 float* __restrict__ out) {
    __shared__ float ssum[256], ssq[256];
    int s = blockIdx.x, tid = threadIdx.x;
    float4 v = ((const float4*)(x + s * D))[tid];
    ssum[tid] = v.x + v.y + v.z + v.w;
    ssq[tid]  = v.x * v.x + v.y * v.y + v.z * v.z + v.w * v.w;
    __syncthreads();
#pragma unroll
    for (int off = 128; off > 0; off >>= 1) {
        if (tid < off) { ssum[tid] += ssum[tid + off]; ssq[tid] += ssq[tid + off]; }
        __syncthreads();
    }
    float mu  = ssum[0] * (1.0f / 1024.0f);
    float var = ssq[0] * (1.0f / 1024.0f) - mu * mu;
    float rs  = rsqrtf(var + 1e-6f);
    float4 scv = ((const float4*)sc)[tid];
    float4 biv = ((const float4*)bi)[tid];
    float4 o;
    o.x = (v.x - mu) * rs * scv.x + biv.x;
    o.y = (v.y - mu) * rs * scv.y + biv.y;
    o.z = (v.z - mu) * rs * scv.z + biv.z;
    o.w = (v.w - mu) * rs * scv.w + biv.w;
    ((float4*)(out + s * D))[tid] = o;
}

// ---------------- LayerNorm -> split fp16 [hi|lo] into a3 ----------------
__global__ __launch_bounds__(256) void ln_split_kernel(const float* __restrict__ x,
                                                       const float* __restrict__ sc,
                                                       const float* __restrict__ bi,
                                                       __half* __restrict__ a3) {
    __shared__ float ssum[256], ssq[256];
    int s = blockIdx.x, tid = threadIdx.x;
    float4 v = ((const float4*)(x + s * D))[tid];
    ssum[tid] = v.x + v.y + v.z + v.w;
    ssq[tid]  = v.x * v.x + v.y * v.y + v.z * v.z + v.w * v.w;
    __syncthreads();
#pragma unroll
    for (int off = 128; off > 0; off >>= 1) {
        if (tid < off) { ssum[tid] += ssum[tid + off]; ssq[tid] += ssq[tid + off]; }
        __syncthreads();
    }
    float mu  = ssum[0] * (1.0f / 1024.0f);
    float var = ssq[0] * (1.0f / 1024.0f) - mu * mu;
    float rs  = rsqrtf(var + 1e-6f);
    float4 scv = ((const float4*)sc)[tid];
    float4 biv = ((const float4*)bi)[tid];
    float o[4];
    o[0] = (v.x - mu) * rs * scv.x + biv.x;
    o[1] = (v.y - mu) * rs * scv.y + biv.y;
    o[2] = (v.z - mu) * rs * scv.z + biv.z;
    o[3] = (v.w - mu) * rs * scv.w + biv.w;
    __half hi[4], lo[4];
#pragma unroll
    for (int j = 0; j < 4; j++) hsplit(o[j], hi[j], lo[j]);
    __half* orow = a3 + (size_t)s * 2 * D + tid * 4;
    *(__half2*)(orow)         = __halves2half2(hi[0], hi[1]);
    *(__half2*)(orow + 2)     = __halves2half2(hi[2], hi[3]);
    *(__half2*)(orow + D)     = __halves2half2(lo[0], lo[1]);
    *(__half2*)(orow + D + 2) = __halves2half2(lo[2], lo[3]);
}

// ---- weight conversion, ALL layers: z = layer*4 + w; w in {wq,wk,wv,wo} ----
__global__ __launch_bounds__(256) void convW4_all(const float* __restrict__ wq,
                                                  const float* __restrict__ wk,
                                                  const float* __restrict__ wv,
                                                  const float* __restrict__ wo,
                                                  __half* __restrict__ wT) {
    __shared__ float t[32][33];
    int z = blockIdx.z, layer = z >> 2, w = z & 3;
    const float* W = ((w == 0) ? wq : (w == 1) ? wk : (w == 2) ? wv : wo)
                     + (size_t)layer * D * D;
    __half* base = wT + (size_t)layer * WT_LAYER + (w < 3 ? 0 : WT_WO);
    int noff = (w < 3) ? w * 1024 : 0;
    const int K = D, N = D;
    int k0 = blockIdx.x * 32, n0 = blockIdx.y * 32;
    int tx = threadIdx.x & 31, ty = threadIdx.x >> 5;
#pragma unroll
    for (int i = 0; i < 4; i++)
        t[ty + i * 8][tx] = W[(size_t)(k0 + ty + i * 8) * N + n0 + tx];
    __syncthreads();
#pragma unroll
    for (int i = 0; i < 4; i++) {
        int n = n0 + ty + i * 8 + noff, k = k0 + tx;
        __half hi = __float2half_rn(t[tx][ty + i * 8]);
        __half* orow = base + (size_t)n * 2 * K;
        orow[k] = hi; orow[K + k] = hi;
    }
}
// ---- w1/w2, ALL layers: blockIdx.y = layer*2 + w ----
__global__ __launch_bounds__(256) void convW12_all(const float* __restrict__ w1,
                                                   const float* __restrict__ w2,
                                                   __half* __restrict__ wT) {
    __shared__ float t[32][33];
    int zy = blockIdx.y, layer = zy >> 1, w = zy & 1;
    const float* W = (w ? w2 : w1) + (size_t)layer * D * MM;
    __half* Wt = wT + (size_t)layer * WT_LAYER + (w ? WT_W2 : WT_W1);
    const int K = w ? MM : D, N = w ? D : MM;
    int bx = blockIdx.x;
    int kb = w ? (bx & 127) : (bx & 31);
    int nb = w ? (bx >> 7)  : (bx >> 5);
    int k0 = kb * 32, n0 = nb * 32;
    int tx = threadIdx.x & 31, ty = threadIdx.x >> 5;
#pragma unroll
    for (int i = 0; i < 4; i++)
        t[ty + i * 8][tx] = W[(size_t)(k0 + ty + i * 8) * N + n0 + tx];
    __syncthreads();
#pragma unroll
    for (int i = 0; i < 4; i++) {
        int n = n0 + ty + i * 8, k = k0 + tx;
        __half hi = __float2half_rn(t[tx][ty + i * 8]);
        __half* orow = Wt + (size_t)n * 2 * K;
        orow[k] = hi; orow[K + k] = hi;
    }
}

// ---- HMMA fp16 GEMM: MTx128 CTA, 256 threads, 2 CTAs/SM, BK=64, 3 stages ----
// MODE 0: fp32 C (+bias/relu/residual). MODE 1: split [hi|lo] into Cs (Kout).
// MODE 2: qkv scatter into g_q/g_k/g_v per-head fp16 buffers.
template<int MT, int MODE>
__global__ __launch_bounds__(256, 2) void gemm_tpl(const __half* __restrict__ A,
                                                   const __half* __restrict__ Bt,
                                                   float* __restrict__ C,
                                                   __half* __restrict__ Cs, int Kout,
                                                   int N, int K2,
                                                   const float* __restrict__ bias,
                                                   const float* residual, int relu) {
    extern __shared__ char sm[];
    constexpr int WTM = MT / 2;
    constexpr int FM = WTM / 16;
    constexpr int ROWB = 144;
    constexpr int STAGE = (MT + 128) * ROWB;
    const int tid = threadIdx.x, lane = tid & 31, wid = tid >> 5;
    const int bm = blockIdx.y * MT, bn = blockIdx.x * 128;
    const int wm = (wid >> 2) * WTM, wn = (wid & 3) * 32;
    const size_t rs = (size_t)K2 * 2;
    const char* Ag = (const char*)A + (size_t)bm * rs;
    const char* Bg = (const char*)Bt + (size_t)bn * rs;
    const uint32_t smb = smem_u32(sm);

    uint32_t a_off[FM], b_off[2];
#pragma unroll
    for (int f = 0; f < FM; f++)
        a_off[f] = (uint32_t)((wm + f * 16 + (lane & 15)) * ROWB + ((lane >> 4) * 16));
#pragma unroll
    for (int pi = 0; pi < 2; pi++) {
        int row = wn + pi * 16 + (lane & 7) + ((lane >> 4) << 3);
        b_off[pi] = (uint32_t)(row * ROWB + (((lane >> 3) & 1) * 16));
    }

    float acc[FM][4][4];
#pragma unroll
    for (int f = 0; f < FM; f++)
#pragma unroll
        for (int ni = 0; ni < 4; ni++)
#pragma unroll
            for (int j = 0; j < 4; j++) acc[f][ni][j] = 0.0f;

    auto load_stage = [&](int buf, int kt) {
        uint32_t sa = smb + buf * STAGE, sb2 = sa + MT * ROWB;
        size_t gk = (size_t)kt * 128;
#pragma unroll
        for (int i = 0; i < MT / 32; i++) {
            int c = tid + i * 256, r = c >> 3, cb = (c & 7) << 4;
            cp16(sa + r * ROWB + cb, Ag + (size_t)r * rs + gk + cb);
        }
#pragma unroll
        for (int i = 0; i < 4; i++) {
            int c = tid + i * 256, r = c >> 3, cb = (c & 7) << 4;
            cp16(sb2 + r * ROWB + cb, Bg + (size_t)r * rs + gk + cb);
        }
    };

    const int KT = K2 >> 6;
    load_stage(0, 0); CP_COMMIT();
    load_stage(1, 1); CP_COMMIT();

    int buf = 0;
    for (int kt = 0; kt < KT; kt++) {
        CP_WAIT1();
        __syncthreads();
        if (kt + 2 < KT) {
            int nbuf = buf + 2; if (nbuf >= 3) nbuf -= 3;
            load_stage(nbuf, kt + 2);
        }
        CP_COMMIT();
        const uint32_t ab = smb + buf * STAGE, bb = ab + MT * ROWB;
#pragma unroll
        for (int ks = 0; ks < 4; ks++) {
            uint32_t a[FM][4];
#pragma unroll
            for (int f = 0; f < FM; f++) ldsm4(a[f], ab + a_off[f] + ks * 32);
#pragma unroll
            for (int pi = 0; pi < 2; pi++) {
                uint32_t b[4];
                ldsm4(b, bb + b_off[pi] + ks * 32);
#pragma unroll
                for (int f = 0; f < FM; f++) {
                    mma16816(acc[f][2 * pi],     a[f], b[0], b[1]);
                    mma16816(acc[f][2 * pi + 1], a[f], b[2], b[3]);
                }
            }
        }
        buf = (buf == 2) ? 0 : buf + 1;
    }

    const int erow = lane >> 2, ecol = (lane & 3) * 2;
#pragma unroll
    for (int f = 0; f < FM; f++) {
#pragma unroll
        for (int ni = 0; ni < 4; ni++) {
            float* c = acc[f][ni];
            int col = bn + wn + ni * 8 + ecol;
#pragma unroll
            for (int half = 0; half < 2; half++) {
                int row = bm + wm + f * 16 + erow + half * 8;
                float vx = c[half * 2 + 0];
                float vy = c[half * 2 + 1];
                if (MODE == 2) {
                    int sec = col >> 10, cc = col & 1023;
                    int head = cc >> 6, d = cc & 63;
                    if (sec == 0) {
                        vx *= 0.125f; vy *= 0.125f;
                        __half hx, lx, hy, ly;
                        hsplit(vx, hx, lx); hsplit(vy, hy, ly);
                        __half* q = g_q + (((size_t)head * S + row) << 7) + d;
                        *(__half2*)(q)      = __halves2half2(hx, hy);
                        *(__half2*)(q + 64) = __halves2half2(lx, ly);
                    } else if (sec == 1) {
                        __half hx = __float2half_rn(vx), hy = __float2half_rn(vy);
                        __half* k = g_k + (((size_t)head * S + row) << 7) + d;
                        *(__half2*)(k)      = __halves2half2(hx, hy);
                        *(__half2*)(k + 64) = __halves2half2(hx, hy);
                    } else {
                        __half* v = g_v + (((size_t)head * S + row) << 6) + d;
                        *(__half2*)(v) = __halves2half2(__float2half_rn(vx), __float2half_rn(vy));
                    }
                } else {
                    if (bias)  { vx += bias[col]; vy += bias[col + 1]; }
                    if (relu)  { vx = fmaxf(vx, 0.f); vy = fmaxf(vy, 0.f); }
                    if (MODE == 1) {
                        __half hx, lx, hy, ly;
                        hsplit(vx, hx, lx); hsplit(vy, hy, ly);
                        __half* orow = Cs + (size_t)row * 2 * Kout;
                        *(__half2*)(orow + col)        = __halves2half2(hx, hy);
                        *(__half2*)(orow + Kout + col) = __halves2half2(lx, ly);
                    } else {
                        if (residual) {
                            const float2 rv = *(const float2*)(residual + (size_t)row * N + col);
                            vx += rv.x; vy += rv.y;
                        }
                        float2 o; o.x = vx; o.y = vy;
                        *(float2*)(C + (size_t)row * N + col) = o;
                    }
                }
            }
        }
    }
}

// ------------- tensor-core flash attention, prepared fp16 inputs ------------
#define A_Q2   0u
#define A_K2   17408u
#define A_P2   34816u
#define A_V2   44032u
#define A_PS   53248u
#define A_CORR 70656u
#define A_LROW 70912u
#define ATTN_SMEM_BYTES 71168

__global__ __launch_bounds__(256) void attn_kernel(__half* __restrict__ a3) {
    extern __shared__ char smem[];
    const uint32_t sb = smem_u32(smem);
    float* Ps   = (float*)(smem + A_PS);
    float* corr_s = (float*)(smem + A_CORR);
    float* lrow = (float*)(smem + A_LROW);

    const int h  = blockIdx.y;
    const int q0 = blockIdx.x * 64;
    const int tid = threadIdx.x, lane = tid & 31, wid = tid >> 5;

    // ---- Q tile: 64 rows x 256B direct copy ----
    const char* gqh = (const char*)(g_q + (((size_t)h * S + q0) << 7));
#pragma unroll
    for (int i = 0; i < 4; i++) {
        int idx = tid + i * 256;
        int r = idx >> 4, c = idx & 15;
        *(uint4*)(smem + A_Q2 + r * 272 + c * 16) = *(const uint4*)(gqh + r * 256 + c * 16);
    }

    const int wm = (wid >> 1) * 16;
    const int wn = (wid & 1) * 32;
    const int erow = lane >> 2, ecol = (lane & 3) * 2;

    const uint32_t aq_off = sb + A_Q2 + (wm + (lane & 15)) * 272 + ((lane >> 4) * 16);
    const uint32_t ap_off = sb + A_P2 + (wm + (lane & 15)) * 144 + ((lane >> 4) * 16);
    uint32_t bk_off[2], bv_off[2];
#pragma unroll
    for (int pi = 0; pi < 2; pi++) {
        int row = wn + pi * 16 + (lane & 7) + ((lane >> 4) << 3);
        bk_off[pi] = sb + A_K2 + row * 272 + (((lane >> 3) & 1) * 16);
        int vrow = (lane & 7) + (((lane >> 3) & 1) << 3);
        bv_off[pi] = sb + A_V2 + vrow * 144 + (wn + pi * 16) * 2 + ((lane >> 4) * 16);
    }

    const int qbase = tid >> 4, kbase = tid & 15;

    float m[4], l[4];
#pragma unroll
    for (int i = 0; i < 4; i++) { m[i] = -1e30f; l[i] = 0.0f; }
    float acc[4][4];
#pragma unroll
    for (int ni = 0; ni < 4; ni++)
#pragma unroll
        for (int j = 0; j < 4; j++) acc[ni][j] = 0.0f;

    int jlo, jhi;
    if (q0 < 64) { jlo = 0; jhi = 31; }
    else {
        int lo = q0 - 256; jlo = lo > 0 ? (lo >> 6) : 0;
        int hi = (q0 + 63 + 256) >> 6; jhi = hi < 31 ? hi : 31;
    }
    const bool extra0 = (q0 >= 64) && (jlo > 0);
    const int ntiles = (jhi - jlo + 1) + (extra0 ? 1 : 0);

    __syncthreads();

    for (int t = 0; t < ntiles; t++) {
        int jt = extra0 ? (t == 0 ? 0 : (jlo + t - 1)) : (jlo + t);
        int k0 = jt * 64;

        // ---- K tile 64x256B, V tile 64x128B: direct copies ----
        const char* gkh = (const char*)(g_k + (((size_t)h * S + k0) << 7));
        const char* gvh = (const char*)(g_v + (((size_t)h * S + k0) << 6));
#pragma unroll
        for (int i = 0; i < 4; i++) {
            int idx = tid + i * 256;
            int r = idx >> 4, c = idx & 15;
            *(uint4*)(smem + A_K2 + r * 272 + c * 16) = *(const uint4*)(gkh + r * 256 + c * 16);
        }
#pragma unroll
        for (int i = 0; i < 2; i++) {
            int idx = tid + i * 256;
            int r = idx >> 3, c = idx & 7;
            *(uint4*)(smem + A_V2 + r * 144 + c * 16) = *(const uint4*)(gvh + r * 128 + c * 16);
        }
        __syncthreads();

        // ---- S = Q' K'^T (k = 128) ----
        float cq[4][4];
#pragma unroll
        for (int ni = 0; ni < 4; ni++)
#pragma unroll
            for (int j = 0; j < 4; j++) cq[ni][j] = 0.0f;
#pragma unroll
        for (int ks = 0; ks < 8; ks++) {
            uint32_t a[4];
            ldsm4(a, aq_off + ks * 32);
#pragma unroll
            for (int pi = 0; pi < 2; pi++) {
                uint32_t b[4];
                ldsm4(b, bk_off[pi] + ks * 32);
                mma16816(cq[2 * pi],     a, b[0], b[1]);
                mma16816(cq[2 * pi + 1], a, b[2], b[3]);
            }
        }
#pragma unroll
        for (int ni = 0; ni < 4; ni++) {
            int col = wn + ni * 8 + ecol;
            float2 s0; s0.x = cq[ni][0]; s0.y = cq[ni][1];
            float2 s1; s1.x = cq[ni][2]; s1.y = cq[ni][3];
            *(float2*)(Ps + (wm + erow) * 68 + col)     = s0;
            *(float2*)(Ps + (wm + erow + 8) * 68 + col) = s1;
        }
        __syncthreads();

        // ---- mask + online softmax ----
        const bool tileAll = (q0 < 64) || (k0 < 64);
#pragma unroll
        for (int i = 0; i < 4; i++) {
            int qr = qbase + 16 * i;
            int gi = q0 + qr;
            float sreg[4];
#pragma unroll
            for (int j = 0; j < 4; j++) {
                sreg[j] = Ps[qr * 68 + kbase + 16 * j];
                if (!tileAll) {
                    int gj = k0 + kbase + 16 * j;
                    int diff = gi - gj; if (diff < 0) diff = -diff;
                    if (diff > 256) sreg[j] = -1e30f;
                }
            }
            float mx = fmaxf(fmaxf(sreg[0], sreg[1]), fmaxf(sreg[2], sreg[3]));
#pragma unroll
            for (int off = 8; off > 0; off >>= 1)
                mx = fmaxf(mx, __shfl_xor_sync(0xffffffffu, mx, off, 16));
            float mnew = fmaxf(m[i], mx);
            float corr = __expf(m[i] - mnew);
            float psum = 0.0f;
#pragma unroll
            for (int j = 0; j < 4; j++) {
                float p = __expf(sreg[j] - mnew);
                sreg[j] = p;
                psum += p;
            }
#pragma unroll
            for (int off = 8; off > 0; off >>= 1)
                psum += __shfl_xor_sync(0xffffffffu, psum, off, 16);
            l[i] = l[i] * corr + psum;
            m[i] = mnew;
            char* prow = smem + A_P2 + qr * 144;
#pragma unroll
            for (int j = 0; j < 4; j++) {
                int col = kbase + 16 * j;
                *(__half*)(prow + 2 * col) = __float2half_rn(sreg[j]);
            }
            if (kbase == 0) corr_s[qr] = corr;
        }
        __syncthreads();

        // ---- ctx: P @ V (k = 64 rows) ----
        float cv[4][4];
#pragma unroll
        for (int ni = 0; ni < 4; ni++)
#pragma unroll
            for (int j = 0; j < 4; j++) cv[ni][j] = 0.0f;
#pragma unroll
        for (int ks = 0; ks < 4; ks++) {
            uint32_t a[4];
            ldsm4(a, ap_off + ks * 32);
#pragma unroll
            for (int pi = 0; pi < 2; pi++) {
                uint32_t b[4];
                ldsm4t(b, bv_off[pi] + ks * 16 * 144);
                mma16816(cv[2 * pi],     a, b[0], b[1]);
                mma16816(cv[2 * pi + 1], a, b[2], b[3]);
            }
        }
        float c0 = corr_s[wm + erow], c1 = corr_s[wm + erow + 8];
#pragma unroll
        for (int ni = 0; ni < 4; ni++) {
            acc[ni][0] = acc[ni][0] * c0 + cv[ni][0];
            acc[ni][1] = acc[ni][1] * c0 + cv[ni][1];
            acc[ni][2] = acc[ni][2] * c1 + cv[ni][2];
            acc[ni][3] = acc[ni][3] * c1 + cv[ni][3];
        }
        __syncthreads();
    }

    if (kbase == 0) {
#pragma unroll
        for (int i = 0; i < 4; i++) lrow[qbase + 16 * i] = l[i];
    }
    __syncthreads();

    float inv0 = 1.0f / lrow[wm + erow];
    float inv1 = 1.0f / lrow[wm + erow + 8];
    int row0 = q0 + wm + erow, row1 = row0 + 8;
    const int qcol = h * HD;
#pragma unroll
    for (int ni = 0; ni < 4; ni++) {
        int col = wn + ni * 8 + ecol;
        float v0 = acc[ni][0] * inv0, v1 = acc[ni][1] * inv0;
        float v2 = acc[ni][2] * inv1, v3 = acc[ni][3] * inv1;
        __half h0, l0h, h1, l1h, h2, l2h, h3, l3h;
        hsplit(v0, h0, l0h); hsplit(v1, h1, l1h);
        hsplit(v2, h2, l2h); hsplit(v3, h3, l3h);
        __half* o0 = a3 + (size_t)row0 * 2 * D + qcol + col;
        __half* o1 = a3 + (size_t)row1 * 2 * D + qcol + col;
        *(__half2*)(o0)     = __halves2half2(h0, h1);
        *(__half2*)(o0 + D) = __halves2half2(l0h, l1h);
        *(__half2*)(o1)     = __halves2half2(h2, h3);
        *(__half2*)(o1 + D) = __halves2half2(l2h, l3h);
    }
}

// ---------------- launch ----------------
extern "C" void kernel_launch(void* const* d_in, const int* in_sizes, int n_in,
                              void* d_out, int out_size) {
    const int*   ids    = (const int*)d_in[0];
    const float* emb    = (const float*)d_in[2];
    const float* wq     = (const float*)d_in[3];
    const float* wk     = (const float*)d_in[4];
    const float* wv     = (const float*)d_in[5];
    const float* wo     = (const float*)d_in[6];
    const float* ln1_s  = (const float*)d_in[7];
    const float* ln1_b  = (const float*)d_in[8];
    const float* ln2_s  = (const float*)d_in[9];
    const float* ln2_b  = (const float*)d_in[10];
    const float* w1     = (const float*)d_in[11];
    const float* b1     = (const float*)d_in[12];
    const float* w2     = (const float*)d_in[13];
    const float* b2     = (const float*)d_in[14];
    const float* lnf_s  = (const float*)d_in[15];
    const float* lnf_b  = (const float*)d_in[16];
    float* out = (float*)d_out;

    void *px, *pa3, *py3, *pwT;
    cudaGetSymbolAddress(&px, g_x);
    cudaGetSymbolAddress(&pa3, g_a3);
    cudaGetSymbolAddress(&py3, g_y3);
    cudaGetSymbolAddress(&pwT, g_wT);
    float* x = (float*)px;
    __half* a3 = (__half*)pa3;
    __half* y3 = (__half*)py3;
    __half* wT = (__half*)pwT;

    cudaFuncSetAttribute(attn_kernel, cudaFuncAttributeMaxDynamicSharedMemorySize, ATTN_SMEM_BYTES);
    const int GS128 = 3 * 256 * 144;
    const int GS64  = 3 * 192 * 144;
    cudaFuncSetAttribute((gemm_tpl<128, 1>), cudaFuncAttributeMaxDynamicSharedMemorySize, GS128);
    cudaFuncSetAttribute((gemm_tpl<64, 0>),  cudaFuncAttributeMaxDynamicSharedMemorySize, GS64);
    cudaFuncSetAttribute((gemm_tpl<64, 2>),  cudaFuncAttributeMaxDynamicSharedMemorySize, GS64);

    embed_kernel<<<S, 256>>>(ids, emb, x);                              // 0
    convW4_all<<<dim3(32, 32, 16), 256>>>(wq, wk, wv, wo, wT);          // 1
    ln_split_kernel<<<S, 256>>>(x, ln1_s, ln1_b, a3);                   // 2

    for (int l = 0; l < LAY; l++) {
        __half* wL = wT + (size_t)l * WT_LAYER;
        if (l > 0)
            ln_split_kernel<<<S, 256>>>(x, ln1_s + l * D, ln1_b + l * D, a3);
        gemm_tpl<64, 2><<<dim3(QKVW / 128, S / 64), 256, GS64>>>(       // 3 (l=0)
            a3, wL, nullptr, nullptr, 0, QKVW, 2 * D, nullptr, nullptr, 0);
        attn_kernel<<<dim3(S / 64, H), 256, ATTN_SMEM_BYTES>>>(a3);     // 4 (l=0)
        if (l == 0)
            convW12_all<<<dim3(4096, 8), 256>>>(w1, w2, wT);            // 5
        gemm_tpl<64, 0><<<dim3(D / 128, S / 64), 256, GS64>>>(
            a3, wL + WT_WO, x, nullptr, 0, D, 2 * D, nullptr, x, 0);
        ln_split_kernel<<<S, 256>>>(x, ln2_s + l * D, ln2_b + l * D, a3);
        gemm_tpl<128, 1><<<dim3(MM / 128, S / 128), 256, GS128>>>(
            a3, wL + WT_W1, nullptr, y3, MM, MM, 2 * D, b1 + (size_t)l * MM, nullptr, 1);
        gemm_tpl<64, 0><<<dim3(D / 128, S / 64), 256, GS64>>>(
            y3, wL + WT_W2, x, nullptr, 0, D, 2 * MM, b2 + (size_t)l * D, x, 0);
    }
    ln_kernel<<<S, 256>>>(x, lnf_s, lnf_b, out);
}

// round 15
// speedup vs baseline: 2.6373x; 1.0295x over previous
#include <cuda_runtime.h>
#include <cuda_fp16.h>
#include <math.h>
#include <stdint.h>

#define S   2048
#define D   1024
#define H   16
#define HD  64
#define MM  4096
#define LAY 4
#define QKVW 3072
#define WT_LAYER 25165824u   // halves per layer block
#define WT_WO    6291456u
#define WT_W1    8388608u
#define WT_W2    16777216u

// ---------------- scratch (device globals) ----------------
__device__ float g_x[S * D];
__device__ __half g_a3[S * 2 * D];
__device__ __half g_y3[S * 2 * MM];
__device__ __half g_wT[4 * WT_LAYER];          // all layers converted once
__device__ __half g_q[H * S * 128];            // [h][s][hi64|lo64] (scaled 1/8)
__device__ __half g_k[H * S * 128];            // [h][s][hi64|hi64]
__device__ __half g_v[H * S * 64];             // [h][s][64]

// ================= PTX helpers =================
__device__ __forceinline__ uint32_t smem_u32(const void* p) {
    uint32_t a;
    asm("{ .reg .u64 t; cvta.to.shared.u64 t, %1; cvt.u32.u64 %0, t; }" : "=r"(a) : "l"(p));
    return a;
}
__device__ __forceinline__ void cp16(uint32_t saddr, const void* g) {
    asm volatile("cp.async.cg.shared.global [%0], [%1], 16;" :: "r"(saddr), "l"(g));
}
#define CP_COMMIT() asm volatile("cp.async.commit_group;" ::: "memory")
#define CP_WAIT1()  asm volatile("cp.async.wait_group 1;" ::: "memory")

__device__ __forceinline__ void ldsm4(uint32_t* r, uint32_t a) {
    asm volatile("ldmatrix.sync.aligned.m8n8.x4.shared.b16 {%0,%1,%2,%3}, [%4];"
                 : "=r"(r[0]), "=r"(r[1]), "=r"(r[2]), "=r"(r[3]) : "r"(a));
}
__device__ __forceinline__ void ldsm4t(uint32_t* r, uint32_t a) {
    asm volatile("ldmatrix.sync.aligned.m8n8.x4.trans.shared.b16 {%0,%1,%2,%3}, [%4];"
                 : "=r"(r[0]), "=r"(r[1]), "=r"(r[2]), "=r"(r[3]) : "r"(a));
}
__device__ __forceinline__ void mma16816(float* c, const uint32_t* a, uint32_t b0, uint32_t b1) {
    asm volatile("mma.sync.aligned.m16n8k16.row.col.f32.f16.f16.f32 "
                 "{%0,%1,%2,%3}, {%4,%5,%6,%7}, {%8,%9}, {%0,%1,%2,%3};"
                 : "+f"(c[0]), "+f"(c[1]), "+f"(c[2]), "+f"(c[3])
                 : "r"(a[0]), "r"(a[1]), "r"(a[2]), "r"(a[3]), "r"(b0), "r"(b1));
}
__device__ __forceinline__ void hsplit(float a, __half& hi, __half& lo) {
    hi = __float2half_rn(a);
    lo = __float2half_rn(a - __half2float(hi));
}

// ---------------- embedding + sinusoidal positional encoding ----------------
__global__ __launch_bounds__(256) void embed_kernel(const int* __restrict__ ids,
                                                    const float* __restrict__ emb,
                                                    float* __restrict__ x) {
    int s = blockIdx.x;
    int id = ids[s];
    const double c = -9.210340371976184 / 1024.0;
    for (int d = threadIdx.x; d < D; d += 256) {
        int p2 = d & ~1;
        double freq = exp((double)p2 * c);
        double phase = (double)s * freq;
        double pe = (d & 1) ? cos(phase) : sin(phase);
        x[s * D + d] = emb[id * D + d] + (float)pe;
    }
}

// ---------------- LayerNorm -> fp32 out (final) ----------------
__global__ __launch_bounds__(256) void ln_kernel(const float* __restrict__ x,
                                                 const float* __restrict__ sc,
                                                 const float* __restrict__ bi,
                                                 float* __restrict__ out) {
    __shared__ float ssum[256], ssq[256];
    int s = blockIdx.x, tid = threadIdx.x;
    float4 v = ((const float4*)(x + s * D))[tid];
    ssum[tid] = v.x + v.y + v.z + v.w;
    ssq[tid]  = v.x * v.x + v.y * v.y + v.z * v.z + v.w * v.w;
    __syncthreads();
#pragma unroll
    for (int off = 128; off > 0; off >>= 1) {
        if (tid < off) { ssum[tid] += ssum[tid + off]; ssq[tid] += ssq[tid + off]; }
        __syncthreads();
    }
    float mu  = ssum[0] * (1.0f / 1024.0f);
    float var = ssq[0] * (1.0f / 1024.0f) - mu * mu;
    float rs  = rsqrtf(var + 1e-6f);
    float4 scv = ((const float4*)sc)[tid];
    float4 biv = ((const float4*)bi)[tid];
    float4 o;
    o.x = (v.x - mu) * rs * scv.x + biv.x;
    o.y = (v.y - mu) * rs * scv.y + biv.y;
    o.z = (v.z - mu) * rs * scv.z + biv.z;
    o.w = (v.w - mu) * rs * scv.w + biv.w;
    ((float4*)(out + s * D))[tid] = o;
}

// ---------------- LayerNorm -> split fp16 [hi|lo] into a3 ----------------
__global__ __launch_bounds__(256) void ln_split_kernel(const float* __restrict__ x,
                                                       const float* __restrict__ sc,
                                                       const float* __restrict__ bi,
                                                       __half* __restrict__ a3) {
    __shared__ float ssum[256], ssq[256];
    int s = blockIdx.x, tid = threadIdx.x;
    float4 v = ((const float4*)(x + s * D))[tid];
    ssum[tid] = v.x + v.y + v.z + v.w;
    ssq[tid]  = v.x * v.x + v.y * v.y + v.z * v.z + v.w * v.w;
    __syncthreads();
#pragma unroll
    for (int off = 128; off > 0; off >>= 1) {
        if (tid < off) { ssum[tid] += ssum[tid + off]; ssq[tid] += ssq[tid + off]; }
        __syncthreads();
    }
    float mu  = ssum[0] * (1.0f / 1024.0f);
    float var = ssq[0] * (1.0f / 1024.0f) - mu * mu;
    float rs  = rsqrtf(var + 1e-6f);
    float4 scv = ((const float4*)sc)[tid];
    float4 biv = ((const float4*)bi)[tid];
    float o[4];
    o[0] = (v.x - mu) * rs * scv.x + biv.x;
    o[1] = (v.y - mu) * rs * scv.y + biv.y;
    o[2] = (v.z - mu) * rs * scv.z + biv.z;
    o[3] = (v.w - mu) * rs * scv.w + biv.w;
    __half hi[4], lo[4];
#pragma unroll
    for (int j = 0; j < 4; j++) hsplit(o[j], hi[j], lo[j]);
    __half* orow = a3 + (size_t)s * 2 * D + tid * 4;
    *(__half2*)(orow)         = __halves2half2(hi[0], hi[1]);
    *(__half2*)(orow + 2)     = __halves2half2(hi[2], hi[3]);
    *(__half2*)(orow + D)     = __halves2half2(lo[0], lo[1]);
    *(__half2*)(orow + D + 2) = __halves2half2(lo[2], lo[3]);
}

// ---- weight conversion, ALL layers: z = layer*4 + w; w in {wq,wk,wv,wo} ----
__global__ __launch_bounds__(256) void convW4_all(const float* __restrict__ wq,
                                                  const float* __restrict__ wk,
                                                  const float* __restrict__ wv,
                                                  const float* __restrict__ wo,
                                                  __half* __restrict__ wT) {
    __shared__ float t[32][33];
    int z = blockIdx.z, layer = z >> 2, w = z & 3;
    const float* W = ((w == 0) ? wq : (w == 1) ? wk : (w == 2) ? wv : wo)
                     + (size_t)layer * D * D;
    __half* base = wT + (size_t)layer * WT_LAYER + (w < 3 ? 0 : WT_WO);
    int noff = (w < 3) ? w * 1024 : 0;
    const int K = D, N = D;
    int k0 = blockIdx.x * 32, n0 = blockIdx.y * 32;
    int tx = threadIdx.x & 31, ty = threadIdx.x >> 5;
#pragma unroll
    for (int i = 0; i < 4; i++)
        t[ty + i * 8][tx] = W[(size_t)(k0 + ty + i * 8) * N + n0 + tx];
    __syncthreads();
#pragma unroll
    for (int i = 0; i < 4; i++) {
        int n = n0 + ty + i * 8 + noff, k = k0 + tx;
        __half hi = __float2half_rn(t[tx][ty + i * 8]);
        __half* orow = base + (size_t)n * 2 * K;
        orow[k] = hi; orow[K + k] = hi;
    }
}
// ---- w1/w2, ALL layers: blockIdx.y = layer*2 + w ----
__global__ __launch_bounds__(256) void convW12_all(const float* __restrict__ w1,
                                                   const float* __restrict__ w2,
                                                   __half* __restrict__ wT) {
    __shared__ float t[32][33];
    int zy = blockIdx.y, layer = zy >> 1, w = zy & 1;
    const float* W = (w ? w2 : w1) + (size_t)layer * D * MM;
    __half* Wt = wT + (size_t)layer * WT_LAYER + (w ? WT_W2 : WT_W1);
    const int K = w ? MM : D, N = w ? D : MM;
    int bx = blockIdx.x;
    int kb = w ? (bx & 127) : (bx & 31);
    int nb = w ? (bx >> 7)  : (bx >> 5);
    int k0 = kb * 32, n0 = nb * 32;
    int tx = threadIdx.x & 31, ty = threadIdx.x >> 5;
#pragma unroll
    for (int i = 0; i < 4; i++)
        t[ty + i * 8][tx] = W[(size_t)(k0 + ty + i * 8) * N + n0 + tx];
    __syncthreads();
#pragma unroll
    for (int i = 0; i < 4; i++) {
        int n = n0 + ty + i * 8, k = k0 + tx;
        __half hi = __float2half_rn(t[tx][ty + i * 8]);
        __half* orow = Wt + (size_t)n * 2 * K;
        orow[k] = hi; orow[K + k] = hi;
    }
}

// ---- HMMA fp16 GEMM: MTx128 CTA, 256 threads, 2 CTAs/SM, BK=64, 3 stages ----
// MODE 0: fp32 C (+bias/relu/residual). MODE 1: split [hi|lo] into Cs (Kout).
// MODE 2: qkv scatter into g_q/g_k/g_v per-head fp16 buffers.
template<int MT, int MODE>
__global__ __launch_bounds__(256, 2) void gemm_tpl(const __half* __restrict__ A,
                                                   const __half* __restrict__ Bt,
                                                   float* __restrict__ C,
                                                   __half* __restrict__ Cs, int Kout,
                                                   int N, int K2,
                                                   const float* __restrict__ bias,
                                                   const float* residual, int relu) {
    extern __shared__ char sm[];
    constexpr int WTM = MT / 2;
    constexpr int FM = WTM / 16;
    constexpr int ROWB = 144;
    constexpr int STAGE = (MT + 128) * ROWB;
    const int tid = threadIdx.x, lane = tid & 31, wid = tid >> 5;
    const int bm = blockIdx.y * MT, bn = blockIdx.x * 128;
    const int wm = (wid >> 2) * WTM, wn = (wid & 3) * 32;
    const size_t rs = (size_t)K2 * 2;
    const char* Ag = (const char*)A + (size_t)bm * rs;
    const char* Bg = (const char*)Bt + (size_t)bn * rs;
    const uint32_t smb = smem_u32(sm);

    uint32_t a_off[FM], b_off[2];
#pragma unroll
    for (int f = 0; f < FM; f++)
        a_off[f] = (uint32_t)((wm + f * 16 + (lane & 15)) * ROWB + ((lane >> 4) * 16));
#pragma unroll
    for (int pi = 0; pi < 2; pi++) {
        int row = wn + pi * 16 + (lane & 7) + ((lane >> 4) << 3);
        b_off[pi] = (uint32_t)(row * ROWB + (((lane >> 3) & 1) * 16));
    }

    float acc[FM][4][4];
#pragma unroll
    for (int f = 0; f < FM; f++)
#pragma unroll
        for (int ni = 0; ni < 4; ni++)
#pragma unroll
            for (int j = 0; j < 4; j++) acc[f][ni][j] = 0.0f;

    auto load_stage = [&](int buf, int kt) {
        uint32_t sa = smb + buf * STAGE, sb2 = sa + MT * ROWB;
        size_t gk = (size_t)kt * 128;
#pragma unroll
        for (int i = 0; i < MT / 32; i++) {
            int c = tid + i * 256, r = c >> 3, cb = (c & 7) << 4;
            cp16(sa + r * ROWB + cb, Ag + (size_t)r * rs + gk + cb);
        }
#pragma unroll
        for (int i = 0; i < 4; i++) {
            int c = tid + i * 256, r = c >> 3, cb = (c & 7) << 4;
            cp16(sb2 + r * ROWB + cb, Bg + (size_t)r * rs + gk + cb);
        }
    };

    const int KT = K2 >> 6;
    load_stage(0, 0); CP_COMMIT();
    load_stage(1, 1); CP_COMMIT();

    int buf = 0;
    for (int kt = 0; kt < KT; kt++) {
        CP_WAIT1();
        __syncthreads();
        if (kt + 2 < KT) {
            int nbuf = buf + 2; if (nbuf >= 3) nbuf -= 3;
            load_stage(nbuf, kt + 2);
        }
        CP_COMMIT();
        const uint32_t ab = smb + buf * STAGE, bb = ab + MT * ROWB;
#pragma unroll
        for (int ks = 0; ks < 4; ks++) {
            uint32_t a[FM][4];
#pragma unroll
            for (int f = 0; f < FM; f++) ldsm4(a[f], ab + a_off[f] + ks * 32);
#pragma unroll
            for (int pi = 0; pi < 2; pi++) {
                uint32_t b[4];
                ldsm4(b, bb + b_off[pi] + ks * 32);
#pragma unroll
                for (int f = 0; f < FM; f++) {
                    mma16816(acc[f][2 * pi],     a[f], b[0], b[1]);
                    mma16816(acc[f][2 * pi + 1], a[f], b[2], b[3]);
                }
            }
        }
        buf = (buf == 2) ? 0 : buf + 1;
    }

    const int erow = lane >> 2, ecol = (lane & 3) * 2;
#pragma unroll
    for (int f = 0; f < FM; f++) {
#pragma unroll
        for (int ni = 0; ni < 4; ni++) {
            float* c = acc[f][ni];
            int col = bn + wn + ni * 8 + ecol;
#pragma unroll
            for (int half = 0; half < 2; half++) {
                int row = bm + wm + f * 16 + erow + half * 8;
                float vx = c[half * 2 + 0];
                float vy = c[half * 2 + 1];
                if (MODE == 2) {
                    int sec = col >> 10, cc = col & 1023;
                    int head = cc >> 6, d = cc & 63;
                    if (sec == 0) {
                        vx *= 0.125f; vy *= 0.125f;
                        __half hx, lx, hy, ly;
                        hsplit(vx, hx, lx); hsplit(vy, hy, ly);
                        __half* q = g_q + (((size_t)head * S + row) << 7) + d;
                        *(__half2*)(q)      = __halves2half2(hx, hy);
                        *(__half2*)(q + 64) = __halves2half2(lx, ly);
                    } else if (sec == 1) {
                        __half hx = __float2half_rn(vx), hy = __float2half_rn(vy);
                        __half* k = g_k + (((size_t)head * S + row) << 7) + d;
                        *(__half2*)(k)      = __halves2half2(hx, hy);
                        *(__half2*)(k + 64) = __halves2half2(hx, hy);
                    } else {
                        __half* v = g_v + (((size_t)head * S + row) << 6) + d;
                        *(__half2*)(v) = __halves2half2(__float2half_rn(vx), __float2half_rn(vy));
                    }
                } else {
                    if (bias)  { vx += bias[col]; vy += bias[col + 1]; }
                    if (relu)  { vx = fmaxf(vx, 0.f); vy = fmaxf(vy, 0.f); }
                    if (MODE == 1) {
                        __half hx, lx, hy, ly;
                        hsplit(vx, hx, lx); hsplit(vy, hy, ly);
                        __half* orow = Cs + (size_t)row * 2 * Kout;
                        *(__half2*)(orow + col)        = __halves2half2(hx, hy);
                        *(__half2*)(orow + Kout + col) = __halves2half2(lx, ly);
                    } else {
                        if (residual) {
                            const float2 rv = *(const float2*)(residual + (size_t)row * N + col);
                            vx += rv.x; vy += rv.y;
                        }
                        float2 o; o.x = vx; o.y = vy;
                        *(float2*)(C + (size_t)row * N + col) = o;
                    }
                }
            }
        }
    }
}

// ------------- tensor-core flash attention, prepared fp16 inputs ------------
#define A_Q2   0u
#define A_K2   17408u
#define A_P2   34816u
#define A_V2   44032u
#define A_PS   53248u
#define A_CORR 70656u
#define A_LROW 70912u
#define ATTN_SMEM_BYTES 71168

__global__ __launch_bounds__(256) void attn_kernel(__half* __restrict__ a3) {
    extern __shared__ char smem[];
    const uint32_t sb = smem_u32(smem);
    float* Ps   = (float*)(smem + A_PS);
    float* corr_s = (float*)(smem + A_CORR);
    float* lrow = (float*)(smem + A_LROW);

    const int h  = blockIdx.y;
    const int q0 = blockIdx.x * 64;
    const int tid = threadIdx.x, lane = tid & 31, wid = tid >> 5;

    // ---- Q tile: 64 rows x 256B direct copy ----
    const char* gqh = (const char*)(g_q + (((size_t)h * S + q0) << 7));
#pragma unroll
    for (int i = 0; i < 4; i++) {
        int idx = tid + i * 256;
        int r = idx >> 4, c = idx & 15;
        *(uint4*)(smem + A_Q2 + r * 272 + c * 16) = *(const uint4*)(gqh + r * 256 + c * 16);
    }

    const int wm = (wid >> 1) * 16;
    const int wn = (wid & 1) * 32;
    const int erow = lane >> 2, ecol = (lane & 3) * 2;

    const uint32_t aq_off = sb + A_Q2 + (wm + (lane & 15)) * 272 + ((lane >> 4) * 16);
    const uint32_t ap_off = sb + A_P2 + (wm + (lane & 15)) * 144 + ((lane >> 4) * 16);
    uint32_t bk_off[2], bv_off[2];
#pragma unroll
    for (int pi = 0; pi < 2; pi++) {
        int row = wn + pi * 16 + (lane & 7) + ((lane >> 4) << 3);
        bk_off[pi] = sb + A_K2 + row * 272 + (((lane >> 3) & 1) * 16);
        int vrow = (lane & 7) + (((lane >> 3) & 1) << 3);
        bv_off[pi] = sb + A_V2 + vrow * 144 + (wn + pi * 16) * 2 + ((lane >> 4) * 16);
    }

    const int qbase = tid >> 4, kbase = tid & 15;

    float m[4], l[4];
#pragma unroll
    for (int i = 0; i < 4; i++) { m[i] = -1e30f; l[i] = 0.0f; }
    float acc[4][4];
#pragma unroll
    for (int ni = 0; ni < 4; ni++)
#pragma unroll
        for (int j = 0; j < 4; j++) acc[ni][j] = 0.0f;

    int jlo, jhi;
    if (q0 < 64) { jlo = 0; jhi = 31; }
    else {
        int lo = q0 - 256; jlo = lo > 0 ? (lo >> 6) : 0;
        int hi = (q0 + 63 + 256) >> 6; jhi = hi < 31 ? hi : 31;
    }
    const bool extra0 = (q0 >= 64) && (jlo > 0);
    const int ntiles = (jhi - jlo + 1) + (extra0 ? 1 : 0);

    __syncthreads();

    for (int t = 0; t < ntiles; t++) {
        int jt = extra0 ? (t == 0 ? 0 : (jlo + t - 1)) : (jlo + t);
        int k0 = jt * 64;

        // ---- K tile 64x256B, V tile 64x128B: direct copies ----
        const char* gkh = (const char*)(g_k + (((size_t)h * S + k0) << 7));
        const char* gvh = (const char*)(g_v + (((size_t)h * S + k0) << 6));
#pragma unroll
        for (int i = 0; i < 4; i++) {
            int idx = tid + i * 256;
            int r = idx >> 4, c = idx & 15;
            *(uint4*)(smem + A_K2 + r * 272 + c * 16) = *(const uint4*)(gkh + r * 256 + c * 16);
        }
#pragma unroll
        for (int i = 0; i < 2; i++) {
            int idx = tid + i * 256;
            int r = idx >> 3, c = idx & 7;
            *(uint4*)(smem + A_V2 + r * 144 + c * 16) = *(const uint4*)(gvh + r * 128 + c * 16);
        }
        __syncthreads();

        // ---- S = Q' K'^T (k = 128) ----
        float cq[4][4];
#pragma unroll
        for (int ni = 0; ni < 4; ni++)
#pragma unroll
            for (int j = 0; j < 4; j++) cq[ni][j] = 0.0f;
#pragma unroll
        for (int ks = 0; ks < 8; ks++) {
            uint32_t a[4];
            ldsm4(a, aq_off + ks * 32);
#pragma unroll
            for (int pi = 0; pi < 2; pi++) {
                uint32_t b[4];
                ldsm4(b, bk_off[pi] + ks * 32);
                mma16816(cq[2 * pi],     a, b[0], b[1]);
                mma16816(cq[2 * pi + 1], a, b[2], b[3]);
            }
        }
#pragma unroll
        for (int ni = 0; ni < 4; ni++) {
            int col = wn + ni * 8 + ecol;
            float2 s0; s0.x = cq[ni][0]; s0.y = cq[ni][1];
            float2 s1; s1.x = cq[ni][2]; s1.y = cq[ni][3];
            *(float2*)(Ps + (wm + erow) * 68 + col)     = s0;
            *(float2*)(Ps + (wm + erow + 8) * 68 + col) = s1;
        }
        __syncthreads();

        // ---- mask + online softmax ----
        const bool tileAll = (q0 < 64) || (k0 < 64);
#pragma unroll
        for (int i = 0; i < 4; i++) {
            int qr = qbase + 16 * i;
            int gi = q0 + qr;
            float sreg[4];
#pragma unroll
            for (int j = 0; j < 4; j++) {
                sreg[j] = Ps[qr * 68 + kbase + 16 * j];
                if (!tileAll) {
                    int gj = k0 + kbase + 16 * j;
                    int diff = gi - gj; if (diff < 0) diff = -diff;
                    if (diff > 256) sreg[j] = -1e30f;
                }
            }
            float mx = fmaxf(fmaxf(sreg[0], sreg[1]), fmaxf(sreg[2], sreg[3]));
#pragma unroll
            for (int off = 8; off > 0; off >>= 1)
                mx = fmaxf(mx, __shfl_xor_sync(0xffffffffu, mx, off, 16));
            float mnew = fmaxf(m[i], mx);
            float corr = __expf(m[i] - mnew);
            float psum = 0.0f;
#pragma unroll
            for (int j = 0; j < 4; j++) {
                float p = __expf(sreg[j] - mnew);
                sreg[j] = p;
                psum += p;
            }
#pragma unroll
            for (int off = 8; off > 0; off >>= 1)
                psum += __shfl_xor_sync(0xffffffffu, psum, off, 16);
            l[i] = l[i] * corr + psum;
            m[i] = mnew;
            char* prow = smem + A_P2 + qr * 144;
#pragma unroll
            for (int j = 0; j < 4; j++) {
                int col = kbase + 16 * j;
                *(__half*)(prow + 2 * col) = __float2half_rn(sreg[j]);
            }
            if (kbase == 0) corr_s[qr] = corr;
        }
        __syncthreads();

        // ---- ctx: P @ V (k = 64 rows) ----
        float cv[4][4];
#pragma unroll
        for (int ni = 0; ni < 4; ni++)
#pragma unroll
            for (int j = 0; j < 4; j++) cv[ni][j] = 0.0f;
#pragma unroll
        for (int ks = 0; ks < 4; ks++) {
            uint32_t a[4];
            ldsm4(a, ap_off + ks * 32);
#pragma unroll
            for (int pi = 0; pi < 2; pi++) {
                uint32_t b[4];
                ldsm4t(b, bv_off[pi] + ks * 16 * 144);
                mma16816(cv[2 * pi],     a, b[0], b[1]);
                mma16816(cv[2 * pi + 1], a, b[2], b[3]);
            }
        }
        float c0 = corr_s[wm + erow], c1 = corr_s[wm + erow + 8];
#pragma unroll
        for (int ni = 0; ni < 4; ni++) {
            acc[ni][0] = acc[ni][0] * c0 + cv[ni][0];
            acc[ni][1] = acc[ni][1] * c0 + cv[ni][1];
            acc[ni][2] = acc[ni][2] * c1 + cv[ni][2];
            acc[ni][3] = acc[ni][3] * c1 + cv[ni][3];
        }
        __syncthreads();
    }

    if (kbase == 0) {
#pragma unroll
        for (int i = 0; i < 4; i++) lrow[qbase + 16 * i] = l[i];
    }
    __syncthreads();

    float inv0 = 1.0f / lrow[wm + erow];
    float inv1 = 1.0f / lrow[wm + erow + 8];
    int row0 = q0 + wm + erow, row1 = row0 + 8;
    const int qcol = h * HD;
#pragma unroll
    for (int ni = 0; ni < 4; ni++) {
        int col = wn + ni * 8 + ecol;
        float v0 = acc[ni][0] * inv0, v1 = acc[ni][1] * inv0;
        float v2 = acc[ni][2] * inv1, v3 = acc[ni][3] * inv1;
        __half h0, l0h, h1, l1h, h2, l2h, h3, l3h;
        hsplit(v0, h0, l0h); hsplit(v1, h1, l1h);
        hsplit(v2, h2, l2h); hsplit(v3, h3, l3h);
        __half* o0 = a3 + (size_t)row0 * 2 * D + qcol + col;
        __half* o1 = a3 + (size_t)row1 * 2 * D + qcol + col;
        *(__half2*)(o0)     = __halves2half2(h0, h1);
        *(__half2*)(o0 + D) = __halves2half2(l0h, l1h);
        *(__half2*)(o1)     = __halves2half2(h2, h3);
        *(__half2*)(o1 + D) = __halves2half2(l2h, l3h);
    }
}

// ---------------- launch ----------------
extern "C" void kernel_launch(void* const* d_in, const int* in_sizes, int n_in,
                              void* d_out, int out_size) {
    const int*   ids    = (const int*)d_in[0];
    const float* emb    = (const float*)d_in[2];
    const float* wq     = (const float*)d_in[3];
    const float* wk     = (const float*)d_in[4];
    const float* wv     = (const float*)d_in[5];
    const float* wo     = (const float*)d_in[6];
    const float* ln1_s  = (const float*)d_in[7];
    const float* ln1_b  = (const float*)d_in[8];
    const float* ln2_s  = (const float*)d_in[9];
    const float* ln2_b  = (const float*)d_in[10];
    const float* w1     = (const float*)d_in[11];
    const float* b1     = (const float*)d_in[12];
    const float* w2     = (const float*)d_in[13];
    const float* b2     = (const float*)d_in[14];
    const float* lnf_s  = (const float*)d_in[15];
    const float* lnf_b  = (const float*)d_in[16];
    float* out = (float*)d_out;

    void *px, *pa3, *py3, *pwT;
    cudaGetSymbolAddress(&px, g_x);
    cudaGetSymbolAddress(&pa3, g_a3);
    cudaGetSymbolAddress(&py3, g_y3);
    cudaGetSymbolAddress(&pwT, g_wT);
    float* x = (float*)px;
    __half* a3 = (__half*)pa3;
    __half* y3 = (__half*)py3;
    __half* wT = (__half*)pwT;

    cudaFuncSetAttribute(attn_kernel, cudaFuncAttributeMaxDynamicSharedMemorySize, ATTN_SMEM_BYTES);
    const int GS128 = 3 * 256 * 144;
    const int GS64  = 3 * 192 * 144;
    cudaFuncSetAttribute((gemm_tpl<128, 1>), cudaFuncAttributeMaxDynamicSharedMemorySize, GS128);
    cudaFuncSetAttribute((gemm_tpl<128, 2>), cudaFuncAttributeMaxDynamicSharedMemorySize, GS128);
    cudaFuncSetAttribute((gemm_tpl<64, 0>),  cudaFuncAttributeMaxDynamicSharedMemorySize, GS64);

    embed_kernel<<<S, 256>>>(ids, emb, x);                              // 0
    convW4_all<<<dim3(32, 32, 16), 256>>>(wq, wk, wv, wo, wT);          // 1
    ln_split_kernel<<<S, 256>>>(x, ln1_s, ln1_b, a3);                   // 2

    for (int l = 0; l < LAY; l++) {
        __half* wL = wT + (size_t)l * WT_LAYER;
        if (l > 0)
            ln_split_kernel<<<S, 256>>>(x, ln1_s + l * D, ln1_b + l * D, a3);
        gemm_tpl<128, 2><<<dim3(QKVW / 128, S / 128), 256, GS128>>>(    // 3 (l=0)
            a3, wL, nullptr, nullptr, 0, QKVW, 2 * D, nullptr, nullptr, 0);
        attn_kernel<<<dim3(S / 64, H), 256, ATTN_SMEM_BYTES>>>(a3);     // 4 (l=0)
        if (l == 0)
            convW12_all<<<dim3(4096, 8), 256>>>(w1, w2, wT);            // 5
        gemm_tpl<64, 0><<<dim3(D / 128, S / 64), 256, GS64>>>(
            a3, wL + WT_WO, x, nullptr, 0, D, 2 * D, nullptr, x, 0);
        ln_split_kernel<<<S, 256>>>(x, ln2_s + l * D, ln2_b + l * D, a3);
        gemm_tpl<128, 1><<<dim3(MM / 128, S / 128), 256, GS128>>>(
            a3, wL + WT_W1, nullptr, y3, MM, MM, 2 * D, b1 + (size_t)l * MM, nullptr, 1);
        gemm_tpl<64, 0><<<dim3(D / 128, S / 64), 256, GS64>>>(
            y3, wL + WT_W2, x, nullptr, 0, D, 2 * MM, b2 + (size_t)l * D, x, 0);
    }
    ln_kernel<<<S, 256>>>(x, lnf_s, lnf_b, out);
}

// round 16
// speedup vs baseline: 4.0846x; 1.5487x over previous
#include <cuda_runtime.h>
#include <cuda_fp16.h>
#include <math.h>
#include <stdint.h>

#define S   2048
#define D   1024
#define H   16
#define HD  64
#define MM  4096
#define LAY 4
#define QKVW 3072
// per-layer fp16 weight block offsets (halves)
#define WT_QKV   0u
#define WT_WO    3145728u
#define WT_W1    4194304u
#define WT_W2    8388608u
#define WT_LAYER 12582912u

// ---------------- scratch (device globals) ----------------
__device__ float g_x[S * D];
__device__ __half g_a3[S * D];
__device__ __half g_y3[S * MM];
__device__ __half g_wT[4 * WT_LAYER];
__device__ __half g_q[H * S * 64];   // [h][s][64] (scaled 1/8)
__device__ __half g_k[H * S * 64];
__device__ __half g_v[H * S * 64];

// ================= PTX helpers =================
__device__ __forceinline__ uint32_t smem_u32(const void* p) {
    uint32_t a;
    asm("{ .reg .u64 t; cvta.to.shared.u64 t, %1; cvt.u32.u64 %0, t; }" : "=r"(a) : "l"(p));
    return a;
}
__device__ __forceinline__ void cp16(uint32_t saddr, const void* g) {
    asm volatile("cp.async.cg.shared.global [%0], [%1], 16;" :: "r"(saddr), "l"(g));
}
#define CP_COMMIT() asm volatile("cp.async.commit_group;" ::: "memory")
#define CP_WAIT1()  asm volatile("cp.async.wait_group 1;" ::: "memory")

__device__ __forceinline__ void ldsm4(uint32_t* r, uint32_t a) {
    asm volatile("ldmatrix.sync.aligned.m8n8.x4.shared.b16 {%0,%1,%2,%3}, [%4];"
                 : "=r"(r[0]), "=r"(r[1]), "=r"(r[2]), "=r"(r[3]) : "r"(a));
}
__device__ __forceinline__ void ldsm4t(uint32_t* r, uint32_t a) {
    asm volatile("ldmatrix.sync.aligned.m8n8.x4.trans.shared.b16 {%0,%1,%2,%3}, [%4];"
                 : "=r"(r[0]), "=r"(r[1]), "=r"(r[2]), "=r"(r[3]) : "r"(a));
}
__device__ __forceinline__ void mma16816(float* c, const uint32_t* a, uint32_t b0, uint32_t b1) {
    asm volatile("mma.sync.aligned.m16n8k16.row.col.f32.f16.f16.f32 "
                 "{%0,%1,%2,%3}, {%4,%5,%6,%7}, {%8,%9}, {%0,%1,%2,%3};"
                 : "+f"(c[0]), "+f"(c[1]), "+f"(c[2]), "+f"(c[3])
                 : "r"(a[0]), "r"(a[1]), "r"(a[2]), "r"(a[3]), "r"(b0), "r"(b1));
}

// ---------------- embedding + sinusoidal positional encoding ----------------
__global__ __launch_bounds__(256) void embed_kernel(const int* __restrict__ ids,
                                                    const float* __restrict__ emb,
                                                    float* __restrict__ x) {
    int s = blockIdx.x;
    int id = ids[s];
    const double c = -9.210340371976184 / 1024.0;
    for (int d = threadIdx.x; d < D; d += 256) {
        int p2 = d & ~1;
        double freq = exp((double)p2 * c);
        double phase = (double)s * freq;
        double pe = (d & 1) ? cos(phase) : sin(phase);
        x[s * D + d] = emb[id * D + d] + (float)pe;
    }
}

// ---------------- LayerNorm -> fp32 out (final) ----------------
__global__ __launch_bounds__(256) void ln_kernel(const float* __restrict__ x,
                                                 const float* __restrict__ sc,
                                                 const float* __restrict__ bi,
                                                 float* __restrict__ out) {
    __shared__ float ssum[256], ssq[256];
    int s = blockIdx.x, tid = threadIdx.x;
    float4 v = ((const float4*)(x + s * D))[tid];
    ssum[tid] = v.x + v.y + v.z + v.w;
    ssq[tid]  = v.x * v.x + v.y * v.y + v.z * v.z + v.w * v.w;
    __syncthreads();
#pragma unroll
    for (int off = 128; off > 0; off >>= 1) {
        if (tid < off) { ssum[tid] += ssum[tid + off]; ssq[tid] += ssq[tid + off]; }
        __syncthreads();
    }
    float mu  = ssum[0] * (1.0f / 1024.0f);
    float var = ssq[0] * (1.0f / 1024.0f) - mu * mu;
    float rs  = rsqrtf(var + 1e-6f);
    float4 scv = ((const float4*)sc)[tid];
    float4 biv = ((const float4*)bi)[tid];
    float4 o;
    o.x = (v.x - mu) * rs * scv.x + biv.x;
    o.y = (v.y - mu) * rs * scv.y + biv.y;
    o.z = (v.z - mu) * rs * scv.z + biv.z;
    o.w = (v.w - mu) * rs * scv.w + biv.w;
    ((float4*)(out + s * D))[tid] = o;
}

// ---------------- LayerNorm -> fp16 into a3 ----------------
__global__ __launch_bounds__(256) void ln_half_kernel(const float* __restrict__ x,
                                                      const float* __restrict__ sc,
                                                      const float* __restrict__ bi,
                                                      __half* __restrict__ a3) {
    __shared__ float ssum[256], ssq[256];
    int s = blockIdx.x, tid = threadIdx.x;
    float4 v = ((const float4*)(x + s * D))[tid];
    ssum[tid] = v.x + v.y + v.z + v.w;
    ssq[tid]  = v.x * v.x + v.y * v.y + v.z * v.z + v.w * v.w;
    __syncthreads();
#pragma unroll
    for (int off = 128; off > 0; off >>= 1) {
        if (tid < off) { ssum[tid] += ssum[tid + off]; ssq[tid] += ssq[tid + off]; }
        __syncthreads();
    }
    float mu  = ssum[0] * (1.0f / 1024.0f);
    float var = ssq[0] * (1.0f / 1024.0f) - mu * mu;
    float rs  = rsqrtf(var + 1e-6f);
    float4 scv = ((const float4*)sc)[tid];
    float4 biv = ((const float4*)bi)[tid];
    __half h0 = __float2half_rn((v.x - mu) * rs * scv.x + biv.x);
    __half h1 = __float2half_rn((v.y - mu) * rs * scv.y + biv.y);
    __half h2 = __float2half_rn((v.z - mu) * rs * scv.z + biv.z);
    __half h3 = __float2half_rn((v.w - mu) * rs * scv.w + biv.w);
    __half* orow = a3 + (size_t)s * D + tid * 4;
    *(__half2*)(orow)     = __halves2half2(h0, h1);
    *(__half2*)(orow + 2) = __halves2half2(h2, h3);
}

// ---- weight conversion, ALL layers: z = layer*4 + w; w in {wq,wk,wv,wo} ----
__global__ __launch_bounds__(256) void convW4_all(const float* __restrict__ wq,
                                                  const float* __restrict__ wk,
                                                  const float* __restrict__ wv,
                                                  const float* __restrict__ wo,
                                                  __half* __restrict__ wT) {
    __shared__ float t[32][33];
    int z = blockIdx.z, layer = z >> 2, w = z & 3;
    const float* W = ((w == 0) ? wq : (w == 1) ? wk : (w == 2) ? wv : wo)
                     + (size_t)layer * D * D;
    __half* base = wT + (size_t)layer * WT_LAYER + (w < 3 ? WT_QKV : WT_WO);
    int noff = (w < 3) ? w * 1024 : 0;
    const int K = D, N = D;
    int k0 = blockIdx.x * 32, n0 = blockIdx.y * 32;
    int tx = threadIdx.x & 31, ty = threadIdx.x >> 5;
#pragma unroll
    for (int i = 0; i < 4; i++)
        t[ty + i * 8][tx] = W[(size_t)(k0 + ty + i * 8) * N + n0 + tx];
    __syncthreads();
#pragma unroll
    for (int i = 0; i < 4; i++) {
        int n = n0 + ty + i * 8 + noff, k = k0 + tx;
        base[(size_t)n * K + k] = __float2half_rn(t[tx][ty + i * 8]);
    }
}
// ---- w1/w2, ALL layers: blockIdx.y = layer*2 + w ----
__global__ __launch_bounds__(256) void convW12_all(const float* __restrict__ w1,
                                                   const float* __restrict__ w2,
                                                   __half* __restrict__ wT) {
    __shared__ float t[32][33];
    int zy = blockIdx.y, layer = zy >> 1, w = zy & 1;
    const float* W = (w ? w2 : w1) + (size_t)layer * D * MM;
    __half* Wt = wT + (size_t)layer * WT_LAYER + (w ? WT_W2 : WT_W1);
    const int K = w ? MM : D, N = w ? D : MM;
    int bx = blockIdx.x;
    int kb = w ? (bx & 127) : (bx & 31);
    int nb = w ? (bx >> 7)  : (bx >> 5);
    int k0 = kb * 32, n0 = nb * 32;
    int tx = threadIdx.x & 31, ty = threadIdx.x >> 5;
#pragma unroll
    for (int i = 0; i < 4; i++)
        t[ty + i * 8][tx] = W[(size_t)(k0 + ty + i * 8) * N + n0 + tx];
    __syncthreads();
#pragma unroll
    for (int i = 0; i < 4; i++) {
        int n = n0 + ty + i * 8, k = k0 + tx;
        Wt[(size_t)n * K + k] = __float2half_rn(t[tx][ty + i * 8]);
    }
}

// ---- HMMA fp16 GEMM: MTx128 CTA, 256 threads, 2 CTAs/SM, BK=64, 3 stages ----
// MODE 0: fp32 C (+bias/relu/residual). MODE 1: fp16 into Cs [M,N].
// MODE 2: qkv scatter into g_q/g_k/g_v per-head fp16 buffers.
template<int MT, int MODE>
__global__ __launch_bounds__(256, 2) void gemm_tpl(const __half* __restrict__ A,
                                                   const __half* __restrict__ Bt,
                                                   float* __restrict__ C,
                                                   __half* __restrict__ Cs,
                                                   int N, int K,
                                                   const float* __restrict__ bias,
                                                   const float* residual, int relu) {
    extern __shared__ char sm[];
    constexpr int WTM = MT / 2;
    constexpr int FM = WTM / 16;
    constexpr int ROWB = 144;
    constexpr int STAGE = (MT + 128) * ROWB;
    const int tid = threadIdx.x, lane = tid & 31, wid = tid >> 5;
    const int bm = blockIdx.y * MT, bn = blockIdx.x * 128;
    const int wm = (wid >> 2) * WTM, wn = (wid & 3) * 32;
    const size_t rs = (size_t)K * 2;
    const char* Ag = (const char*)A + (size_t)bm * rs;
    const char* Bg = (const char*)Bt + (size_t)bn * rs;
    const uint32_t smb = smem_u32(sm);

    uint32_t a_off[FM], b_off[2];
#pragma unroll
    for (int f = 0; f < FM; f++)
        a_off[f] = (uint32_t)((wm + f * 16 + (lane & 15)) * ROWB + ((lane >> 4) * 16));
#pragma unroll
    for (int pi = 0; pi < 2; pi++) {
        int row = wn + pi * 16 + (lane & 7) + ((lane >> 4) << 3);
        b_off[pi] = (uint32_t)(row * ROWB + (((lane >> 3) & 1) * 16));
    }

    float acc[FM][4][4];
#pragma unroll
    for (int f = 0; f < FM; f++)
#pragma unroll
        for (int ni = 0; ni < 4; ni++)
#pragma unroll
            for (int j = 0; j < 4; j++) acc[f][ni][j] = 0.0f;

    auto load_stage = [&](int buf, int kt) {
        uint32_t sa = smb + buf * STAGE, sb2 = sa + MT * ROWB;
        size_t gk = (size_t)kt * 128;
#pragma unroll
        for (int i = 0; i < MT / 32; i++) {
            int c = tid + i * 256, r = c >> 3, cb = (c & 7) << 4;
            cp16(sa + r * ROWB + cb, Ag + (size_t)r * rs + gk + cb);
        }
#pragma unroll
        for (int i = 0; i < 4; i++) {
            int c = tid + i * 256, r = c >> 3, cb = (c & 7) << 4;
            cp16(sb2 + r * ROWB + cb, Bg + (size_t)r * rs + gk + cb);
        }
    };

    const int KT = K >> 6;
    load_stage(0, 0); CP_COMMIT();
    load_stage(1, 1); CP_COMMIT();

    int buf = 0;
    for (int kt = 0; kt < KT; kt++) {
        CP_WAIT1();
        __syncthreads();
        if (kt + 2 < KT) {
            int nbuf = buf + 2; if (nbuf >= 3) nbuf -= 3;
            load_stage(nbuf, kt + 2);
        }
        CP_COMMIT();
        const uint32_t ab = smb + buf * STAGE, bb = ab + MT * ROWB;
#pragma unroll
        for (int ks = 0; ks < 4; ks++) {
            uint32_t a[FM][4];
#pragma unroll
            for (int f = 0; f < FM; f++) ldsm4(a[f], ab + a_off[f] + ks * 32);
#pragma unroll
            for (int pi = 0; pi < 2; pi++) {
                uint32_t b[4];
                ldsm4(b, bb + b_off[pi] + ks * 32);
#pragma unroll
                for (int f = 0; f < FM; f++) {
                    mma16816(acc[f][2 * pi],     a[f], b[0], b[1]);
                    mma16816(acc[f][2 * pi + 1], a[f], b[2], b[3]);
                }
            }
        }
        buf = (buf == 2) ? 0 : buf + 1;
    }

    const int erow = lane >> 2, ecol = (lane & 3) * 2;
#pragma unroll
    for (int f = 0; f < FM; f++) {
#pragma unroll
        for (int ni = 0; ni < 4; ni++) {
            float* c = acc[f][ni];
            int col = bn + wn + ni * 8 + ecol;
#pragma unroll
            for (int half = 0; half < 2; half++) {
                int row = bm + wm + f * 16 + erow + half * 8;
                float vx = c[half * 2 + 0];
                float vy = c[half * 2 + 1];
                if (MODE == 2) {
                    int sec = col >> 10, cc = col & 1023;
                    int head = cc >> 6, d = cc & 63;
                    __half2* dst;
                    if (sec == 0) {
                        vx *= 0.125f; vy *= 0.125f;
                        dst = (__half2*)(g_q + (((size_t)head * S + row) << 6) + d);
                    } else if (sec == 1) {
                        dst = (__half2*)(g_k + (((size_t)head * S + row) << 6) + d);
                    } else {
                        dst = (__half2*)(g_v + (((size_t)head * S + row) << 6) + d);
                    }
                    *dst = __halves2half2(__float2half_rn(vx), __float2half_rn(vy));
                } else {
                    if (bias)  { vx += bias[col]; vy += bias[col + 1]; }
                    if (relu)  { vx = fmaxf(vx, 0.f); vy = fmaxf(vy, 0.f); }
                    if (MODE == 1) {
                        *(__half2*)(Cs + (size_t)row * N + col) =
                            __halves2half2(__float2half_rn(vx), __float2half_rn(vy));
                    } else {
                        if (residual) {
                            const float2 rv = *(const float2*)(residual + (size_t)row * N + col);
                            vx += rv.x; vy += rv.y;
                        }
                        float2 o; o.x = vx; o.y = vy;
                        *(float2*)(C + (size_t)row * N + col) = o;
                    }
                }
            }
        }
    }
}

// ------------- tensor-core flash attention, fp16 single-term ----------------
// Q/K/P/V rows: 144B stride (128B data + 16B pad)
#define A_Q    0u
#define A_K    9216u
#define A_P    18432u
#define A_V    27648u
#define A_PS   36864u
#define A_CORR 54272u
#define A_LROW 54528u
#define ATTN_SMEM_BYTES 54784

__global__ __launch_bounds__(256) void attn_kernel(__half* __restrict__ a3) {
    extern __shared__ char smem[];
    const uint32_t sb = smem_u32(smem);
    float* Ps     = (float*)(smem + A_PS);
    float* corr_s = (float*)(smem + A_CORR);
    float* lrow   = (float*)(smem + A_LROW);

    const int h  = blockIdx.y;
    const int q0 = blockIdx.x * 64;
    const int tid = threadIdx.x, lane = tid & 31, wid = tid >> 5;

    // ---- Q tile: 64 rows x 128B direct copy ----
    const char* gqh = (const char*)(g_q + (((size_t)h * S + q0) << 6));
#pragma unroll
    for (int i = 0; i < 2; i++) {
        int idx = tid + i * 256;
        int r = idx >> 3, c = idx & 7;
        *(uint4*)(smem + A_Q + r * 144 + c * 16) = *(const uint4*)(gqh + r * 128 + c * 16);
    }

    const int wm = (wid >> 1) * 16;
    const int wn = (wid & 1) * 32;
    const int erow = lane >> 2, ecol = (lane & 3) * 2;

    const uint32_t aq_off = sb + A_Q + (wm + (lane & 15)) * 144 + ((lane >> 4) * 16);
    const uint32_t ap_off = sb + A_P + (wm + (lane & 15)) * 144 + ((lane >> 4) * 16);
    uint32_t bk_off[2], bv_off[2];
#pragma unroll
    for (int pi = 0; pi < 2; pi++) {
        int row = wn + pi * 16 + (lane & 7) + ((lane >> 4) << 3);
        bk_off[pi] = sb + A_K + row * 144 + (((lane >> 3) & 1) * 16);
        int vrow = (lane & 7) + (((lane >> 3) & 1) << 3);
        bv_off[pi] = sb + A_V + vrow * 144 + (wn + pi * 16) * 2 + ((lane >> 4) * 16);
    }

    const int qbase = tid >> 4, kbase = tid & 15;

    float m[4], l[4];
#pragma unroll
    for (int i = 0; i < 4; i++) { m[i] = -1e30f; l[i] = 0.0f; }
    float acc[4][4];
#pragma unroll
    for (int ni = 0; ni < 4; ni++)
#pragma unroll
        for (int j = 0; j < 4; j++) acc[ni][j] = 0.0f;

    int jlo, jhi;
    if (q0 < 64) { jlo = 0; jhi = 31; }
    else {
        int lo = q0 - 256; jlo = lo > 0 ? (lo >> 6) : 0;
        int hi = (q0 + 63 + 256) >> 6; jhi = hi < 31 ? hi : 31;
    }
    const bool extra0 = (q0 >= 64) && (jlo > 0);
    const int ntiles = (jhi - jlo + 1) + (extra0 ? 1 : 0);

    __syncthreads();

    for (int t = 0; t < ntiles; t++) {
        int jt = extra0 ? (t == 0 ? 0 : (jlo + t - 1)) : (jlo + t);
        int k0 = jt * 64;

        // ---- K, V tiles: 64 rows x 128B direct copies ----
        const char* gkh = (const char*)(g_k + (((size_t)h * S + k0) << 6));
        const char* gvh = (const char*)(g_v + (((size_t)h * S + k0) << 6));
#pragma unroll
        for (int i = 0; i < 2; i++) {
            int idx = tid + i * 256;
            int r = idx >> 3, c = idx & 7;
            *(uint4*)(smem + A_K + r * 144 + c * 16) = *(const uint4*)(gkh + r * 128 + c * 16);
            *(uint4*)(smem + A_V + r * 144 + c * 16) = *(const uint4*)(gvh + r * 128 + c * 16);
        }
        __syncthreads();

        // ---- S = Q K^T (k = 64) ----
        float cq[4][4];
#pragma unroll
        for (int ni = 0; ni < 4; ni++)
#pragma unroll
            for (int j = 0; j < 4; j++) cq[ni][j] = 0.0f;
#pragma unroll
        for (int ks = 0; ks < 4; ks++) {
            uint32_t a[4];
            ldsm4(a, aq_off + ks * 32);
#pragma unroll
            for (int pi = 0; pi < 2; pi++) {
                uint32_t b[4];
                ldsm4(b, bk_off[pi] + ks * 32);
                mma16816(cq[2 * pi],     a, b[0], b[1]);
                mma16816(cq[2 * pi + 1], a, b[2], b[3]);
            }
        }
#pragma unroll
        for (int ni = 0; ni < 4; ni++) {
            int col = wn + ni * 8 + ecol;
            float2 s0; s0.x = cq[ni][0]; s0.y = cq[ni][1];
            float2 s1; s1.x = cq[ni][2]; s1.y = cq[ni][3];
            *(float2*)(Ps + (wm + erow) * 68 + col)     = s0;
            *(float2*)(Ps + (wm + erow + 8) * 68 + col) = s1;
        }
        __syncthreads();

        // ---- mask + online softmax ----
        const bool tileAll = (q0 < 64) || (k0 < 64);
#pragma unroll
        for (int i = 0; i < 4; i++) {
            int qr = qbase + 16 * i;
            int gi = q0 + qr;
            float sreg[4];
#pragma unroll
            for (int j = 0; j < 4; j++) {
                sreg[j] = Ps[qr * 68 + kbase + 16 * j];
                if (!tileAll) {
                    int gj = k0 + kbase + 16 * j;
                    int diff = gi - gj; if (diff < 0) diff = -diff;
                    if (diff > 256) sreg[j] = -1e30f;
                }
            }
            float mx = fmaxf(fmaxf(sreg[0], sreg[1]), fmaxf(sreg[2], sreg[3]));
#pragma unroll
            for (int off = 8; off > 0; off >>= 1)
                mx = fmaxf(mx, __shfl_xor_sync(0xffffffffu, mx, off, 16));
            float mnew = fmaxf(m[i], mx);
            float corr = __expf(m[i] - mnew);
            float psum = 0.0f;
#pragma unroll
            for (int j = 0; j < 4; j++) {
                float p = __expf(sreg[j] - mnew);
                sreg[j] = p;
                psum += p;
            }
#pragma unroll
            for (int off = 8; off > 0; off >>= 1)
                psum += __shfl_xor_sync(0xffffffffu, psum, off, 16);
            l[i] = l[i] * corr + psum;
            m[i] = mnew;
            char* prow = smem + A_P + qr * 144;
#pragma unroll
            for (int j = 0; j < 4; j++) {
                int col = kbase + 16 * j;
                *(__half*)(prow + 2 * col) = __float2half_rn(sreg[j]);
            }
            if (kbase == 0) corr_s[qr] = corr;
        }
        __syncthreads();

        // ---- ctx: P @ V (k = 64 rows) ----
        float cv[4][4];
#pragma unroll
        for (int ni = 0; ni < 4; ni++)
#pragma unroll
            for (int j = 0; j < 4; j++) cv[ni][j] = 0.0f;
#pragma unroll
        for (int ks = 0; ks < 4; ks++) {
            uint32_t a[4];
            ldsm4(a, ap_off + ks * 32);
#pragma unroll
            for (int pi = 0; pi < 2; pi++) {
                uint32_t b[4];
                ldsm4t(b, bv_off[pi] + ks * 16 * 144);
                mma16816(cv[2 * pi],     a, b[0], b[1]);
                mma16816(cv[2 * pi + 1], a, b[2], b[3]);
            }
        }
        float c0 = corr_s[wm + erow], c1 = corr_s[wm + erow + 8];
#pragma unroll
        for (int ni = 0; ni < 4; ni++) {
            acc[ni][0] = acc[ni][0] * c0 + cv[ni][0];
            acc[ni][1] = acc[ni][1] * c0 + cv[ni][1];
            acc[ni][2] = acc[ni][2] * c1 + cv[ni][2];
            acc[ni][3] = acc[ni][3] * c1 + cv[ni][3];
        }
        __syncthreads();
    }

    if (kbase == 0) {
#pragma unroll
        for (int i = 0; i < 4; i++) lrow[qbase + 16 * i] = l[i];
    }
    __syncthreads();

    float inv0 = 1.0f / lrow[wm + erow];
    float inv1 = 1.0f / lrow[wm + erow + 8];
    int row0 = q0 + wm + erow, row1 = row0 + 8;
    const int qcol = h * HD;
#pragma unroll
    for (int ni = 0; ni < 4; ni++) {
        int col = wn + ni * 8 + ecol;
        __half h0 = __float2half_rn(acc[ni][0] * inv0);
        __half h1 = __float2half_rn(acc[ni][1] * inv0);
        __half h2 = __float2half_rn(acc[ni][2] * inv1);
        __half h3 = __float2half_rn(acc[ni][3] * inv1);
        *(__half2*)(a3 + (size_t)row0 * D + qcol + col) = __halves2half2(h0, h1);
        *(__half2*)(a3 + (size_t)row1 * D + qcol + col) = __halves2half2(h2, h3);
    }
}

// ---------------- launch ----------------
extern "C" void kernel_launch(void* const* d_in, const int* in_sizes, int n_in,
                              void* d_out, int out_size) {
    const int*   ids    = (const int*)d_in[0];
    const float* emb    = (const float*)d_in[2];
    const float* wq     = (const float*)d_in[3];
    const float* wk     = (const float*)d_in[4];
    const float* wv     = (const float*)d_in[5];
    const float* wo     = (const float*)d_in[6];
    const float* ln1_s  = (const float*)d_in[7];
    const float* ln1_b  = (const float*)d_in[8];
    const float* ln2_s  = (const float*)d_in[9];
    const float* ln2_b  = (const float*)d_in[10];
    const float* w1     = (const float*)d_in[11];
    const float* b1     = (const float*)d_in[12];
    const float* w2     = (const float*)d_in[13];
    const float* b2     = (const float*)d_in[14];
    const float* lnf_s  = (const float*)d_in[15];
    const float* lnf_b  = (const float*)d_in[16];
    float* out = (float*)d_out;

    void *px, *pa3, *py3, *pwT;
    cudaGetSymbolAddress(&px, g_x);
    cudaGetSymbolAddress(&pa3, g_a3);
    cudaGetSymbolAddress(&py3, g_y3);
    cudaGetSymbolAddress(&pwT, g_wT);
    float* x = (float*)px;
    __half* a3 = (__half*)pa3;
    __half* y3 = (__half*)py3;
    __half* wT = (__half*)pwT;

    cudaFuncSetAttribute(attn_kernel, cudaFuncAttributeMaxDynamicSharedMemorySize, ATTN_SMEM_BYTES);
    const int GS128 = 3 * 256 * 144;
    const int GS64  = 3 * 192 * 144;
    cudaFuncSetAttribute((gemm_tpl<128, 1>), cudaFuncAttributeMaxDynamicSharedMemorySize, GS128);
    cudaFuncSetAttribute((gemm_tpl<128, 2>), cudaFuncAttributeMaxDynamicSharedMemorySize, GS128);
    cudaFuncSetAttribute((gemm_tpl<64, 0>),  cudaFuncAttributeMaxDynamicSharedMemorySize, GS64);

    embed_kernel<<<S, 256>>>(ids, emb, x);                              // 0
    convW4_all<<<dim3(32, 32, 16), 256>>>(wq, wk, wv, wo, wT);          // 1
    ln_half_kernel<<<S, 256>>>(x, ln1_s, ln1_b, a3);                    // 2

    for (int l = 0; l < LAY; l++) {
        __half* wL = wT + (size_t)l * WT_LAYER;
        if (l > 0)
            ln_half_kernel<<<S, 256>>>(x, ln1_s + l * D, ln1_b + l * D, a3);
        gemm_tpl<128, 2><<<dim3(QKVW / 128, S / 128), 256, GS128>>>(    // 3 (l=0)
            a3, wL + WT_QKV, nullptr, nullptr, QKVW, D, nullptr, nullptr, 0);
        attn_kernel<<<dim3(S / 64, H), 256, ATTN_SMEM_BYTES>>>(a3);     // 4 (l=0)
        if (l == 0)
            convW12_all<<<dim3(4096, 8), 256>>>(w1, w2, wT);            // 5
        gemm_tpl<64, 0><<<dim3(D / 128, S / 64), 256, GS64>>>(
            a3, wL + WT_WO, x, nullptr, D, D, nullptr, x, 0);
        ln_half_kernel<<<S, 256>>>(x, ln2_s + l * D, ln2_b + l * D, a3);
        gemm_tpl<128, 1><<<dim3(MM / 128, S / 128), 256, GS128>>>(
            a3, wL + WT_W1, nullptr, y3, MM, D, b1 + (size_t)l * MM, nullptr, 1);
        gemm_tpl<64, 0><<<dim3(D / 128, S / 64), 256, GS64>>>(
            y3, wL + WT_W2, x, nullptr, D, MM, b2 + (size_t)l * D, x, 0);
    }
    ln_kernel<<<S, 256>>>(x, lnf_s, lnf_b, out);
}